// round 7
// baseline (speedup 1.0000x reference)
#include <cuda_runtime.h>
#include <math.h>

// ---------------- problem constants ----------------
#define BB   2
#define NN   512
#define HIDD 768
#define BIAF 256
#define DD   257      // BIAF + 1
#define DP   272      // DD padded to multiple of 16
#define CLSK 14
#define HSZ  539      // 2*(BIAF+1) + 25
#define NPOS 30
#define SDIM 25

// ---------------- device scratch ----------------
// K-permuted layout: logical col l stored at physical (l&~7) + p8(l&7),
// p8: 0,1,2,3,4,5,6,7 -> 0,2,4,6,1,3,5,7  (so fragment pairs {t, t+4} are adjacent)
__device__ float g_h1[BB * NN * DP];                   // tf32, permuted K, gelu(x@mlp1)+1
__device__ float g_t1[BB * NN * DP];
__device__ float g_head1[BB * NN * DD];                // full precision, natural layout
__device__ float g_tail1[BB * NN * DD];
__device__ float g_u[BB * CLSK * NN * DP];             // tf32, permuted K
__device__ float g_bwT[CLSK * DP * DP + 64 * DP];      // tf32, [k][j][i], i permuted, + slack
__device__ float g_headW[BB * CLSK * NN];
__device__ float g_tailW[BB * CLSK * NN];
__device__ float g_sbias[CLSK * NPOS];

// ---------------- helpers ----------------
__device__ __forceinline__ int p8(int c) {
    int i = c & 7;
    return (c & ~7) + ((i & 3) * 2 + (i >> 2));
}
__device__ __forceinline__ unsigned f2t(float f) {
    unsigned u; asm("cvt.rna.tf32.f32 %0, %1;" : "=r"(u) : "f"(f)); return u;
}
__device__ __forceinline__ float f2tf(float f) { unsigned u = f2t(f); return __uint_as_float(u); }
__device__ __forceinline__ void mma8(float c[4], const unsigned a[4], const unsigned b[2]) {
    asm volatile("mma.sync.aligned.m16n8k8.row.col.f32.tf32.tf32.f32 "
                 "{%0,%1,%2,%3}, {%4,%5,%6,%7}, {%8,%9}, {%0,%1,%2,%3};"
                 : "+f"(c[0]), "+f"(c[1]), "+f"(c[2]), "+f"(c[3])
                 : "r"(a[0]), "r"(a[1]), "r"(a[2]), "r"(a[3]), "r"(b[0]), "r"(b[1]));
}
__device__ __forceinline__ void cp16(void* dst, const void* src) {
    unsigned d = (unsigned)__cvta_generic_to_shared(dst);
    asm volatile("cp.async.ca.shared.global [%0], [%1], 16;" :: "r"(d), "l"(src));
}
#define CP_COMMIT() asm volatile("cp.async.commit_group;")
#define CP_WAIT(n)  asm volatile("cp.async.wait_group %0;" :: "n"(n))

// ---------------- prep: fused transpose(biaf_W) + pad/ones + size-bias ----------------
#define TR_BLOCKS (9 * 9 * CLSK)
__global__ void prep_kernel(const float* __restrict__ bw, const float* __restrict__ W,
                            const float* __restrict__ se)
{
    int bi = blockIdx.x;
    int tid = threadIdx.x;

    if (bi < TR_BLOCKS) {
        __shared__ float tile[32][33];
        int k = bi / 81;
        int rem = bi % 81;
        int i0 = (rem / 9) * 32, j0 = (rem % 9) * 32;
        int tx = tid & 31, ty = tid >> 5;
        #pragma unroll
        for (int r = 0; r < 4; r++) {
            int i = i0 + ty + r * 8, j = j0 + tx;
            tile[ty + r * 8][tx] = (i < DD && j < DD) ? bw[(k * DD + i) * DD + j] : 0.0f;
        }
        __syncthreads();
        #pragma unroll
        for (int r = 0; r < 4; r++) {
            int j = j0 + ty + r * 8, i = i0 + tx;
            if (j < DP && i < DP)
                g_bwT[(k * DP + j) * DP + p8(i)] = f2tf(tile[tx][ty + r * 8]);
        }
        return;
    }

    if (bi < TR_BLOCKS + 4) {
        int bm = (bi - TR_BLOCKS) * 256 + tid;
        if (bm < BB * NN) {
            // zero pad region first, then the ones (physical slot of logical 256 is 256)
            #pragma unroll
            for (int j = 257; j < DP; j++) { g_h1[bm * DP + j] = 0.0f; g_t1[bm * DP + j] = 0.0f; }
            g_h1[bm * DP + 256] = 1.0f;
            g_t1[bm * DP + 256] = 1.0f;
            g_head1[bm * DD + 256] = 1.0f;
            g_tail1[bm * DD + 256] = 1.0f;
        }
        return;
    }

    for (int idx = tid; idx < CLSK * NPOS; idx += 256) {
        int k = idx / NPOS, p = idx % NPOS;
        float s = 0.0f;
        #pragma unroll
        for (int d = 0; d < SDIM; d++) s += se[p * SDIM + d] * W[k * HSZ + 2 * DD + d];
        g_sbias[idx] = s;
    }
}

// ---------------- stage 1: projections via tf32 mma. 64x64 tiles, 128 thr ----------------
__global__ void proj_kernel(const float* __restrict__ x, const float* __restrict__ y,
                            const float* __restrict__ w1, const float* __restrict__ b1,
                            const float* __restrict__ w2, const float* __restrict__ b2,
                            const float* __restrict__ hw, const float* __restrict__ hb,
                            const float* __restrict__ tw, const float* __restrict__ tb)
{
    __shared__ unsigned As[64][20];
    __shared__ unsigned Bs[64][20];

    const int v = blockIdx.z;
    const float* X = (v == 1) ? y : x;
    const float* Wm; const float* bias;
    if (v == 0)      { Wm = w1; bias = b1; }
    else if (v == 1) { Wm = w2; bias = b2; }
    else if (v == 2) { Wm = hw; bias = hb; }
    else             { Wm = tw; bias = tb; }

    const int m0 = blockIdx.x * 64;
    const int n0 = blockIdx.y * 64;
    const int tid = threadIdx.x;
    const int w = tid >> 5, lane = tid & 31, g = lane >> 2, tig = lane & 3;
    const int wm = (w >> 1) * 32, wn = (w & 1) * 32;

    float acc[2][4][4] = {};
    float4 na, nb;
    {
        int f = tid, r = f >> 1, kq = (f & 1) * 8;
        na = *(const float4*)&X[(m0 + r) * HIDD + kq];
        nb = *(const float4*)&Wm[(n0 + r) * HIDD + kq];
    }

    for (int k0 = 0; k0 < HIDD; k0 += 16) {
        int f = tid, r = f >> 1, kq = (f & 1) * 8;
        float4 na2 = *(const float4*)&X[(m0 + r) * HIDD + k0 + kq + 4];
        float4 nb2 = *(const float4*)&Wm[(n0 + r) * HIDD + k0 + kq + 4];
        unsigned* da = &As[r][kq];
        da[0] = f2t(na.x); da[1] = f2t(na.y); da[2] = f2t(na.z); da[3] = f2t(na.w);
        da[4] = f2t(na2.x); da[5] = f2t(na2.y); da[6] = f2t(na2.z); da[7] = f2t(na2.w);
        unsigned* db = &Bs[r][kq];
        db[0] = f2t(nb.x); db[1] = f2t(nb.y); db[2] = f2t(nb.z); db[3] = f2t(nb.w);
        db[4] = f2t(nb2.x); db[5] = f2t(nb2.y); db[6] = f2t(nb2.z); db[7] = f2t(nb2.w);
        __syncthreads();
        if (k0 + 16 < HIDD) {
            na = *(const float4*)&X[(m0 + r) * HIDD + k0 + 16 + kq];
            nb = *(const float4*)&Wm[(n0 + r) * HIDD + k0 + 16 + kq];
        }
        #pragma unroll
        for (int kk = 0; kk < 2; kk++) {
            unsigned a[2][4], b[4][2];
            #pragma unroll
            for (int i = 0; i < 2; i++) {
                a[i][0] = As[wm + i * 16 + g][kk * 8 + tig];
                a[i][1] = As[wm + i * 16 + g + 8][kk * 8 + tig];
                a[i][2] = As[wm + i * 16 + g][kk * 8 + tig + 4];
                a[i][3] = As[wm + i * 16 + g + 8][kk * 8 + tig + 4];
            }
            #pragma unroll
            for (int j = 0; j < 4; j++) {
                b[j][0] = Bs[wn + j * 8 + g][kk * 8 + tig];
                b[j][1] = Bs[wn + j * 8 + g][kk * 8 + tig + 4];
            }
            #pragma unroll
            for (int i = 0; i < 2; i++)
                #pragma unroll
                for (int j = 0; j < 4; j++) mma8(acc[i][j], a[i], b[j]);
        }
        __syncthreads();
    }

    #pragma unroll
    for (int i = 0; i < 2; i++) {
        #pragma unroll
        for (int rh = 0; rh < 2; rh++) {
            int m = m0 + wm + i * 16 + g + rh * 8;
            #pragma unroll
            for (int j = 0; j < 4; j++) {
                #pragma unroll
                for (int cb = 0; cb < 2; cb++) {
                    int c = n0 + wn + j * 8 + tig * 2 + cb;
                    float vv = acc[i][j][rh * 2 + cb] + bias[c];
                    if (v < 2) {
                        vv = 0.5f * vv * (1.0f + erff(vv * 0.70710678118654752f));
                        float* dst = (v == 0) ? g_h1 : g_t1;
                        dst[m * DP + p8(c)] = f2tf(vv);   // permuted K for mma consumers
                    } else {
                        vv = (vv > 0.0f) ? vv : 0.01f * vv;
                        float* dst = (v == 2) ? g_head1 : g_tail1;
                        dst[m * DD + c] = vv;
                    }
                }
            }
        }
    }
}

// ---------------- stage 3: rank-1 bias precomputes (warp per row, 2 passes of 7 classes) ----------------
__global__ void hw_kernel(const float* __restrict__ W)
{
    int warp_id = (blockIdx.x * blockDim.x + threadIdx.x) >> 5;
    int lane = threadIdx.x & 31;
    if (warp_id >= 2 * BB * NN) return;
    int which = (warp_id >= BB * NN) ? 1 : 0;
    int bm = warp_id - which * BB * NN;
    const float* hr = (which ? g_tail1 : g_head1) + bm * DD;

    float h[9];
    #pragma unroll
    for (int s = 0; s < 9; s++) {
        int i = lane + 32 * s;
        h[s] = (i < DD) ? hr[i] : 0.0f;
    }

    const float* Wb = W + which * DD;
    float* dst = which ? g_tailW : g_headW;
    int b = bm / NN, m = bm % NN;

    #pragma unroll
    for (int half = 0; half < 2; half++) {
        float acc[7];
        #pragma unroll
        for (int k = 0; k < 7; k++) acc[k] = 0.0f;
        #pragma unroll
        for (int sg = 0; sg < 9; sg++) {
            int i = lane + 32 * sg;
            if (i < DD) {
                float hv = h[sg];
                #pragma unroll
                for (int k = 0; k < 7; k++)
                    acc[k] += hv * __ldg(&Wb[(half * 7 + k) * HSZ + i]);
            }
        }
        #pragma unroll
        for (int k = 0; k < 7; k++) {
            #pragma unroll
            for (int o = 16; o; o >>= 1) acc[k] += __shfl_xor_sync(0xffffffffu, acc[k], o);
        }
        if (lane == 0) {
            #pragma unroll
            for (int k = 0; k < 7; k++)
                dst[(b * CLSK + half * 7 + k) * NN + m] = acc[k];
        }
    }
}

// ---------------- stage 4: u = h1 @ bwT^T. 64x64 tiles, 128 thr, 3-stage cp.async, LDS.64 frags ----------------
__global__ void u_kernel()
{
    __shared__ unsigned As[3][64][24];
    __shared__ unsigned Bs[3][64][24];

    const int bk = blockIdx.z;
    const int b = bk / CLSK, kcls = bk % CLSK;
    const int m0 = blockIdx.x * 64;
    const int n0 = blockIdx.y * 64;
    const float* A  = g_h1 + b * NN * DP;
    const float* Bm = g_bwT + kcls * DP * DP;
    const int tid = threadIdx.x;
    const int w = tid >> 5, lane = tid & 31, g = lane >> 2, tig = lane & 3;
    const int wm = (w >> 1) * 32, wn = (w & 1) * 32;

    float acc[2][4][4] = {};

    #define U_STAGE(buf, k0)                                                     \
        do { _Pragma("unroll")                                                   \
        for (int h = 0; h < 2; h++) {                                            \
            int f = tid + h * 128;                                               \
            int r = f >> 2, kq = (f & 3) * 4;                                    \
            cp16(&As[buf][r][kq], &A[(m0 + r) * DP + (k0) + kq]);                \
            cp16(&Bs[buf][r][kq], &Bm[(n0 + r) * DP + (k0) + kq]);               \
        } } while (0)

    U_STAGE(0, 0);  CP_COMMIT();
    U_STAGE(1, 16); CP_COMMIT();

    const int NT = DP / 16;  // 17
    int cur = 0;
    for (int kt = 0; kt < NT; kt++) {
        if (kt + 1 < NT) CP_WAIT(1); else CP_WAIT(0);
        __syncthreads();
        if (kt + 2 < NT) {
            int nxt = cur + 2; if (nxt >= 3) nxt -= 3;
            U_STAGE(nxt, (kt + 2) * 16);
            CP_COMMIT();
        }
        #pragma unroll
        for (int kk = 0; kk < 2; kk++) {
            unsigned a[2][4], b2[4][2];
            #pragma unroll
            for (int i = 0; i < 2; i++) {
                uint2 v0 = *(const uint2*)&As[cur][wm + i * 16 + g][kk * 8 + 2 * tig];
                uint2 v1 = *(const uint2*)&As[cur][wm + i * 16 + g + 8][kk * 8 + 2 * tig];
                a[i][0] = v0.x; a[i][1] = v1.x; a[i][2] = v0.y; a[i][3] = v1.y;
            }
            #pragma unroll
            for (int j = 0; j < 4; j++) {
                uint2 vb = *(const uint2*)&Bs[cur][wn + j * 8 + g][kk * 8 + 2 * tig];
                b2[j][0] = vb.x; b2[j][1] = vb.y;
            }
            #pragma unroll
            for (int i = 0; i < 2; i++)
                #pragma unroll
                for (int j = 0; j < 4; j++) mma8(acc[i][j], a[i], b2[j]);
        }
        if (++cur == 3) cur = 0;
    }

    float* U = g_u + bk * NN * DP;
    #pragma unroll
    for (int i = 0; i < 2; i++) {
        #pragma unroll
        for (int rh = 0; rh < 2; rh++) {
            int m = m0 + wm + i * 16 + g + rh * 8;
            #pragma unroll
            for (int j = 0; j < 4; j++) {
                #pragma unroll
                for (int cb = 0; cb < 2; cb++) {
                    int c = n0 + wn + j * 8 + tig * 2 + cb;
                    if (c < DP) U[m * DP + p8(c)] = f2tf(acc[i][j][rh * 2 + cb]);
                }
            }
        }
    }
}

// ---------------- stage 5: out = u @ t1^T + biases. 128x128 tiles, 256 thr, LDS.64 frags ----------------
#define O_TILE_U (128 * 24)
__global__ void out_kernel(float* __restrict__ out)
{
    extern __shared__ unsigned dyn[];
    unsigned (*As)[128][24] = (unsigned(*)[128][24])dyn;
    unsigned (*Bs)[128][24] = (unsigned(*)[128][24])(dyn + 3 * O_TILE_U);
    __shared__ float sHW[128], sTW[128], sSB[NPOS];

    const int bk = blockIdx.z;
    const int b = bk / CLSK, kcls = bk % CLSK;
    const int m0 = blockIdx.x * 128;
    const int n0 = blockIdx.y * 128;
    const float* A  = g_u + bk * NN * DP;
    const float* Bt = g_t1 + b * NN * DP;
    const int tid = threadIdx.x;
    const int w = tid >> 5, lane = tid & 31, g = lane >> 2, tig = lane & 3;
    const int wm = (w >> 1) * 32, wn = (w & 1) * 64;

    if (tid < 128) {
        sHW[tid] = g_headW[bk * NN + m0 + tid];
        sTW[tid] = g_tailW[bk * NN + n0 + tid];
    }
    if (tid < NPOS) sSB[tid] = g_sbias[kcls * NPOS + tid];

    float acc[2][8][4] = {};

    #define O_STAGE(buf, k0)                                                     \
        do { _Pragma("unroll")                                                   \
        for (int h = 0; h < 2; h++) {                                            \
            int f = tid + h * 256;                                               \
            int r = f >> 2, kq = (f & 3) * 4;                                    \
            cp16(&As[buf][r][kq], &A[(m0 + r) * DP + (k0) + kq]);                \
            cp16(&Bs[buf][r][kq], &Bt[(n0 + r) * DP + (k0) + kq]);               \
        } } while (0)

    O_STAGE(0, 0);  CP_COMMIT();
    O_STAGE(1, 16); CP_COMMIT();

    const int NT = DP / 16;  // 17
    int cur = 0;
    for (int kt = 0; kt < NT; kt++) {
        if (kt + 1 < NT) CP_WAIT(1); else CP_WAIT(0);
        __syncthreads();
        if (kt + 2 < NT) {
            int nxt = cur + 2; if (nxt >= 3) nxt -= 3;
            O_STAGE(nxt, (kt + 2) * 16);
            CP_COMMIT();
        }
        #pragma unroll
        for (int kk = 0; kk < 2; kk++) {
            unsigned a[2][4], b2[8][2];
            #pragma unroll
            for (int i = 0; i < 2; i++) {
                uint2 v0 = *(const uint2*)&As[cur][wm + i * 16 + g][kk * 8 + 2 * tig];
                uint2 v1 = *(const uint2*)&As[cur][wm + i * 16 + g + 8][kk * 8 + 2 * tig];
                a[i][0] = v0.x; a[i][1] = v1.x; a[i][2] = v0.y; a[i][3] = v1.y;
            }
            #pragma unroll
            for (int j = 0; j < 8; j++) {
                uint2 vb = *(const uint2*)&Bs[cur][wn + j * 8 + g][kk * 8 + 2 * tig];
                b2[j][0] = vb.x; b2[j][1] = vb.y;
            }
            #pragma unroll
            for (int i = 0; i < 2; i++)
                #pragma unroll
                for (int j = 0; j < 8; j++) mma8(acc[i][j], a[i], b2[j]);
        }
        if (++cur == 3) cur = 0;
    }

    #pragma unroll
    for (int i = 0; i < 2; i++) {
        #pragma unroll
        for (int rh = 0; rh < 2; rh++) {
            int ml = wm + i * 16 + g + rh * 8;
            int m = m0 + ml;
            float hv = sHW[ml];
            #pragma unroll
            for (int j = 0; j < 8; j++) {
                int cl = wn + j * 8 + tig * 2;
                int n = n0 + cl;
                int d0 = n - m;     d0 = (d0 < -15) ? -15 : (d0 > 14 ? 14 : d0);
                int d1 = n + 1 - m; d1 = (d1 < -15) ? -15 : (d1 > 14 ? 14 : d1);
                float2 vv;
                vv.x = acc[i][j][rh * 2 + 0] + hv + sTW[cl]     + sSB[d0 + 15];
                vv.y = acc[i][j][rh * 2 + 1] + hv + sTW[cl + 1] + sSB[d1 + 15];
                *(float2*)&out[(bk * NN + m) * NN + n] = vv;
            }
        }
    }
}

// ---------------- launch ----------------
extern "C" void kernel_launch(void* const* d_in, const int* in_sizes, int n_in,
                              void* d_out, int out_size)
{
    const float* x   = (const float*)d_in[0];
    const float* y   = (const float*)d_in[1];
    // d_in[2] = z : dead input
    const float* w1  = (const float*)d_in[3];
    const float* b1  = (const float*)d_in[4];
    const float* w2  = (const float*)d_in[5];
    const float* b2  = (const float*)d_in[6];
    const float* hw  = (const float*)d_in[7];
    const float* hb  = (const float*)d_in[8];
    const float* tw  = (const float*)d_in[9];
    const float* tb  = (const float*)d_in[10];
    const float* bw  = (const float*)d_in[11];
    const float* W   = (const float*)d_in[12];
    const float* se  = (const float*)d_in[13];
    float* out = (float*)d_out;

    const int OUT_SMEM = 3 * 2 * O_TILE_U * 4;   // 73728 bytes
    static int attr_done = 0;
    if (!attr_done) {
        cudaFuncSetAttribute(out_kernel, cudaFuncAttributeMaxDynamicSharedMemorySize, OUT_SMEM);
        attr_done = 1;
    }

    prep_kernel<<<TR_BLOCKS + 5, 256>>>(bw, W, se);
    proj_kernel<<<dim3(16, 4, 4), 128>>>(x, y, w1, b1, w2, b2, hw, hb, tw, tb);
    hw_kernel<<<256, 256>>>(W);
    u_kernel<<<dim3(8, 5, BB * CLSK), 128>>>();
    out_kernel<<<dim3(4, 4, BB * CLSK), 256, OUT_SMEM>>>(out);
}

// round 8
// speedup vs baseline: 1.1202x; 1.1202x over previous
#include <cuda_runtime.h>
#include <math.h>

// ---------------- problem constants ----------------
#define BB   2
#define NN   512
#define HIDD 768
#define BIAF 256
#define DD   257      // BIAF + 1
#define DP   272      // DD padded to multiple of 16
#define CLSK 14
#define HSZ  539      // 2*(BIAF+1) + 25
#define NPOS 30
#define SDIM 25

// ---------------- device scratch ----------------
__device__ float g_h1[BB * NN * DP];                   // tf32-rounded gelu(x@mlp1)+1, zero pad
__device__ float g_t1[BB * NN * DP];
__device__ float g_head1[BB * NN * DD];                // full precision (for bias dots)
__device__ float g_tail1[BB * NN * DD];
__device__ float g_u[BB * CLSK * NN * DP];             // tf32-rounded h1 @ biaf_W[k]
__device__ float g_bwT[CLSK * DP * DP + 64 * DP];      // tf32 [k][j][i], zero pad + slack (slack stays 0)
__device__ float g_headW[BB * CLSK * NN];
__device__ float g_tailW[BB * CLSK * NN];
__device__ float g_sbias[CLSK * NPOS];

// ---------------- helpers ----------------
__device__ __forceinline__ unsigned f2t(float f) {
    unsigned u; asm("cvt.rna.tf32.f32 %0, %1;" : "=r"(u) : "f"(f)); return u;
}
__device__ __forceinline__ float f2tf(float f) { unsigned u = f2t(f); return __uint_as_float(u); }
__device__ __forceinline__ void mma8(float c[4], const unsigned a[4], const unsigned b[2]) {
    asm volatile("mma.sync.aligned.m16n8k8.row.col.f32.tf32.tf32.f32 "
                 "{%0,%1,%2,%3}, {%4,%5,%6,%7}, {%8,%9}, {%0,%1,%2,%3};"
                 : "+f"(c[0]), "+f"(c[1]), "+f"(c[2]), "+f"(c[3])
                 : "r"(a[0]), "r"(a[1]), "r"(a[2]), "r"(a[3]), "r"(b[0]), "r"(b[1]));
}
__device__ __forceinline__ void cp16(void* dst, const void* src) {
    unsigned d = (unsigned)__cvta_generic_to_shared(dst);
    asm volatile("cp.async.ca.shared.global [%0], [%1], 16;" :: "r"(d), "l"(src));
}
#define CP_COMMIT() asm volatile("cp.async.commit_group;")
#define CP_WAIT(n)  asm volatile("cp.async.wait_group %0;" :: "n"(n))

// ---------------- prep: fused transpose(biaf_W) + pad/ones + size-bias ----------------
#define TR_BLOCKS (9 * 9 * CLSK)
__global__ void prep_kernel(const float* __restrict__ bw, const float* __restrict__ W,
                            const float* __restrict__ se)
{
    int bi = blockIdx.x;
    int tid = threadIdx.x;

    if (bi < TR_BLOCKS) {
        __shared__ float tile[32][33];
        int k = bi / 81;
        int rem = bi % 81;
        int i0 = (rem / 9) * 32, j0 = (rem % 9) * 32;
        int tx = tid & 31, ty = tid >> 5;
        #pragma unroll
        for (int r = 0; r < 4; r++) {
            int i = i0 + ty + r * 8, j = j0 + tx;
            tile[ty + r * 8][tx] = (i < DD && j < DD) ? bw[(k * DD + i) * DD + j] : 0.0f;
        }
        __syncthreads();
        #pragma unroll
        for (int r = 0; r < 4; r++) {
            int j = j0 + ty + r * 8, i = i0 + tx;
            if (j < DP && i < DP) g_bwT[(k * DP + j) * DP + i] = f2tf(tile[tx][ty + r * 8]);
        }
        return;
    }

    if (bi < TR_BLOCKS + 4) {
        int bm = (bi - TR_BLOCKS) * 256 + tid;
        if (bm < BB * NN) {
            g_h1[bm * DP + 256] = 1.0f;
            g_t1[bm * DP + 256] = 1.0f;
            #pragma unroll
            for (int j = 257; j < DP; j++) { g_h1[bm * DP + j] = 0.0f; g_t1[bm * DP + j] = 0.0f; }
            g_head1[bm * DD + 256] = 1.0f;
            g_tail1[bm * DD + 256] = 1.0f;
        }
        return;
    }

    for (int idx = tid; idx < CLSK * NPOS; idx += 256) {
        int k = idx / NPOS, p = idx % NPOS;
        float s = 0.0f;
        #pragma unroll
        for (int d = 0; d < SDIM; d++) s += se[p * SDIM + d] * W[k * HSZ + 2 * DD + d];
        g_sbias[idx] = s;
    }
}

// ---------------- stage 1: projections via tf32 mma. 64x64 tiles, 128 thr ----------------
__global__ void proj_kernel(const float* __restrict__ x, const float* __restrict__ y,
                            const float* __restrict__ w1, const float* __restrict__ b1,
                            const float* __restrict__ w2, const float* __restrict__ b2,
                            const float* __restrict__ hw, const float* __restrict__ hb,
                            const float* __restrict__ tw, const float* __restrict__ tb)
{
    __shared__ unsigned As[64][20];
    __shared__ unsigned Bs[64][20];

    const int v = blockIdx.z;
    const float* X = (v == 1) ? y : x;
    const float* Wm; const float* bias;
    if (v == 0)      { Wm = w1; bias = b1; }
    else if (v == 1) { Wm = w2; bias = b2; }
    else if (v == 2) { Wm = hw; bias = hb; }
    else             { Wm = tw; bias = tb; }

    const int m0 = blockIdx.x * 64;
    const int n0 = blockIdx.y * 64;
    const int tid = threadIdx.x;
    const int w = tid >> 5, lane = tid & 31, g = lane >> 2, tig = lane & 3;
    const int wm = (w >> 1) * 32, wn = (w & 1) * 32;

    float acc[2][4][4] = {};
    float4 na, nb;
    {
        int f = tid, r = f >> 1, kq = (f & 1) * 8;
        na = *(const float4*)&X[(m0 + r) * HIDD + kq];
        nb = *(const float4*)&Wm[(n0 + r) * HIDD + kq];
    }

    for (int k0 = 0; k0 < HIDD; k0 += 16) {
        int f = tid, r = f >> 1, kq = (f & 1) * 8;
        float4 na2 = *(const float4*)&X[(m0 + r) * HIDD + k0 + kq + 4];
        float4 nb2 = *(const float4*)&Wm[(n0 + r) * HIDD + k0 + kq + 4];
        unsigned* da = &As[r][kq];
        da[0] = f2t(na.x); da[1] = f2t(na.y); da[2] = f2t(na.z); da[3] = f2t(na.w);
        da[4] = f2t(na2.x); da[5] = f2t(na2.y); da[6] = f2t(na2.z); da[7] = f2t(na2.w);
        unsigned* db = &Bs[r][kq];
        db[0] = f2t(nb.x); db[1] = f2t(nb.y); db[2] = f2t(nb.z); db[3] = f2t(nb.w);
        db[4] = f2t(nb2.x); db[5] = f2t(nb2.y); db[6] = f2t(nb2.z); db[7] = f2t(nb2.w);
        __syncthreads();
        if (k0 + 16 < HIDD) {
            na = *(const float4*)&X[(m0 + r) * HIDD + k0 + 16 + kq];
            nb = *(const float4*)&Wm[(n0 + r) * HIDD + k0 + 16 + kq];
        }
        #pragma unroll
        for (int kk = 0; kk < 2; kk++) {
            unsigned a[2][4], b[4][2];
            #pragma unroll
            for (int i = 0; i < 2; i++) {
                a[i][0] = As[wm + i * 16 + g][kk * 8 + tig];
                a[i][1] = As[wm + i * 16 + g + 8][kk * 8 + tig];
                a[i][2] = As[wm + i * 16 + g][kk * 8 + tig + 4];
                a[i][3] = As[wm + i * 16 + g + 8][kk * 8 + tig + 4];
            }
            #pragma unroll
            for (int j = 0; j < 4; j++) {
                b[j][0] = Bs[wn + j * 8 + g][kk * 8 + tig];
                b[j][1] = Bs[wn + j * 8 + g][kk * 8 + tig + 4];
            }
            #pragma unroll
            for (int i = 0; i < 2; i++)
                #pragma unroll
                for (int j = 0; j < 4; j++) mma8(acc[i][j], a[i], b[j]);
        }
        __syncthreads();
    }

    #pragma unroll
    for (int i = 0; i < 2; i++) {
        #pragma unroll
        for (int rh = 0; rh < 2; rh++) {
            int m = m0 + wm + i * 16 + g + rh * 8;
            #pragma unroll
            for (int j = 0; j < 4; j++) {
                #pragma unroll
                for (int cb = 0; cb < 2; cb++) {
                    int c = n0 + wn + j * 8 + tig * 2 + cb;
                    float vv = acc[i][j][rh * 2 + cb] + bias[c];
                    if (v < 2) {
                        vv = 0.5f * vv * (1.0f + erff(vv * 0.70710678118654752f));
                        float* dst = (v == 0) ? g_h1 : g_t1;
                        dst[m * DP + c] = f2tf(vv);
                    } else {
                        vv = (vv > 0.0f) ? vv : 0.01f * vv;
                        float* dst = (v == 2) ? g_head1 : g_tail1;
                        dst[m * DD + c] = vv;
                    }
                }
            }
        }
    }
}

// ---------------- stage 3: rank-1 bias precomputes (warp per row, 2 passes of 7 classes) ----------------
__global__ void hw_kernel(const float* __restrict__ W)
{
    int warp_id = (blockIdx.x * blockDim.x + threadIdx.x) >> 5;
    int lane = threadIdx.x & 31;
    if (warp_id >= 2 * BB * NN) return;
    int which = (warp_id >= BB * NN) ? 1 : 0;
    int bm = warp_id - which * BB * NN;
    const float* hr = (which ? g_tail1 : g_head1) + bm * DD;

    float h[9];
    #pragma unroll
    for (int s = 0; s < 9; s++) {
        int i = lane + 32 * s;
        h[s] = (i < DD) ? hr[i] : 0.0f;
    }

    const float* Wb = W + which * DD;
    float* dst = which ? g_tailW : g_headW;
    int b = bm / NN, m = bm % NN;

    #pragma unroll
    for (int half = 0; half < 2; half++) {
        float acc[7];
        #pragma unroll
        for (int k = 0; k < 7; k++) acc[k] = 0.0f;
        #pragma unroll
        for (int sg = 0; sg < 9; sg++) {
            int i = lane + 32 * sg;
            if (i < DD) {
                float hv = h[sg];
                #pragma unroll
                for (int k = 0; k < 7; k++)
                    acc[k] += hv * __ldg(&Wb[(half * 7 + k) * HSZ + i]);
            }
        }
        #pragma unroll
        for (int k = 0; k < 7; k++) {
            #pragma unroll
            for (int o = 16; o; o >>= 1) acc[k] += __shfl_xor_sync(0xffffffffu, acc[k], o);
        }
        if (lane == 0) {
            #pragma unroll
            for (int k = 0; k < 7; k++)
                dst[(b * CLSK + half * 7 + k) * NN + m] = acc[k];
        }
    }
}

// ---------------- stage 4: u = h1 @ bwT^T. block 128x64, 4 warps of 64x32, 3-stage cp.async ----------------
__global__ void __launch_bounds__(128) u_kernel()
{
    __shared__ unsigned As[3][128][20];
    __shared__ unsigned Bs[3][64][20];

    const int bk = blockIdx.z;
    const int b = bk / CLSK, kcls = bk % CLSK;
    const int m0 = blockIdx.x * 128;
    const int n0 = blockIdx.y * 64;
    const float* A  = g_h1 + b * NN * DP;
    const float* Bm = g_bwT + kcls * DP * DP;
    const int tid = threadIdx.x;
    const int w = tid >> 5, lane = tid & 31, g = lane >> 2, tig = lane & 3;
    const int wm = (w >> 1) * 64, wn = (w & 1) * 32;

    float acc[4][4][4] = {};

    #define U_STAGE(buf, k0)                                                     \
        do { _Pragma("unroll")                                                   \
        for (int h = 0; h < 4; h++) {                                            \
            int f = tid + h * 128;                                               \
            int r = f >> 2, kq = (f & 3) * 4;                                    \
            cp16(&As[buf][r][kq], &A[(m0 + r) * DP + (k0) + kq]);                \
        } _Pragma("unroll")                                                      \
        for (int h = 0; h < 2; h++) {                                            \
            int f = tid + h * 128;                                               \
            int r = f >> 2, kq = (f & 3) * 4;                                    \
            cp16(&Bs[buf][r][kq], &Bm[(n0 + r) * DP + (k0) + kq]);               \
        } } while (0)

    U_STAGE(0, 0);  CP_COMMIT();
    U_STAGE(1, 16); CP_COMMIT();

    const int NT = DP / 16;  // 17
    int cur = 0;
    for (int kt = 0; kt < NT; kt++) {
        if (kt + 1 < NT) CP_WAIT(1); else CP_WAIT(0);
        __syncthreads();
        if (kt + 2 < NT) {
            int nxt = cur + 2; if (nxt >= 3) nxt -= 3;
            U_STAGE(nxt, (kt + 2) * 16);
            CP_COMMIT();
        }
        #pragma unroll
        for (int kk = 0; kk < 2; kk++) {
            unsigned a[4][4], b2[4][2];
            #pragma unroll
            for (int i = 0; i < 4; i++) {
                a[i][0] = As[cur][wm + i * 16 + g][kk * 8 + tig];
                a[i][1] = As[cur][wm + i * 16 + g + 8][kk * 8 + tig];
                a[i][2] = As[cur][wm + i * 16 + g][kk * 8 + tig + 4];
                a[i][3] = As[cur][wm + i * 16 + g + 8][kk * 8 + tig + 4];
            }
            #pragma unroll
            for (int j = 0; j < 4; j++) {
                b2[j][0] = Bs[cur][wn + j * 8 + g][kk * 8 + tig];
                b2[j][1] = Bs[cur][wn + j * 8 + g][kk * 8 + tig + 4];
            }
            #pragma unroll
            for (int i = 0; i < 4; i++)
                #pragma unroll
                for (int j = 0; j < 4; j++) mma8(acc[i][j], a[i], b2[j]);
        }
        if (++cur == 3) cur = 0;
    }

    float* U = g_u + bk * NN * DP;
    #pragma unroll
    for (int i = 0; i < 4; i++) {
        #pragma unroll
        for (int rh = 0; rh < 2; rh++) {
            int m = m0 + wm + i * 16 + g + rh * 8;
            #pragma unroll
            for (int j = 0; j < 4; j++) {
                int c = n0 + wn + j * 8 + tig * 2;
                if (c + 1 < DP) {
                    float2 vv = make_float2(f2tf(acc[i][j][rh * 2 + 0]),
                                            f2tf(acc[i][j][rh * 2 + 1]));
                    *(float2*)&U[m * DP + c] = vv;
                }
            }
        }
    }
}

// ---------------- stage 5: out = u @ t1^T + biases. block 128x128, 4 warps of 64x64 ----------------
#define O_TILE_U (128 * 20)
__global__ void __launch_bounds__(128) out_kernel(float* __restrict__ out)
{
    extern __shared__ unsigned dyn[];
    unsigned (*As)[128][20] = (unsigned(*)[128][20])dyn;
    unsigned (*Bs)[128][20] = (unsigned(*)[128][20])(dyn + 3 * O_TILE_U);
    __shared__ float sHW[128], sTW[128], sSB[NPOS];

    const int bk = blockIdx.z;
    const int b = bk / CLSK, kcls = bk % CLSK;
    const int m0 = blockIdx.x * 128;
    const int n0 = blockIdx.y * 128;
    const float* A  = g_u + bk * NN * DP;
    const float* Bt = g_t1 + b * NN * DP;
    const int tid = threadIdx.x;
    const int w = tid >> 5, lane = tid & 31, g = lane >> 2, tig = lane & 3;
    const int wm = (w >> 1) * 64, wn = (w & 1) * 64;

    if (tid < 128) {
        sHW[tid] = g_headW[bk * NN + m0 + tid];
        sTW[tid] = g_tailW[bk * NN + n0 + tid];
    }
    if (tid < NPOS) sSB[tid] = g_sbias[kcls * NPOS + tid];

    float acc[4][8][4] = {};

    #define O_STAGE(buf, k0)                                                     \
        do { _Pragma("unroll")                                                   \
        for (int h = 0; h < 4; h++) {                                            \
            int f = tid + h * 128;                                               \
            int r = f >> 2, kq = (f & 3) * 4;                                    \
            cp16(&As[buf][r][kq], &A[(m0 + r) * DP + (k0) + kq]);                \
            cp16(&Bs[buf][r][kq], &Bt[(n0 + r) * DP + (k0) + kq]);               \
        } } while (0)

    O_STAGE(0, 0);  CP_COMMIT();
    O_STAGE(1, 16); CP_COMMIT();

    const int NT = DP / 16;  // 17
    int cur = 0;
    for (int kt = 0; kt < NT; kt++) {
        if (kt + 1 < NT) CP_WAIT(1); else CP_WAIT(0);
        __syncthreads();
        if (kt + 2 < NT) {
            int nxt = cur + 2; if (nxt >= 3) nxt -= 3;
            O_STAGE(nxt, (kt + 2) * 16);
            CP_COMMIT();
        }
        #pragma unroll
        for (int kk = 0; kk < 2; kk++) {
            unsigned a[4][4], b2[8][2];
            #pragma unroll
            for (int i = 0; i < 4; i++) {
                a[i][0] = As[cur][wm + i * 16 + g][kk * 8 + tig];
                a[i][1] = As[cur][wm + i * 16 + g + 8][kk * 8 + tig];
                a[i][2] = As[cur][wm + i * 16 + g][kk * 8 + tig + 4];
                a[i][3] = As[cur][wm + i * 16 + g + 8][kk * 8 + tig + 4];
            }
            #pragma unroll
            for (int j = 0; j < 8; j++) {
                b2[j][0] = Bs[cur][wn + j * 8 + g][kk * 8 + tig];
                b2[j][1] = Bs[cur][wn + j * 8 + g][kk * 8 + tig + 4];
            }
            #pragma unroll
            for (int i = 0; i < 4; i++)
                #pragma unroll
                for (int j = 0; j < 8; j++) mma8(acc[i][j], a[i], b2[j]);
        }
        if (++cur == 3) cur = 0;
    }

    #pragma unroll
    for (int i = 0; i < 4; i++) {
        #pragma unroll
        for (int rh = 0; rh < 2; rh++) {
            int ml = wm + i * 16 + g + rh * 8;
            int m = m0 + ml;
            float hv = sHW[ml];
            #pragma unroll
            for (int j = 0; j < 8; j++) {
                int cl = wn + j * 8 + tig * 2;
                int n = n0 + cl;
                int d0 = n - m;     d0 = (d0 < -15) ? -15 : (d0 > 14 ? 14 : d0);
                int d1 = n + 1 - m; d1 = (d1 < -15) ? -15 : (d1 > 14 ? 14 : d1);
                float2 vv;
                vv.x = acc[i][j][rh * 2 + 0] + hv + sTW[cl]     + sSB[d0 + 15];
                vv.y = acc[i][j][rh * 2 + 1] + hv + sTW[cl + 1] + sSB[d1 + 15];
                *(float2*)&out[(bk * NN + m) * NN + n] = vv;
            }
        }
    }
}

// ---------------- launch ----------------
extern "C" void kernel_launch(void* const* d_in, const int* in_sizes, int n_in,
                              void* d_out, int out_size)
{
    const float* x   = (const float*)d_in[0];
    const float* y   = (const float*)d_in[1];
    // d_in[2] = z : dead input
    const float* w1  = (const float*)d_in[3];
    const float* b1  = (const float*)d_in[4];
    const float* w2  = (const float*)d_in[5];
    const float* b2  = (const float*)d_in[6];
    const float* hw  = (const float*)d_in[7];
    const float* hb  = (const float*)d_in[8];
    const float* tw  = (const float*)d_in[9];
    const float* tb  = (const float*)d_in[10];
    const float* bw  = (const float*)d_in[11];
    const float* W   = (const float*)d_in[12];
    const float* se  = (const float*)d_in[13];
    float* out = (float*)d_out;

    const int OUT_SMEM = 3 * 2 * O_TILE_U * 4;   // 61440 bytes
    static int attr_done = 0;
    if (!attr_done) {
        cudaFuncSetAttribute(out_kernel, cudaFuncAttributeMaxDynamicSharedMemorySize, OUT_SMEM);
        attr_done = 1;
    }

    prep_kernel<<<TR_BLOCKS + 5, 256>>>(bw, W, se);
    proj_kernel<<<dim3(16, 4, 4), 128>>>(x, y, w1, b1, w2, b2, hw, hb, tw, tb);
    hw_kernel<<<256, 256>>>(W);
    u_kernel<<<dim3(4, 5, BB * CLSK), 128>>>();
    out_kernel<<<dim3(4, 4, BB * CLSK), 128, OUT_SMEM>>>(out);
}

// round 10
// speedup vs baseline: 1.2395x; 1.1065x over previous
#include <cuda_runtime.h>
#include <cuda_fp16.h>
#include <math.h>
#include <stdint.h>

// ---------------- problem constants ----------------
#define BB   2
#define NN   512
#define HIDD 768
#define BIAF 256
#define DD   257      // BIAF + 1
#define DP   288      // DD padded to 9*32 (fp16 K-tiles of 32) — zero pad
#define CLSK 14
#define HSZ  539      // 2*(BIAF+1) + 25
#define NPOS 30
#define SDIM 25

// ---------------- device scratch ----------------
__device__ __half g_h1h[BB * NN * DP];                 // fp16 gelu(x@mlp1)+1, zero pad
__device__ __half g_t1h[BB * NN * DP];
__device__ float  g_head1[BB * NN * DD];               // full precision (for bias dots)
__device__ float  g_tail1[BB * NN * DD];
__device__ __half g_uh[BB * CLSK * NN * DP];           // fp16 h1 @ biaf_W[k]
__device__ __half g_bwTh[CLSK * DP * DP + 64 * DP];    // fp16 [k][j][i], zero pad + slack (zero-init)
__device__ float  g_headW[BB * CLSK * NN];
__device__ float  g_tailW[BB * CLSK * NN];
__device__ float  g_sbias[CLSK * NPOS];

// ---------------- helpers ----------------
__device__ __forceinline__ unsigned f2t(float f) {
    unsigned u; asm("cvt.rna.tf32.f32 %0, %1;" : "=r"(u) : "f"(f)); return u;
}
__device__ __forceinline__ void mma8(float c[4], const unsigned a[4], const unsigned b[2]) {
    asm volatile("mma.sync.aligned.m16n8k8.row.col.f32.tf32.tf32.f32 "
                 "{%0,%1,%2,%3}, {%4,%5,%6,%7}, {%8,%9}, {%0,%1,%2,%3};"
                 : "+f"(c[0]), "+f"(c[1]), "+f"(c[2]), "+f"(c[3])
                 : "r"(a[0]), "r"(a[1]), "r"(a[2]), "r"(a[3]), "r"(b[0]), "r"(b[1]));
}
__device__ __forceinline__ void mma16(float c[4], const unsigned a[4], const unsigned b[2]) {
    asm volatile("mma.sync.aligned.m16n8k16.row.col.f32.f16.f16.f32 "
                 "{%0,%1,%2,%3}, {%4,%5,%6,%7}, {%8,%9}, {%0,%1,%2,%3};"
                 : "+f"(c[0]), "+f"(c[1]), "+f"(c[2]), "+f"(c[3])
                 : "r"(a[0]), "r"(a[1]), "r"(a[2]), "r"(a[3]), "r"(b[0]), "r"(b[1]));
}
__device__ __forceinline__ void cp16(void* dst, const void* src) {
    unsigned d = (unsigned)__cvta_generic_to_shared(dst);
    asm volatile("cp.async.ca.shared.global [%0], [%1], 16;" :: "r"(d), "l"(src));
}
#define CP_COMMIT() asm volatile("cp.async.commit_group;")
#define CP_WAIT(n)  asm volatile("cp.async.wait_group %0;" :: "n"(n))

// ---------------- prep: fused transpose(biaf_W) + pad/ones + size-bias ----------------
#define TR_BLOCKS (9 * 9 * CLSK)
__global__ void prep_kernel(const float* __restrict__ bw, const float* __restrict__ W,
                            const float* __restrict__ se)
{
    int bi = blockIdx.x;
    int tid = threadIdx.x;

    if (bi < TR_BLOCKS) {
        __shared__ float tile[32][33];
        int k = bi / 81;
        int rem = bi % 81;
        int i0 = (rem / 9) * 32, j0 = (rem % 9) * 32;
        int tx = tid & 31, ty = tid >> 5;
        #pragma unroll
        for (int r = 0; r < 4; r++) {
            int i = i0 + ty + r * 8, j = j0 + tx;
            tile[ty + r * 8][tx] = (i < DD && j < DD) ? bw[(k * DD + i) * DD + j] : 0.0f;
        }
        __syncthreads();
        #pragma unroll
        for (int r = 0; r < 4; r++) {
            int j = j0 + ty + r * 8, i = i0 + tx;
            if (j < DP && i < DP)
                g_bwTh[(k * DP + j) * DP + i] = __float2half_rn(tile[tx][ty + r * 8]);
        }
        return;
    }

    if (bi < TR_BLOCKS + 4) {
        int bm = (bi - TR_BLOCKS) * 256 + tid;
        if (bm < BB * NN) {
            g_h1h[bm * DP + 256] = __float2half_rn(1.0f);
            g_t1h[bm * DP + 256] = __float2half_rn(1.0f);
            #pragma unroll
            for (int j = 257; j < DP; j++) {
                g_h1h[bm * DP + j] = __float2half_rn(0.0f);
                g_t1h[bm * DP + j] = __float2half_rn(0.0f);
            }
            g_head1[bm * DD + 256] = 1.0f;
            g_tail1[bm * DD + 256] = 1.0f;
        }
        return;
    }

    for (int idx = tid; idx < CLSK * NPOS; idx += 256) {
        int k = idx / NPOS, p = idx % NPOS;
        float s = 0.0f;
        #pragma unroll
        for (int d = 0; d < SDIM; d++) s += se[p * SDIM + d] * W[k * HSZ + 2 * DD + d];
        g_sbias[idx] = s;
    }
}

// ---------------- stage 1: projections via tf32 mma (fp32 inputs). 64x64 tiles, 128 thr ----------------
__global__ void proj_kernel(const float* __restrict__ x, const float* __restrict__ y,
                            const float* __restrict__ w1, const float* __restrict__ b1,
                            const float* __restrict__ w2, const float* __restrict__ b2,
                            const float* __restrict__ hw, const float* __restrict__ hb,
                            const float* __restrict__ tw, const float* __restrict__ tb)
{
    __shared__ unsigned As[64][20];
    __shared__ unsigned Bs[64][20];

    const int v = blockIdx.z;
    const float* X = (v == 1) ? y : x;
    const float* Wm; const float* bias;
    if (v == 0)      { Wm = w1; bias = b1; }
    else if (v == 1) { Wm = w2; bias = b2; }
    else if (v == 2) { Wm = hw; bias = hb; }
    else             { Wm = tw; bias = tb; }

    const int m0 = blockIdx.x * 64;
    const int n0 = blockIdx.y * 64;
    const int tid = threadIdx.x;
    const int w = tid >> 5, lane = tid & 31, g = lane >> 2, tig = lane & 3;
    const int wm = (w >> 1) * 32, wn = (w & 1) * 32;

    float acc[2][4][4] = {};
    float4 na, nb;
    {
        int f = tid, r = f >> 1, kq = (f & 1) * 8;
        na = *(const float4*)&X[(m0 + r) * HIDD + kq];
        nb = *(const float4*)&Wm[(n0 + r) * HIDD + kq];
    }

    for (int k0 = 0; k0 < HIDD; k0 += 16) {
        int f = tid, r = f >> 1, kq = (f & 1) * 8;
        float4 na2 = *(const float4*)&X[(m0 + r) * HIDD + k0 + kq + 4];
        float4 nb2 = *(const float4*)&Wm[(n0 + r) * HIDD + k0 + kq + 4];
        unsigned* da = &As[r][kq];
        da[0] = f2t(na.x); da[1] = f2t(na.y); da[2] = f2t(na.z); da[3] = f2t(na.w);
        da[4] = f2t(na2.x); da[5] = f2t(na2.y); da[6] = f2t(na2.z); da[7] = f2t(na2.w);
        unsigned* db = &Bs[r][kq];
        db[0] = f2t(nb.x); db[1] = f2t(nb.y); db[2] = f2t(nb.z); db[3] = f2t(nb.w);
        db[4] = f2t(nb2.x); db[5] = f2t(nb2.y); db[6] = f2t(nb2.z); db[7] = f2t(nb2.w);
        __syncthreads();
        if (k0 + 16 < HIDD) {
            na = *(const float4*)&X[(m0 + r) * HIDD + k0 + 16 + kq];
            nb = *(const float4*)&Wm[(n0 + r) * HIDD + k0 + 16 + kq];
        }
        #pragma unroll
        for (int kk = 0; kk < 2; kk++) {
            unsigned a[2][4], b[4][2];
            #pragma unroll
            for (int i = 0; i < 2; i++) {
                a[i][0] = As[wm + i * 16 + g][kk * 8 + tig];
                a[i][1] = As[wm + i * 16 + g + 8][kk * 8 + tig];
                a[i][2] = As[wm + i * 16 + g][kk * 8 + tig + 4];
                a[i][3] = As[wm + i * 16 + g + 8][kk * 8 + tig + 4];
            }
            #pragma unroll
            for (int j = 0; j < 4; j++) {
                b[j][0] = Bs[wn + j * 8 + g][kk * 8 + tig];
                b[j][1] = Bs[wn + j * 8 + g][kk * 8 + tig + 4];
            }
            #pragma unroll
            for (int i = 0; i < 2; i++)
                #pragma unroll
                for (int j = 0; j < 4; j++) mma8(acc[i][j], a[i], b[j]);
        }
        __syncthreads();
    }

    #pragma unroll
    for (int i = 0; i < 2; i++) {
        #pragma unroll
        for (int rh = 0; rh < 2; rh++) {
            int m = m0 + wm + i * 16 + g + rh * 8;
            #pragma unroll
            for (int j = 0; j < 4; j++) {
                #pragma unroll
                for (int cb = 0; cb < 2; cb++) {
                    int c = n0 + wn + j * 8 + tig * 2 + cb;
                    float vv = acc[i][j][rh * 2 + cb] + bias[c];
                    if (v < 2) {
                        vv = 0.5f * vv * (1.0f + erff(vv * 0.70710678118654752f));
                        __half* dst = (v == 0) ? g_h1h : g_t1h;
                        dst[m * DP + c] = __float2half_rn(vv);
                    } else {
                        vv = (vv > 0.0f) ? vv : 0.01f * vv;
                        float* dst = (v == 2) ? g_head1 : g_tail1;
                        dst[m * DD + c] = vv;
                    }
                }
            }
        }
    }
}

// ---------------- stage 3: rank-1 bias precomputes (warp per row, 2 passes of 7 classes) ----------------
__global__ void hw_kernel(const float* __restrict__ W)
{
    int warp_id = (blockIdx.x * blockDim.x + threadIdx.x) >> 5;
    int lane = threadIdx.x & 31;
    if (warp_id >= 2 * BB * NN) return;
    int which = (warp_id >= BB * NN) ? 1 : 0;
    int bm = warp_id - which * BB * NN;
    const float* hr = (which ? g_tail1 : g_head1) + bm * DD;

    float h[9];
    #pragma unroll
    for (int s = 0; s < 9; s++) {
        int i = lane + 32 * s;
        h[s] = (i < DD) ? hr[i] : 0.0f;
    }

    const float* Wb = W + which * DD;
    float* dst = which ? g_tailW : g_headW;
    int b = bm / NN, m = bm % NN;

    #pragma unroll
    for (int half = 0; half < 2; half++) {
        float acc[7];
        #pragma unroll
        for (int k = 0; k < 7; k++) acc[k] = 0.0f;
        #pragma unroll
        for (int sg = 0; sg < 9; sg++) {
            int i = lane + 32 * sg;
            if (i < DD) {
                float hv = h[sg];
                #pragma unroll
                for (int k = 0; k < 7; k++)
                    acc[k] += hv * __ldg(&Wb[(half * 7 + k) * HSZ + i]);
            }
        }
        #pragma unroll
        for (int k = 0; k < 7; k++) {
            #pragma unroll
            for (int o = 16; o; o >>= 1) acc[k] += __shfl_xor_sync(0xffffffffu, acc[k], o);
        }
        if (lane == 0) {
            #pragma unroll
            for (int k = 0; k < 7; k++)
                dst[(b * CLSK + half * 7 + k) * NN + m] = acc[k];
        }
    }
}

// ---------------- stage 4: u = h1 @ bwT^T (fp16). block 128x64, 4 warps of 64x32 ----------------
// smem rows: 32 halves = 16 half2 data + 4 pad -> stride 20 half2 (conflict-free pattern)
__global__ void __launch_bounds__(128) u_kernel()
{
    __shared__ unsigned As[3][128][20];
    __shared__ unsigned Bs[3][64][20];

    const int bk = blockIdx.z;
    const int b = bk / CLSK, kcls = bk % CLSK;
    const int m0 = blockIdx.x * 128;
    const int n0 = blockIdx.y * 64;
    const __half* A  = g_h1h + b * NN * DP;
    const __half* Bm = g_bwTh + kcls * DP * DP;
    const int tid = threadIdx.x;
    const int w = tid >> 5, lane = tid & 31, g = lane >> 2, tig = lane & 3;
    const int wm = (w >> 1) * 64, wn = (w & 1) * 32;

    float acc[4][4][4] = {};

    #define U_STAGE(buf, k0)                                                     \
        do { _Pragma("unroll")                                                   \
        for (int h = 0; h < 4; h++) {                                            \
            int f = tid + h * 128;                                               \
            int r = f >> 2, q = f & 3;                                           \
            cp16(&As[buf][r][q * 4], &A[(m0 + r) * DP + (k0) + q * 8]);          \
        } _Pragma("unroll")                                                      \
        for (int h = 0; h < 2; h++) {                                            \
            int f = tid + h * 128;                                               \
            int r = f >> 2, q = f & 3;                                           \
            cp16(&Bs[buf][r][q * 4], &Bm[(n0 + r) * DP + (k0) + q * 8]);         \
        } } while (0)

    U_STAGE(0, 0);  CP_COMMIT();
    U_STAGE(1, 32); CP_COMMIT();

    const int NT = DP / 32;  // 9
    int cur = 0;
    for (int kt = 0; kt < NT; kt++) {
        if (kt + 1 < NT) CP_WAIT(1); else CP_WAIT(0);
        __syncthreads();
        if (kt + 2 < NT) {
            int nxt = cur + 2; if (nxt >= 3) nxt -= 3;
            U_STAGE(nxt, (kt + 2) * 32);
            CP_COMMIT();
        }
        #pragma unroll
        for (int kk = 0; kk < 2; kk++) {
            unsigned a[4][4], b2[4][2];
            #pragma unroll
            for (int i = 0; i < 4; i++) {
                a[i][0] = As[cur][wm + i * 16 + g][kk * 8 + tig];
                a[i][1] = As[cur][wm + i * 16 + g + 8][kk * 8 + tig];
                a[i][2] = As[cur][wm + i * 16 + g][kk * 8 + tig + 4];
                a[i][3] = As[cur][wm + i * 16 + g + 8][kk * 8 + tig + 4];
            }
            #pragma unroll
            for (int j = 0; j < 4; j++) {
                b2[j][0] = Bs[cur][wn + j * 8 + g][kk * 8 + tig];
                b2[j][1] = Bs[cur][wn + j * 8 + g][kk * 8 + tig + 4];
            }
            #pragma unroll
            for (int i = 0; i < 4; i++)
                #pragma unroll
                for (int j = 0; j < 4; j++) mma16(acc[i][j], a[i], b2[j]);
        }
        if (++cur == 3) cur = 0;
    }

    __half* U = g_uh + bk * NN * DP;
    #pragma unroll
    for (int i = 0; i < 4; i++) {
        #pragma unroll
        for (int rh = 0; rh < 2; rh++) {
            int m = m0 + wm + i * 16 + g + rh * 8;
            #pragma unroll
            for (int j = 0; j < 4; j++) {
                int c = n0 + wn + j * 8 + tig * 2;
                if (c < DP) {
                    __half2 hv = __floats2half2_rn(acc[i][j][rh * 2 + 0],
                                                   acc[i][j][rh * 2 + 1]);
                    *(__half2*)&U[m * DP + c] = hv;
                }
            }
        }
    }
}

// ---------------- stage 5: out = u @ t1^T + biases (fp16). block 128x128, 4 warps of 64x64 ----------------
#define O_TILE_U (128 * 20)
__global__ void __launch_bounds__(128) out_kernel(float* __restrict__ out)
{
    extern __shared__ unsigned dyn[];
    unsigned (*As)[128][20] = (unsigned(*)[128][20])dyn;
    unsigned (*Bs)[128][20] = (unsigned(*)[128][20])(dyn + 3 * O_TILE_U);
    __shared__ float sHW[128], sTW[128], sSB[NPOS];

    const int bk = blockIdx.z;
    const int b = bk / CLSK, kcls = bk % CLSK;
    const int m0 = blockIdx.x * 128;
    const int n0 = blockIdx.y * 128;
    const __half* A  = g_uh + bk * NN * DP;
    const __half* Bt = g_t1h + b * NN * DP;
    const int tid = threadIdx.x;
    const int w = tid >> 5, lane = tid & 31, g = lane >> 2, tig = lane & 3;
    const int wm = (w >> 1) * 64, wn = (w & 1) * 64;

    if (tid < 128) {
        sHW[tid] = g_headW[bk * NN + m0 + tid];
        sTW[tid] = g_tailW[bk * NN + n0 + tid];
    }
    if (tid < NPOS) sSB[tid] = g_sbias[kcls * NPOS + tid];

    float acc[4][8][4] = {};

    #define O_STAGE(buf, k0)                                                     \
        do { _Pragma("unroll")                                                   \
        for (int h = 0; h < 4; h++) {                                            \
            int f = tid + h * 128;                                               \
            int r = f >> 2, q = f & 3;                                           \
            cp16(&As[buf][r][q * 4], &A[(m0 + r) * DP + (k0) + q * 8]);          \
            cp16(&Bs[buf][r][q * 4], &Bt[(n0 + r) * DP + (k0) + q * 8]);         \
        } } while (0)

    O_STAGE(0, 0);  CP_COMMIT();
    O_STAGE(1, 32); CP_COMMIT();

    const int NT = DP / 32;  // 9
    int cur = 0;
    for (int kt = 0; kt < NT; kt++) {
        if (kt + 1 < NT) CP_WAIT(1); else CP_WAIT(0);
        __syncthreads();
        if (kt + 2 < NT) {
            int nxt = cur + 2; if (nxt >= 3) nxt -= 3;
            O_STAGE(nxt, (kt + 2) * 32);
            CP_COMMIT();
        }
        #pragma unroll
        for (int kk = 0; kk < 2; kk++) {
            unsigned a[4][4], b2[8][2];
            #pragma unroll
            for (int i = 0; i < 4; i++) {
                a[i][0] = As[cur][wm + i * 16 + g][kk * 8 + tig];
                a[i][1] = As[cur][wm + i * 16 + g + 8][kk * 8 + tig];
                a[i][2] = As[cur][wm + i * 16 + g][kk * 8 + tig + 4];
                a[i][3] = As[cur][wm + i * 16 + g + 8][kk * 8 + tig + 4];
            }
            #pragma unroll
            for (int j = 0; j < 8; j++) {
                b2[j][0] = Bs[cur][wn + j * 8 + g][kk * 8 + tig];
                b2[j][1] = Bs[cur][wn + j * 8 + g][kk * 8 + tig + 4];
            }
            #pragma unroll
            for (int i = 0; i < 4; i++)
                #pragma unroll
                for (int j = 0; j < 8; j++) mma16(acc[i][j], a[i], b2[j]);
        }
        if (++cur == 3) cur = 0;
    }

    #pragma unroll
    for (int i = 0; i < 4; i++) {
        #pragma unroll
        for (int rh = 0; rh < 2; rh++) {
            int ml = wm + i * 16 + g + rh * 8;
            int m = m0 + ml;
            float hv = sHW[ml];
            #pragma unroll
            for (int j = 0; j < 8; j++) {
                int cl = wn + j * 8 + tig * 2;
                int n = n0 + cl;
                int d0 = n - m;     d0 = (d0 < -15) ? -15 : (d0 > 14 ? 14 : d0);
                int d1 = n + 1 - m; d1 = (d1 < -15) ? -15 : (d1 > 14 ? 14 : d1);
                float2 vv;
                vv.x = acc[i][j][rh * 2 + 0] + hv + sTW[cl]     + sSB[d0 + 15];
                vv.y = acc[i][j][rh * 2 + 1] + hv + sTW[cl + 1] + sSB[d1 + 15];
                *(float2*)&out[(bk * NN + m) * NN + n] = vv;
            }
        }
    }
}

// ---------------- launch ----------------
extern "C" void kernel_launch(void* const* d_in, const int* in_sizes, int n_in,
                              void* d_out, int out_size)
{
    const float* x   = (const float*)d_in[0];
    const float* y   = (const float*)d_in[1];
    // d_in[2] = z : dead input
    const float* w1  = (const float*)d_in[3];
    const float* b1  = (const float*)d_in[4];
    const float* w2  = (const float*)d_in[5];
    const float* b2  = (const float*)d_in[6];
    const float* hw  = (const float*)d_in[7];
    const float* hb  = (const float*)d_in[8];
    const float* tw  = (const float*)d_in[9];
    const float* tb  = (const float*)d_in[10];
    const float* bw  = (const float*)d_in[11];
    const float* W   = (const float*)d_in[12];
    const float* se  = (const float*)d_in[13];
    float* out = (float*)d_out;

    const int OUT_SMEM = 3 * 2 * O_TILE_U * 4;   // 61440 bytes
    static int attr_done = 0;
    if (!attr_done) {
        cudaFuncSetAttribute(out_kernel, cudaFuncAttributeMaxDynamicSharedMemorySize, OUT_SMEM);
        attr_done = 1;
    }

    prep_kernel<<<TR_BLOCKS + 5, 256>>>(bw, W, se);
    proj_kernel<<<dim3(16, 4, 4), 128>>>(x, y, w1, b1, w2, b2, hw, hb, tw, tb);
    hw_kernel<<<256, 256>>>(W);
    u_kernel<<<dim3(4, 5, BB * CLSK), 128>>>();
    out_kernel<<<dim3(4, 4, BB * CLSK), 128, OUT_SMEM>>>(out);
}

// round 11
// speedup vs baseline: 1.4542x; 1.1733x over previous
#include <cuda_runtime.h>
#include <cuda_fp16.h>
#include <math.h>
#include <stdint.h>

// ---------------- problem constants ----------------
#define BB   2
#define NN   512
#define HIDD 768
#define BIAF 256
#define DD   257      // BIAF + 1
#define DP   288      // DD padded to 9*32 (fp16 K-tiles of 32) — zero pad
#define CLSK 14
#define HSZ  539      // 2*(BIAF+1) + 25
#define NPOS 30
#define SDIM 25

// ---------------- device scratch ----------------
__device__ __half g_h1h[BB * NN * DP];                 // fp16 gelu(x@mlp1)+1, zero pad
__device__ __half g_t1h[BB * NN * DP];
__device__ float  g_head1[BB * NN * DD];               // full precision (for bias dots)
__device__ float  g_tail1[BB * NN * DD];
__device__ __half g_uh[BB * CLSK * NN * DP];           // fp16 h1 @ biaf_W[k]
__device__ __half g_bwTh[CLSK * DP * DP + 64 * DP];    // fp16 [k][j][i], zero pad + slack (zero-init)
__device__ float  g_headW[BB * CLSK * NN];
__device__ float  g_tailW[BB * CLSK * NN];
__device__ float  g_sbias[CLSK * NPOS];

// ---------------- helpers ----------------
__device__ __forceinline__ void mma16(float c[4], const unsigned a[4], const unsigned b[2]) {
    asm volatile("mma.sync.aligned.m16n8k16.row.col.f32.f16.f16.f32 "
                 "{%0,%1,%2,%3}, {%4,%5,%6,%7}, {%8,%9}, {%0,%1,%2,%3};"
                 : "+f"(c[0]), "+f"(c[1]), "+f"(c[2]), "+f"(c[3])
                 : "r"(a[0]), "r"(a[1]), "r"(a[2]), "r"(a[3]), "r"(b[0]), "r"(b[1]));
}
__device__ __forceinline__ void ldsm4(unsigned& r0, unsigned& r1, unsigned& r2, unsigned& r3,
                                      uint32_t a) {
    asm volatile("ldmatrix.sync.aligned.m8n8.x4.shared.b16 {%0,%1,%2,%3}, [%4];"
                 : "=r"(r0), "=r"(r1), "=r"(r2), "=r"(r3) : "r"(a));
}
__device__ __forceinline__ void cp16(void* dst, const void* src) {
    unsigned d = (unsigned)__cvta_generic_to_shared(dst);
    asm volatile("cp.async.ca.shared.global [%0], [%1], 16;" :: "r"(d), "l"(src));
}
#define CP_COMMIT() asm volatile("cp.async.commit_group;")
#define CP_WAIT(n)  asm volatile("cp.async.wait_group %0;" :: "n"(n))
__device__ __forceinline__ uint32_t s2u(const void* p) {
    uint32_t a;
    asm("{ .reg .u64 t; cvta.to.shared.u64 t, %1; cvt.u32.u64 %0, t; }" : "=r"(a) : "l"(p));
    return a;
}

// ---------------- prep: fused transpose(biaf_W) + pad/ones + size-bias ----------------
#define TR_BLOCKS (9 * 9 * CLSK)
__global__ void prep_kernel(const float* __restrict__ bw, const float* __restrict__ W,
                            const float* __restrict__ se)
{
    int bi = blockIdx.x;
    int tid = threadIdx.x;

    if (bi < TR_BLOCKS) {
        __shared__ float tile[32][33];
        int k = bi / 81;
        int rem = bi % 81;
        int i0 = (rem / 9) * 32, j0 = (rem % 9) * 32;
        int tx = tid & 31, ty = tid >> 5;
        #pragma unroll
        for (int r = 0; r < 4; r++) {
            int i = i0 + ty + r * 8, j = j0 + tx;
            tile[ty + r * 8][tx] = (i < DD && j < DD) ? bw[(k * DD + i) * DD + j] : 0.0f;
        }
        __syncthreads();
        #pragma unroll
        for (int r = 0; r < 4; r++) {
            int j = j0 + ty + r * 8, i = i0 + tx;
            if (j < DP && i < DP)
                g_bwTh[(k * DP + j) * DP + i] = __float2half_rn(tile[tx][ty + r * 8]);
        }
        return;
    }

    if (bi < TR_BLOCKS + 4) {
        int bm = (bi - TR_BLOCKS) * 256 + tid;
        if (bm < BB * NN) {
            g_h1h[bm * DP + 256] = __float2half_rn(1.0f);
            g_t1h[bm * DP + 256] = __float2half_rn(1.0f);
            #pragma unroll
            for (int j = 257; j < DP; j++) {
                g_h1h[bm * DP + j] = __float2half_rn(0.0f);
                g_t1h[bm * DP + j] = __float2half_rn(0.0f);
            }
            g_head1[bm * DD + 256] = 1.0f;
            g_tail1[bm * DD + 256] = 1.0f;
        }
        return;
    }

    for (int idx = tid; idx < CLSK * NPOS; idx += 256) {
        int k = idx / NPOS, p = idx % NPOS;
        float s = 0.0f;
        #pragma unroll
        for (int d = 0; d < SDIM; d++) s += se[p * SDIM + d] * W[k * HSZ + 2 * DD + d];
        g_sbias[idx] = s;
    }
}

// ---------------- stage 1: projections via fp16 mma16 + ldmatrix. 64x64 tiles, 128 thr ----------------
__global__ void proj_kernel(const float* __restrict__ x, const float* __restrict__ y,
                            const float* __restrict__ w1, const float* __restrict__ b1,
                            const float* __restrict__ w2, const float* __restrict__ b2,
                            const float* __restrict__ hw, const float* __restrict__ hb,
                            const float* __restrict__ tw, const float* __restrict__ tb)
{
    __shared__ unsigned As[64][20];
    __shared__ unsigned Bs[64][20];

    const int v = blockIdx.z;
    const float* X = (v == 1) ? y : x;
    const float* Wm; const float* bias;
    if (v == 0)      { Wm = w1; bias = b1; }
    else if (v == 1) { Wm = w2; bias = b2; }
    else if (v == 2) { Wm = hw; bias = hb; }
    else             { Wm = tw; bias = tb; }

    const int m0 = blockIdx.x * 64;
    const int n0 = blockIdx.y * 64;
    const int tid = threadIdx.x;
    const int w = tid >> 5, lane = tid & 31, g = lane >> 2, tig = lane & 3;
    const int wm = (w >> 1) * 32, wn = (w & 1) * 32;
    const int lrow = lane & 7, sel = lane >> 3;
    const int aMoff = (sel & 1) * 8, aKw = (sel >> 1) * 4;
    const int bNoff = (sel >> 1) * 8, bKw = (sel & 1) * 4;
    const uint32_t aBase = s2u(&As[0][0]);
    const uint32_t bBase = s2u(&Bs[0][0]);

    float acc[2][4][4] = {};

    for (int k0 = 0; k0 < HIDD; k0 += 32) {
        int r = tid >> 1, hs = tid & 1;
        const float* xs = &X[(m0 + r) * HIDD + k0 + hs * 16];
        const float* ws = &Wm[(n0 + r) * HIDD + k0 + hs * 16];
        unsigned* da = &As[r][hs * 8];
        unsigned* db = &Bs[r][hs * 8];
        #pragma unroll
        for (int e = 0; e < 4; e++) {
            float4 xv = *(const float4*)&xs[e * 4];
            float4 wv = *(const float4*)&ws[e * 4];
            __half2 x01 = __floats2half2_rn(xv.x, xv.y);
            __half2 x23 = __floats2half2_rn(xv.z, xv.w);
            __half2 w01 = __floats2half2_rn(wv.x, wv.y);
            __half2 w23 = __floats2half2_rn(wv.z, wv.w);
            da[e * 2]     = *(unsigned*)&x01;
            da[e * 2 + 1] = *(unsigned*)&x23;
            db[e * 2]     = *(unsigned*)&w01;
            db[e * 2 + 1] = *(unsigned*)&w23;
        }
        __syncthreads();
        #pragma unroll
        for (int kk = 0; kk < 2; kk++) {
            unsigned a[2][4], b[4][2];
            #pragma unroll
            for (int i = 0; i < 2; i++)
                ldsm4(a[i][0], a[i][1], a[i][2], a[i][3],
                      aBase + (((wm + i * 16 + aMoff + lrow) * 20) + kk * 8 + aKw) * 4);
            #pragma unroll
            for (int jp = 0; jp < 2; jp++)
                ldsm4(b[2 * jp][0], b[2 * jp][1], b[2 * jp + 1][0], b[2 * jp + 1][1],
                      bBase + (((wn + jp * 16 + bNoff + lrow) * 20) + kk * 8 + bKw) * 4);
            #pragma unroll
            for (int i = 0; i < 2; i++)
                #pragma unroll
                for (int j = 0; j < 4; j++) mma16(acc[i][j], a[i], b[j]);
        }
        __syncthreads();
    }

    #pragma unroll
    for (int i = 0; i < 2; i++) {
        #pragma unroll
        for (int rh = 0; rh < 2; rh++) {
            int m = m0 + wm + i * 16 + g + rh * 8;
            #pragma unroll
            for (int j = 0; j < 4; j++) {
                #pragma unroll
                for (int cb = 0; cb < 2; cb++) {
                    int c = n0 + wn + j * 8 + tig * 2 + cb;
                    float vv = acc[i][j][rh * 2 + cb] + bias[c];
                    if (v < 2) {
                        vv = 0.5f * vv * (1.0f + erff(vv * 0.70710678118654752f));
                        __half* dst = (v == 0) ? g_h1h : g_t1h;
                        dst[m * DP + c] = __float2half_rn(vv);
                    } else {
                        vv = (vv > 0.0f) ? vv : 0.01f * vv;
                        float* dst = (v == 2) ? g_head1 : g_tail1;
                        dst[m * DD + c] = vv;
                    }
                }
            }
        }
    }
}

// ---------------- stage 3: rank-1 bias precomputes (warp per row, 2 passes of 7 classes) ----------------
__global__ void hw_kernel(const float* __restrict__ W)
{
    int warp_id = (blockIdx.x * blockDim.x + threadIdx.x) >> 5;
    int lane = threadIdx.x & 31;
    if (warp_id >= 2 * BB * NN) return;
    int which = (warp_id >= BB * NN) ? 1 : 0;
    int bm = warp_id - which * BB * NN;
    const float* hr = (which ? g_tail1 : g_head1) + bm * DD;

    float h[9];
    #pragma unroll
    for (int s = 0; s < 9; s++) {
        int i = lane + 32 * s;
        h[s] = (i < DD) ? hr[i] : 0.0f;
    }

    const float* Wb = W + which * DD;
    float* dst = which ? g_tailW : g_headW;
    int b = bm / NN, m = bm % NN;

    #pragma unroll
    for (int half = 0; half < 2; half++) {
        float acc[7];
        #pragma unroll
        for (int k = 0; k < 7; k++) acc[k] = 0.0f;
        #pragma unroll
        for (int sg = 0; sg < 9; sg++) {
            int i = lane + 32 * sg;
            if (i < DD) {
                float hv = h[sg];
                #pragma unroll
                for (int k = 0; k < 7; k++)
                    acc[k] += hv * __ldg(&Wb[(half * 7 + k) * HSZ + i]);
            }
        }
        #pragma unroll
        for (int k = 0; k < 7; k++) {
            #pragma unroll
            for (int o = 16; o; o >>= 1) acc[k] += __shfl_xor_sync(0xffffffffu, acc[k], o);
        }
        if (lane == 0) {
            #pragma unroll
            for (int k = 0; k < 7; k++)
                dst[(b * CLSK + half * 7 + k) * NN + m] = acc[k];
        }
    }
}

// ---------------- stage 4: u = h1 @ bwT^T (fp16, ldmatrix). block 128x64, 4 warps of 64x32 ----------------
__global__ void __launch_bounds__(128) u_kernel()
{
    __shared__ unsigned As[3][128][20];
    __shared__ unsigned Bs[3][64][20];

    const int bk = blockIdx.z;
    const int b = bk / CLSK, kcls = bk % CLSK;
    const int m0 = blockIdx.x * 128;
    const int n0 = blockIdx.y * 64;
    const __half* A  = g_h1h + b * NN * DP;
    const __half* Bm = g_bwTh + kcls * DP * DP;
    const int tid = threadIdx.x;
    const int w = tid >> 5, lane = tid & 31, g = lane >> 2, tig = lane & 3;
    const int wm = (w >> 1) * 64, wn = (w & 1) * 32;
    const int lrow = lane & 7, sel = lane >> 3;
    const int aMoff = (sel & 1) * 8, aKw = (sel >> 1) * 4;
    const int bNoff = (sel >> 1) * 8, bKw = (sel & 1) * 4;

    float acc[4][4][4] = {};

    #define U_STAGE(buf, k0)                                                     \
        do { _Pragma("unroll")                                                   \
        for (int h = 0; h < 4; h++) {                                            \
            int f = tid + h * 128;                                               \
            int r = f >> 2, q = f & 3;                                           \
            cp16(&As[buf][r][q * 4], &A[(m0 + r) * DP + (k0) + q * 8]);          \
        } _Pragma("unroll")                                                      \
        for (int h = 0; h < 2; h++) {                                            \
            int f = tid + h * 128;                                               \
            int r = f >> 2, q = f & 3;                                           \
            cp16(&Bs[buf][r][q * 4], &Bm[(n0 + r) * DP + (k0) + q * 8]);         \
        } } while (0)

    U_STAGE(0, 0);  CP_COMMIT();
    U_STAGE(1, 32); CP_COMMIT();

    const int NT = DP / 32;  // 9
    int cur = 0;
    for (int kt = 0; kt < NT; kt++) {
        if (kt + 1 < NT) CP_WAIT(1); else CP_WAIT(0);
        __syncthreads();
        if (kt + 2 < NT) {
            int nxt = cur + 2; if (nxt >= 3) nxt -= 3;
            U_STAGE(nxt, (kt + 2) * 32);
            CP_COMMIT();
        }
        uint32_t aBase = s2u(&As[cur][0][0]);
        uint32_t bBase = s2u(&Bs[cur][0][0]);
        #pragma unroll
        for (int kk = 0; kk < 2; kk++) {
            unsigned a[4][4], b2[4][2];
            #pragma unroll
            for (int i = 0; i < 4; i++)
                ldsm4(a[i][0], a[i][1], a[i][2], a[i][3],
                      aBase + (((wm + i * 16 + aMoff + lrow) * 20) + kk * 8 + aKw) * 4);
            #pragma unroll
            for (int jp = 0; jp < 2; jp++)
                ldsm4(b2[2 * jp][0], b2[2 * jp][1], b2[2 * jp + 1][0], b2[2 * jp + 1][1],
                      bBase + (((wn + jp * 16 + bNoff + lrow) * 20) + kk * 8 + bKw) * 4);
            #pragma unroll
            for (int i = 0; i < 4; i++)
                #pragma unroll
                for (int j = 0; j < 4; j++) mma16(acc[i][j], a[i], b2[j]);
        }
        if (++cur == 3) cur = 0;
    }

    __half* U = g_uh + bk * NN * DP;
    #pragma unroll
    for (int i = 0; i < 4; i++) {
        #pragma unroll
        for (int rh = 0; rh < 2; rh++) {
            int m = m0 + wm + i * 16 + g + rh * 8;
            #pragma unroll
            for (int j = 0; j < 4; j++) {
                int c = n0 + wn + j * 8 + tig * 2;
                if (c < DP) {
                    __half2 hv = __floats2half2_rn(acc[i][j][rh * 2 + 0],
                                                   acc[i][j][rh * 2 + 1]);
                    *(__half2*)&U[m * DP + c] = hv;
                }
            }
        }
    }
}

// ---------------- stage 5: out = u @ t1^T + biases (fp16, ldmatrix). 128x128, 4 warps of 64x64 ----------------
#define O_TILE_U (128 * 20)
__global__ void __launch_bounds__(128) out_kernel(float* __restrict__ out)
{
    extern __shared__ unsigned dyn[];
    unsigned (*As)[128][20] = (unsigned(*)[128][20])dyn;
    unsigned (*Bs)[128][20] = (unsigned(*)[128][20])(dyn + 3 * O_TILE_U);
    __shared__ float sHW[128], sTW[128], sSB[NPOS];

    const int bk = blockIdx.z;
    const int b = bk / CLSK, kcls = bk % CLSK;
    const int m0 = blockIdx.x * 128;
    const int n0 = blockIdx.y * 128;
    const __half* A  = g_uh + bk * NN * DP;
    const __half* Bt = g_t1h + b * NN * DP;
    const int tid = threadIdx.x;
    const int w = tid >> 5, lane = tid & 31, g = lane >> 2, tig = lane & 3;
    const int wm = (w >> 1) * 64, wn = (w & 1) * 64;
    const int lrow = lane & 7, sel = lane >> 3;
    const int aMoff = (sel & 1) * 8, aKw = (sel >> 1) * 4;
    const int bNoff = (sel >> 1) * 8, bKw = (sel & 1) * 4;

    if (tid < 128) {
        sHW[tid] = g_headW[bk * NN + m0 + tid];
        sTW[tid] = g_tailW[bk * NN + n0 + tid];
    }
    if (tid < NPOS) sSB[tid] = g_sbias[kcls * NPOS + tid];

    float acc[4][8][4] = {};

    #define O_STAGE(buf, k0)                                                     \
        do { _Pragma("unroll")                                                   \
        for (int h = 0; h < 4; h++) {                                            \
            int f = tid + h * 128;                                               \
            int r = f >> 2, q = f & 3;                                           \
            cp16(&As[buf][r][q * 4], &A[(m0 + r) * DP + (k0) + q * 8]);          \
            cp16(&Bs[buf][r][q * 4], &Bt[(n0 + r) * DP + (k0) + q * 8]);         \
        } } while (0)

    O_STAGE(0, 0);  CP_COMMIT();
    O_STAGE(1, 32); CP_COMMIT();

    const int NT = DP / 32;  // 9
    int cur = 0;
    for (int kt = 0; kt < NT; kt++) {
        if (kt + 1 < NT) CP_WAIT(1); else CP_WAIT(0);
        __syncthreads();
        if (kt + 2 < NT) {
            int nxt = cur + 2; if (nxt >= 3) nxt -= 3;
            O_STAGE(nxt, (kt + 2) * 32);
            CP_COMMIT();
        }
        uint32_t aBase = s2u(&As[cur][0][0]);
        uint32_t bBase = s2u(&Bs[cur][0][0]);
        #pragma unroll
        for (int kk = 0; kk < 2; kk++) {
            unsigned a[4][4], b2[8][2];
            #pragma unroll
            for (int i = 0; i < 4; i++)
                ldsm4(a[i][0], a[i][1], a[i][2], a[i][3],
                      aBase + (((wm + i * 16 + aMoff + lrow) * 20) + kk * 8 + aKw) * 4);
            #pragma unroll
            for (int jp = 0; jp < 4; jp++)
                ldsm4(b2[2 * jp][0], b2[2 * jp][1], b2[2 * jp + 1][0], b2[2 * jp + 1][1],
                      bBase + (((wn + jp * 16 + bNoff + lrow) * 20) + kk * 8 + bKw) * 4);
            #pragma unroll
            for (int i = 0; i < 4; i++)
                #pragma unroll
                for (int j = 0; j < 8; j++) mma16(acc[i][j], a[i], b2[j]);
        }
        if (++cur == 3) cur = 0;
    }

    #pragma unroll
    for (int i = 0; i < 4; i++) {
        #pragma unroll
        for (int rh = 0; rh < 2; rh++) {
            int ml = wm + i * 16 + g + rh * 8;
            int m = m0 + ml;
            float hv = sHW[ml];
            #pragma unroll
            for (int j = 0; j < 8; j++) {
                int cl = wn + j * 8 + tig * 2;
                int n = n0 + cl;
                int d0 = n - m;     d0 = (d0 < -15) ? -15 : (d0 > 14 ? 14 : d0);
                int d1 = n + 1 - m; d1 = (d1 < -15) ? -15 : (d1 > 14 ? 14 : d1);
                float2 vv;
                vv.x = acc[i][j][rh * 2 + 0] + hv + sTW[cl]     + sSB[d0 + 15];
                vv.y = acc[i][j][rh * 2 + 1] + hv + sTW[cl + 1] + sSB[d1 + 15];
                *(float2*)&out[(bk * NN + m) * NN + n] = vv;
            }
        }
    }
}

// ---------------- launch ----------------
extern "C" void kernel_launch(void* const* d_in, const int* in_sizes, int n_in,
                              void* d_out, int out_size)
{
    const float* x   = (const float*)d_in[0];
    const float* y   = (const float*)d_in[1];
    // d_in[2] = z : dead input
    const float* w1  = (const float*)d_in[3];
    const float* b1  = (const float*)d_in[4];
    const float* w2  = (const float*)d_in[5];
    const float* b2  = (const float*)d_in[6];
    const float* hw  = (const float*)d_in[7];
    const float* hb  = (const float*)d_in[8];
    const float* tw  = (const float*)d_in[9];
    const float* tb  = (const float*)d_in[10];
    const float* bw  = (const float*)d_in[11];
    const float* W   = (const float*)d_in[12];
    const float* se  = (const float*)d_in[13];
    float* out = (float*)d_out;

    const int OUT_SMEM = 3 * 2 * O_TILE_U * 4;   // 61440 bytes
    static int attr_done = 0;
    if (!attr_done) {
        cudaFuncSetAttribute(out_kernel, cudaFuncAttributeMaxDynamicSharedMemorySize, OUT_SMEM);
        attr_done = 1;
    }

    prep_kernel<<<TR_BLOCKS + 5, 256>>>(bw, W, se);
    proj_kernel<<<dim3(16, 4, 4), 128>>>(x, y, w1, b1, w2, b2, hw, hb, tw, tb);
    hw_kernel<<<256, 256>>>(W);
    u_kernel<<<dim3(4, 5, BB * CLSK), 128>>>();
    out_kernel<<<dim3(4, 4, BB * CLSK), 128, OUT_SMEM>>>(out);
}

// round 12
// speedup vs baseline: 1.7435x; 1.1989x over previous
#include <cuda_runtime.h>
#include <cuda_fp16.h>
#include <math.h>
#include <stdint.h>

// ---------------- problem constants ----------------
#define BB   2
#define NN   512
#define HIDD 768
#define BIAF 256
#define DD   257      // BIAF + 1
#define DP   288      // DD padded to 9*32 (fp16 K-tiles of 32) — zero pad
#define CLSK 14
#define HSZ  539      // 2*(BIAF+1) + 25
#define NPOS 30
#define SDIM 25

// ---------------- device scratch ----------------
__device__ __half g_h1h[BB * NN * DP];                 // fp16 gelu(x@mlp1)+1, zero pad
__device__ __half g_t1h[BB * NN * DP];
__device__ float  g_head1[BB * NN * DD];               // full precision (for bias dots)
__device__ float  g_tail1[BB * NN * DD];
__device__ __half g_uh[BB * CLSK * NN * DP];           // fp16 h1 @ biaf_W[k]
__device__ __half g_bwTh[CLSK * DP * DP + 64 * DP];    // fp16 [k][j][i], zero pad + slack (zero-init)
__device__ float  g_headW[BB * CLSK * NN];
__device__ float  g_tailW[BB * CLSK * NN];
__device__ float  g_sbias[CLSK * NPOS];

// ---------------- helpers ----------------
__device__ __forceinline__ void mma16(float c[4], const unsigned a[4], const unsigned b[2]) {
    asm volatile("mma.sync.aligned.m16n8k16.row.col.f32.f16.f16.f32 "
                 "{%0,%1,%2,%3}, {%4,%5,%6,%7}, {%8,%9}, {%0,%1,%2,%3};"
                 : "+f"(c[0]), "+f"(c[1]), "+f"(c[2]), "+f"(c[3])
                 : "r"(a[0]), "r"(a[1]), "r"(a[2]), "r"(a[3]), "r"(b[0]), "r"(b[1]));
}
__device__ __forceinline__ void ldsm4(unsigned& r0, unsigned& r1, unsigned& r2, unsigned& r3,
                                      uint32_t a) {
    asm volatile("ldmatrix.sync.aligned.m8n8.x4.shared.b16 {%0,%1,%2,%3}, [%4];"
                 : "=r"(r0), "=r"(r1), "=r"(r2), "=r"(r3) : "r"(a));
}
__device__ __forceinline__ void cp16(void* dst, const void* src) {
    unsigned d = (unsigned)__cvta_generic_to_shared(dst);
    asm volatile("cp.async.ca.shared.global [%0], [%1], 16;" :: "r"(d), "l"(src));
}
#define CP_COMMIT() asm volatile("cp.async.commit_group;")
#define CP_WAIT(n)  asm volatile("cp.async.wait_group %0;" :: "n"(n))
__device__ __forceinline__ uint32_t s2u(const void* p) {
    uint32_t a;
    asm("{ .reg .u64 t; cvta.to.shared.u64 t, %1; cvt.u32.u64 %0, t; }" : "=r"(a) : "l"(p));
    return a;
}

// ---------------- prep: fused transpose(biaf_W) + pad/ones + size-bias ----------------
#define TR_BLOCKS (9 * 9 * CLSK)
__global__ void prep_kernel(const float* __restrict__ bw, const float* __restrict__ W,
                            const float* __restrict__ se)
{
    int bi = blockIdx.x;
    int tid = threadIdx.x;

    if (bi < TR_BLOCKS) {
        __shared__ float tile[32][33];
        int k = bi / 81;
        int rem = bi % 81;
        int i0 = (rem / 9) * 32, j0 = (rem % 9) * 32;
        int tx = tid & 31, ty = tid >> 5;
        #pragma unroll
        for (int r = 0; r < 4; r++) {
            int i = i0 + ty + r * 8, j = j0 + tx;
            tile[ty + r * 8][tx] = (i < DD && j < DD) ? bw[(k * DD + i) * DD + j] : 0.0f;
        }
        __syncthreads();
        #pragma unroll
        for (int r = 0; r < 4; r++) {
            int j = j0 + ty + r * 8, i = i0 + tx;
            if (j < DP && i < DP)
                g_bwTh[(k * DP + j) * DP + i] = __float2half_rn(tile[tx][ty + r * 8]);
        }
        return;
    }

    if (bi < TR_BLOCKS + 4) {
        int bm = (bi - TR_BLOCKS) * 256 + tid;
        if (bm < BB * NN) {
            g_h1h[bm * DP + 256] = __float2half_rn(1.0f);
            g_t1h[bm * DP + 256] = __float2half_rn(1.0f);
            #pragma unroll
            for (int j = 257; j < DP; j++) {
                g_h1h[bm * DP + j] = __float2half_rn(0.0f);
                g_t1h[bm * DP + j] = __float2half_rn(0.0f);
            }
            g_head1[bm * DD + 256] = 1.0f;
            g_tail1[bm * DD + 256] = 1.0f;
        }
        return;
    }

    for (int idx = tid; idx < CLSK * NPOS; idx += 256) {
        int k = idx / NPOS, p = idx % NPOS;
        float s = 0.0f;
        #pragma unroll
        for (int d = 0; d < SDIM; d++) s += se[p * SDIM + d] * W[k * HSZ + 2 * DD + d];
        g_sbias[idx] = s;
    }
}

// ---------------- stage 1: projections via fp16 mma16 + ldmatrix. 64x64 tiles, 128 thr ----------------
__global__ void proj_kernel(const float* __restrict__ x, const float* __restrict__ y,
                            const float* __restrict__ w1, const float* __restrict__ b1,
                            const float* __restrict__ w2, const float* __restrict__ b2,
                            const float* __restrict__ hw, const float* __restrict__ hb,
                            const float* __restrict__ tw, const float* __restrict__ tb)
{
    __shared__ unsigned As[64][20];
    __shared__ unsigned Bs[64][20];

    const int v = blockIdx.z;
    const float* X = (v == 1) ? y : x;
    const float* Wm; const float* bias;
    if (v == 0)      { Wm = w1; bias = b1; }
    else if (v == 1) { Wm = w2; bias = b2; }
    else if (v == 2) { Wm = hw; bias = hb; }
    else             { Wm = tw; bias = tb; }

    const int m0 = blockIdx.x * 64;
    const int n0 = blockIdx.y * 64;
    const int tid = threadIdx.x;
    const int w = tid >> 5, lane = tid & 31, g = lane >> 2, tig = lane & 3;
    const int wm = (w >> 1) * 32, wn = (w & 1) * 32;
    const int lrow = lane & 7, sel = lane >> 3;
    const int aMoff = (sel & 1) * 8, aKw = (sel >> 1) * 4;
    const int bNoff = (sel >> 1) * 8, bKw = (sel & 1) * 4;
    const uint32_t aBase = s2u(&As[0][0]);
    const uint32_t bBase = s2u(&Bs[0][0]);

    float acc[2][4][4] = {};

    for (int k0 = 0; k0 < HIDD; k0 += 32) {
        int r = tid >> 1, hs = tid & 1;
        const float* xs = &X[(m0 + r) * HIDD + k0 + hs * 16];
        const float* ws = &Wm[(n0 + r) * HIDD + k0 + hs * 16];
        unsigned* da = &As[r][hs * 8];
        unsigned* db = &Bs[r][hs * 8];
        #pragma unroll
        for (int e = 0; e < 4; e++) {
            float4 xv = *(const float4*)&xs[e * 4];
            float4 wv = *(const float4*)&ws[e * 4];
            __half2 x01 = __floats2half2_rn(xv.x, xv.y);
            __half2 x23 = __floats2half2_rn(xv.z, xv.w);
            __half2 w01 = __floats2half2_rn(wv.x, wv.y);
            __half2 w23 = __floats2half2_rn(wv.z, wv.w);
            da[e * 2]     = *(unsigned*)&x01;
            da[e * 2 + 1] = *(unsigned*)&x23;
            db[e * 2]     = *(unsigned*)&w01;
            db[e * 2 + 1] = *(unsigned*)&w23;
        }
        __syncthreads();
        #pragma unroll
        for (int kk = 0; kk < 2; kk++) {
            unsigned a[2][4], b[4][2];
            #pragma unroll
            for (int i = 0; i < 2; i++)
                ldsm4(a[i][0], a[i][1], a[i][2], a[i][3],
                      aBase + (((wm + i * 16 + aMoff + lrow) * 20) + kk * 8 + aKw) * 4);
            #pragma unroll
            for (int jp = 0; jp < 2; jp++)
                ldsm4(b[2 * jp][0], b[2 * jp][1], b[2 * jp + 1][0], b[2 * jp + 1][1],
                      bBase + (((wn + jp * 16 + bNoff + lrow) * 20) + kk * 8 + bKw) * 4);
            #pragma unroll
            for (int i = 0; i < 2; i++)
                #pragma unroll
                for (int j = 0; j < 4; j++) mma16(acc[i][j], a[i], b[j]);
        }
        __syncthreads();
    }

    #pragma unroll
    for (int i = 0; i < 2; i++) {
        #pragma unroll
        for (int rh = 0; rh < 2; rh++) {
            int m = m0 + wm + i * 16 + g + rh * 8;
            #pragma unroll
            for (int j = 0; j < 4; j++) {
                #pragma unroll
                for (int cb = 0; cb < 2; cb++) {
                    int c = n0 + wn + j * 8 + tig * 2 + cb;
                    float vv = acc[i][j][rh * 2 + cb] + bias[c];
                    if (v < 2) {
                        vv = 0.5f * vv * (1.0f + erff(vv * 0.70710678118654752f));
                        __half* dst = (v == 0) ? g_h1h : g_t1h;
                        dst[m * DP + c] = __float2half_rn(vv);
                    } else {
                        vv = (vv > 0.0f) ? vv : 0.01f * vv;
                        float* dst = (v == 2) ? g_head1 : g_tail1;
                        dst[m * DD + c] = vv;
                    }
                }
            }
        }
    }
}

// ---------------- stage 3: rank-1 bias precomputes (warp per row, 2 passes of 7 classes) ----------------
__global__ void hw_kernel(const float* __restrict__ W)
{
    int warp_id = (blockIdx.x * blockDim.x + threadIdx.x) >> 5;
    int lane = threadIdx.x & 31;
    if (warp_id >= 2 * BB * NN) return;
    int which = (warp_id >= BB * NN) ? 1 : 0;
    int bm = warp_id - which * BB * NN;
    const float* hr = (which ? g_tail1 : g_head1) + bm * DD;

    float h[9];
    #pragma unroll
    for (int s = 0; s < 9; s++) {
        int i = lane + 32 * s;
        h[s] = (i < DD) ? hr[i] : 0.0f;
    }

    const float* Wb = W + which * DD;
    float* dst = which ? g_tailW : g_headW;
    int b = bm / NN, m = bm % NN;

    #pragma unroll
    for (int half = 0; half < 2; half++) {
        float acc[7];
        #pragma unroll
        for (int k = 0; k < 7; k++) acc[k] = 0.0f;
        #pragma unroll
        for (int sg = 0; sg < 9; sg++) {
            int i = lane + 32 * sg;
            if (i < DD) {
                float hv = h[sg];
                #pragma unroll
                for (int k = 0; k < 7; k++)
                    acc[k] += hv * __ldg(&Wb[(half * 7 + k) * HSZ + i]);
            }
        }
        #pragma unroll
        for (int k = 0; k < 7; k++) {
            #pragma unroll
            for (int o = 16; o; o >>= 1) acc[k] += __shfl_xor_sync(0xffffffffu, acc[k], o);
        }
        if (lane == 0) {
            #pragma unroll
            for (int k = 0; k < 7; k++)
                dst[(b * CLSK + half * 7 + k) * NN + m] = acc[k];
        }
    }
}

// ---------------- stage 4: u = h1 @ bwT^T (fp16, ldmatrix). block 128x64, 4 warps of 64x32 ----------------
__global__ void __launch_bounds__(128) u_kernel()
{
    __shared__ unsigned As[3][128][20];
    __shared__ unsigned Bs[3][64][20];

    const int bk = blockIdx.z;
    const int b = bk / CLSK, kcls = bk % CLSK;
    const int m0 = blockIdx.x * 128;
    const int n0 = blockIdx.y * 64;
    const __half* A  = g_h1h + b * NN * DP;
    const __half* Bm = g_bwTh + kcls * DP * DP;
    const int tid = threadIdx.x;
    const int w = tid >> 5, lane = tid & 31, g = lane >> 2, tig = lane & 3;
    const int wm = (w >> 1) * 64, wn = (w & 1) * 32;
    const int lrow = lane & 7, sel = lane >> 3;
    const int aMoff = (sel & 1) * 8, aKw = (sel >> 1) * 4;
    const int bNoff = (sel >> 1) * 8, bKw = (sel & 1) * 4;

    float acc[4][4][4] = {};

    #define U_STAGE(buf, k0)                                                     \
        do { _Pragma("unroll")                                                   \
        for (int h = 0; h < 4; h++) {                                            \
            int f = tid + h * 128;                                               \
            int r = f >> 2, q = f & 3;                                           \
            cp16(&As[buf][r][q * 4], &A[(m0 + r) * DP + (k0) + q * 8]);          \
        } _Pragma("unroll")                                                      \
        for (int h = 0; h < 2; h++) {                                            \
            int f = tid + h * 128;                                               \
            int r = f >> 2, q = f & 3;                                           \
            cp16(&Bs[buf][r][q * 4], &Bm[(n0 + r) * DP + (k0) + q * 8]);         \
        } } while (0)

    U_STAGE(0, 0);  CP_COMMIT();
    U_STAGE(1, 32); CP_COMMIT();

    const int NT = DP / 32;  // 9
    int cur = 0;
    for (int kt = 0; kt < NT; kt++) {
        if (kt + 1 < NT) CP_WAIT(1); else CP_WAIT(0);
        __syncthreads();
        if (kt + 2 < NT) {
            int nxt = cur + 2; if (nxt >= 3) nxt -= 3;
            U_STAGE(nxt, (kt + 2) * 32);
            CP_COMMIT();
        }
        uint32_t aBase = s2u(&As[cur][0][0]);
        uint32_t bBase = s2u(&Bs[cur][0][0]);
        #pragma unroll
        for (int kk = 0; kk < 2; kk++) {
            unsigned a[4][4], b2[4][2];
            #pragma unroll
            for (int i = 0; i < 4; i++)
                ldsm4(a[i][0], a[i][1], a[i][2], a[i][3],
                      aBase + (((wm + i * 16 + aMoff + lrow) * 20) + kk * 8 + aKw) * 4);
            #pragma unroll
            for (int jp = 0; jp < 2; jp++)
                ldsm4(b2[2 * jp][0], b2[2 * jp][1], b2[2 * jp + 1][0], b2[2 * jp + 1][1],
                      bBase + (((wn + jp * 16 + bNoff + lrow) * 20) + kk * 8 + bKw) * 4);
            #pragma unroll
            for (int i = 0; i < 4; i++)
                #pragma unroll
                for (int j = 0; j < 4; j++) mma16(acc[i][j], a[i], b2[j]);
        }
        if (++cur == 3) cur = 0;
    }

    __half* U = g_uh + bk * NN * DP;
    #pragma unroll
    for (int i = 0; i < 4; i++) {
        #pragma unroll
        for (int rh = 0; rh < 2; rh++) {
            int m = m0 + wm + i * 16 + g + rh * 8;
            #pragma unroll
            for (int j = 0; j < 4; j++) {
                int c = n0 + wn + j * 8 + tig * 2;
                if (c < DP) {
                    __half2 hv = __floats2half2_rn(acc[i][j][rh * 2 + 0],
                                                   acc[i][j][rh * 2 + 1]);
                    *(__half2*)&U[m * DP + c] = hv;
                }
            }
        }
    }
}

// ---------------- stage 5: out = u @ t1^T + biases (fp16, ldmatrix). 128x128, 4 warps of 64x64 ----------------
#define O_TILE_U (128 * 20)
__global__ void __launch_bounds__(128) out_kernel(float* __restrict__ out)
{
    extern __shared__ unsigned dyn[];
    unsigned (*As)[128][20] = (unsigned(*)[128][20])dyn;
    unsigned (*Bs)[128][20] = (unsigned(*)[128][20])(dyn + 3 * O_TILE_U);
    __shared__ float sHW[128], sTW[128], sSB[NPOS];

    const int bk = blockIdx.z;
    const int b = bk / CLSK, kcls = bk % CLSK;
    const int m0 = blockIdx.x * 128;
    const int n0 = blockIdx.y * 128;
    const __half* A  = g_uh + bk * NN * DP;
    const __half* Bt = g_t1h + b * NN * DP;
    const int tid = threadIdx.x;
    const int w = tid >> 5, lane = tid & 31, g = lane >> 2, tig = lane & 3;
    const int wm = (w >> 1) * 64, wn = (w & 1) * 64;
    const int lrow = lane & 7, sel = lane >> 3;
    const int aMoff = (sel & 1) * 8, aKw = (sel >> 1) * 4;
    const int bNoff = (sel >> 1) * 8, bKw = (sel & 1) * 4;

    if (tid < 128) {
        sHW[tid] = g_headW[bk * NN + m0 + tid];
        sTW[tid] = g_tailW[bk * NN + n0 + tid];
    }
    if (tid < NPOS) sSB[tid] = g_sbias[kcls * NPOS + tid];

    float acc[4][8][4] = {};

    #define O_STAGE(buf, k0)                                                     \
        do { _Pragma("unroll")                                                   \
        for (int h = 0; h < 4; h++) {                                            \
            int f = tid + h * 128;                                               \
            int r = f >> 2, q = f & 3;                                           \
            cp16(&As[buf][r][q * 4], &A[(m0 + r) * DP + (k0) + q * 8]);          \
            cp16(&Bs[buf][r][q * 4], &Bt[(n0 + r) * DP + (k0) + q * 8]);         \
        } } while (0)

    O_STAGE(0, 0);  CP_COMMIT();
    O_STAGE(1, 32); CP_COMMIT();

    const int NT = DP / 32;  // 9
    int cur = 0;
    for (int kt = 0; kt < NT; kt++) {
        if (kt + 1 < NT) CP_WAIT(1); else CP_WAIT(0);
        __syncthreads();
        if (kt + 2 < NT) {
            int nxt = cur + 2; if (nxt >= 3) nxt -= 3;
            O_STAGE(nxt, (kt + 2) * 32);
            CP_COMMIT();
        }
        uint32_t aBase = s2u(&As[cur][0][0]);
        uint32_t bBase = s2u(&Bs[cur][0][0]);
        #pragma unroll
        for (int kk = 0; kk < 2; kk++) {
            unsigned a[4][4], b2[8][2];
            #pragma unroll
            for (int i = 0; i < 4; i++)
                ldsm4(a[i][0], a[i][1], a[i][2], a[i][3],
                      aBase + (((wm + i * 16 + aMoff + lrow) * 20) + kk * 8 + aKw) * 4);
            #pragma unroll
            for (int jp = 0; jp < 4; jp++)
                ldsm4(b2[2 * jp][0], b2[2 * jp][1], b2[2 * jp + 1][0], b2[2 * jp + 1][1],
                      bBase + (((wn + jp * 16 + bNoff + lrow) * 20) + kk * 8 + bKw) * 4);
            #pragma unroll
            for (int i = 0; i < 4; i++)
                #pragma unroll
                for (int j = 0; j < 8; j++) mma16(acc[i][j], a[i], b2[j]);
        }
        if (++cur == 3) cur = 0;
    }

    #pragma unroll
    for (int i = 0; i < 4; i++) {
        #pragma unroll
        for (int rh = 0; rh < 2; rh++) {
            int ml = wm + i * 16 + g + rh * 8;
            int m = m0 + ml;
            float hv = sHW[ml];
            #pragma unroll
            for (int j = 0; j < 8; j++) {
                int cl = wn + j * 8 + tig * 2;
                int n = n0 + cl;
                int d0 = n - m;     d0 = (d0 < -15) ? -15 : (d0 > 14 ? 14 : d0);
                int d1 = n + 1 - m; d1 = (d1 < -15) ? -15 : (d1 > 14 ? 14 : d1);
                float2 vv;
                vv.x = acc[i][j][rh * 2 + 0] + hv + sTW[cl]     + sSB[d0 + 15];
                vv.y = acc[i][j][rh * 2 + 1] + hv + sTW[cl + 1] + sSB[d1 + 15];
                *(float2*)&out[(bk * NN + m) * NN + n] = vv;
            }
        }
    }
}

// ---------------- launch: fork/join multi-stream (graph-capturable) ----------------
extern "C" void kernel_launch(void* const* d_in, const int* in_sizes, int n_in,
                              void* d_out, int out_size)
{
    const float* x   = (const float*)d_in[0];
    const float* y   = (const float*)d_in[1];
    // d_in[2] = z : dead input
    const float* w1  = (const float*)d_in[3];
    const float* b1  = (const float*)d_in[4];
    const float* w2  = (const float*)d_in[5];
    const float* b2  = (const float*)d_in[6];
    const float* hw  = (const float*)d_in[7];
    const float* hb  = (const float*)d_in[8];
    const float* tw  = (const float*)d_in[9];
    const float* tb  = (const float*)d_in[10];
    const float* bw  = (const float*)d_in[11];
    const float* W   = (const float*)d_in[12];
    const float* se  = (const float*)d_in[13];
    float* out = (float*)d_out;

    const int OUT_SMEM = 3 * 2 * O_TILE_U * 4;   // 61440 bytes

    static int init_done = 0;
    static cudaStream_t s2;
    static cudaEvent_t eFork, ePrep, eProj, eHw;
    if (!init_done) {
        cudaFuncSetAttribute(out_kernel, cudaFuncAttributeMaxDynamicSharedMemorySize, OUT_SMEM);
        cudaStreamCreateWithFlags(&s2, cudaStreamNonBlocking);
        cudaEventCreateWithFlags(&eFork, cudaEventDisableTiming);
        cudaEventCreateWithFlags(&ePrep, cudaEventDisableTiming);
        cudaEventCreateWithFlags(&eProj, cudaEventDisableTiming);
        cudaEventCreateWithFlags(&eHw,   cudaEventDisableTiming);
        init_done = 1;
    }

    // fork: s2 joins the capture via event dependency
    cudaEventRecord(eFork, 0);
    cudaStreamWaitEvent(s2, eFork, 0);

    // phase 1 (parallel): prep on s2, proj on main
    prep_kernel<<<TR_BLOCKS + 5, 256, 0, s2>>>(bw, W, se);
    proj_kernel<<<dim3(16, 4, 4), 128>>>(x, y, w1, b1, w2, b2, hw, hb, tw, tb);

    // join phase 1
    cudaEventRecord(ePrep, s2);
    cudaEventRecord(eProj, 0);
    cudaStreamWaitEvent(0, ePrep, 0);   // main (u) needs prep (bwT, pad)
    cudaStreamWaitEvent(s2, eProj, 0);  // s2 (hw) needs proj (head1/tail1)

    // phase 2 (parallel): u on main, hw on s2
    u_kernel<<<dim3(4, 5, BB * CLSK), 128>>>();
    hw_kernel<<<256, 256, 0, s2>>>(W);

    // join phase 2: out needs u (main-ordered) + hw
    cudaEventRecord(eHw, s2);
    cudaStreamWaitEvent(0, eHw, 0);

    out_kernel<<<dim3(4, 4, BB * CLSK), 128, OUT_SMEM>>>(out);
}

// round 13
// speedup vs baseline: 1.8111x; 1.0388x over previous
#include <cuda_runtime.h>
#include <cuda_fp16.h>
#include <math.h>
#include <stdint.h>

// ---------------- problem constants ----------------
#define BB   2
#define NN   512
#define HIDD 768
#define BIAF 256
#define DD   257      // BIAF + 1
#define DP   288      // DD padded to 9*32 (fp16 K-tiles of 32) — zero pad
#define CLSK 14
#define HSZ  539      // 2*(BIAF+1) + 25
#define NPOS 30
#define SDIM 25

// ---------------- device scratch ----------------
__device__ __half g_h1h[BB * NN * DP];                 // fp16 gelu(x@mlp1)+1, zero pad
__device__ __half g_t1h[BB * NN * DP];
__device__ float  g_head1[BB * NN * DD];               // full precision (for bias dots)
__device__ float  g_tail1[BB * NN * DD];
__device__ __half g_uh[BB * CLSK * NN * DP];           // fp16 h1 @ biaf_W[k]
__device__ __half g_bwTh[CLSK * DP * DP + 64 * DP];    // fp16 [k][j][i], zero pad + slack (zero-init)
__device__ float  g_headW[BB * CLSK * NN];
__device__ float  g_tailW[BB * CLSK * NN];
__device__ float  g_sbias[CLSK * NPOS];

// ---------------- helpers ----------------
__device__ __forceinline__ void mma16(float c[4], const unsigned a[4], const unsigned b[2]) {
    asm volatile("mma.sync.aligned.m16n8k16.row.col.f32.f16.f16.f32 "
                 "{%0,%1,%2,%3}, {%4,%5,%6,%7}, {%8,%9}, {%0,%1,%2,%3};"
                 : "+f"(c[0]), "+f"(c[1]), "+f"(c[2]), "+f"(c[3])
                 : "r"(a[0]), "r"(a[1]), "r"(a[2]), "r"(a[3]), "r"(b[0]), "r"(b[1]));
}
__device__ __forceinline__ void ldsm4(unsigned& r0, unsigned& r1, unsigned& r2, unsigned& r3,
                                      uint32_t a) {
    asm volatile("ldmatrix.sync.aligned.m8n8.x4.shared.b16 {%0,%1,%2,%3}, [%4];"
                 : "=r"(r0), "=r"(r1), "=r"(r2), "=r"(r3) : "r"(a));
}
__device__ __forceinline__ void cp16(void* dst, const void* src) {
    unsigned d = (unsigned)__cvta_generic_to_shared(dst);
    asm volatile("cp.async.ca.shared.global [%0], [%1], 16;" :: "r"(d), "l"(src));
}
#define CP_COMMIT() asm volatile("cp.async.commit_group;")
#define CP_WAIT(n)  asm volatile("cp.async.wait_group %0;" :: "n"(n))
__device__ __forceinline__ uint32_t s2u(const void* p) {
    uint32_t a;
    asm("{ .reg .u64 t; cvta.to.shared.u64 t, %1; cvt.u32.u64 %0, t; }" : "=r"(a) : "l"(p));
    return a;
}

// ============================================================================
// fused1 = proj (blocks [0,256)) + tr (256+[0,1134)) + pad (next 8) + sb (last)
// 128 threads everywhere.
// ============================================================================
#define F1_PROJ 256
#define F1_TR   (9 * 9 * CLSK)       // 1134
#define F1_PAD  8
#define F1_BLOCKS (F1_PROJ + F1_TR + F1_PAD + 1)

__global__ void __launch_bounds__(128) fused1_kernel(
    const float* __restrict__ x, const float* __restrict__ y,
    const float* __restrict__ w1, const float* __restrict__ b1,
    const float* __restrict__ w2, const float* __restrict__ b2,
    const float* __restrict__ hw, const float* __restrict__ hb,
    const float* __restrict__ tw, const float* __restrict__ tb,
    const float* __restrict__ bw, const float* __restrict__ W,
    const float* __restrict__ se)
{
    const int bi = blockIdx.x;
    const int tid = threadIdx.x;

    if (bi < F1_PROJ) {
        // ---------------- proj: fp16 mma16 + ldmatrix, 64x64 tiles ----------------
        __shared__ unsigned As[64][20];
        __shared__ unsigned Bs[64][20];

        const int v = bi >> 6;
        const int rem = bi & 63;
        const int m0 = (rem >> 2) * 64;
        const int n0 = (rem & 3) * 64;
        const float* X = (v == 1) ? y : x;
        const float* Wm; const float* bias;
        if (v == 0)      { Wm = w1; bias = b1; }
        else if (v == 1) { Wm = w2; bias = b2; }
        else if (v == 2) { Wm = hw; bias = hb; }
        else             { Wm = tw; bias = tb; }

        const int w = tid >> 5, lane = tid & 31, g = lane >> 2, tig = lane & 3;
        const int wm = (w >> 1) * 32, wn = (w & 1) * 32;
        const int lrow = lane & 7, sel = lane >> 3;
        const int aMoff = (sel & 1) * 8, aKw = (sel >> 1) * 4;
        const int bNoff = (sel >> 1) * 8, bKw = (sel & 1) * 4;
        const uint32_t aBase = s2u(&As[0][0]);
        const uint32_t bBase = s2u(&Bs[0][0]);

        float acc[2][4][4] = {};

        for (int k0 = 0; k0 < HIDD; k0 += 32) {
            int r = tid >> 1, hs = tid & 1;
            const float* xs = &X[(m0 + r) * HIDD + k0 + hs * 16];
            const float* ws = &Wm[(n0 + r) * HIDD + k0 + hs * 16];
            unsigned* da = &As[r][hs * 8];
            unsigned* db = &Bs[r][hs * 8];
            #pragma unroll
            for (int e = 0; e < 4; e++) {
                float4 xv = *(const float4*)&xs[e * 4];
                float4 wv = *(const float4*)&ws[e * 4];
                __half2 x01 = __floats2half2_rn(xv.x, xv.y);
                __half2 x23 = __floats2half2_rn(xv.z, xv.w);
                __half2 w01 = __floats2half2_rn(wv.x, wv.y);
                __half2 w23 = __floats2half2_rn(wv.z, wv.w);
                da[e * 2]     = *(unsigned*)&x01;
                da[e * 2 + 1] = *(unsigned*)&x23;
                db[e * 2]     = *(unsigned*)&w01;
                db[e * 2 + 1] = *(unsigned*)&w23;
            }
            __syncthreads();
            #pragma unroll
            for (int kk = 0; kk < 2; kk++) {
                unsigned a[2][4], b[4][2];
                #pragma unroll
                for (int i = 0; i < 2; i++)
                    ldsm4(a[i][0], a[i][1], a[i][2], a[i][3],
                          aBase + (((wm + i * 16 + aMoff + lrow) * 20) + kk * 8 + aKw) * 4);
                #pragma unroll
                for (int jp = 0; jp < 2; jp++)
                    ldsm4(b[2 * jp][0], b[2 * jp][1], b[2 * jp + 1][0], b[2 * jp + 1][1],
                          bBase + (((wn + jp * 16 + bNoff + lrow) * 20) + kk * 8 + bKw) * 4);
                #pragma unroll
                for (int i = 0; i < 2; i++)
                    #pragma unroll
                    for (int j = 0; j < 4; j++) mma16(acc[i][j], a[i], b[j]);
            }
            __syncthreads();
        }

        #pragma unroll
        for (int i = 0; i < 2; i++) {
            #pragma unroll
            for (int rh = 0; rh < 2; rh++) {
                int m = m0 + wm + i * 16 + g + rh * 8;
                #pragma unroll
                for (int j = 0; j < 4; j++) {
                    #pragma unroll
                    for (int cb = 0; cb < 2; cb++) {
                        int c = n0 + wn + j * 8 + tig * 2 + cb;
                        float vv = acc[i][j][rh * 2 + cb] + bias[c];
                        if (v < 2) {
                            vv = 0.5f * vv * (1.0f + erff(vv * 0.70710678118654752f));
                            __half* dst = (v == 0) ? g_h1h : g_t1h;
                            dst[m * DP + c] = __float2half_rn(vv);
                        } else {
                            vv = (vv > 0.0f) ? vv : 0.01f * vv;
                            float* dst = (v == 2) ? g_head1 : g_tail1;
                            dst[m * DD + c] = vv;
                        }
                    }
                }
            }
        }
        return;
    }

    if (bi < F1_PROJ + F1_TR) {
        // ---------------- transpose biaf_W -> g_bwTh ----------------
        __shared__ float tile[32][33];
        int t = bi - F1_PROJ;
        int k = t / 81;
        int rem = t % 81;
        int i0 = (rem / 9) * 32, j0 = (rem % 9) * 32;
        int tx = tid & 31, ty = tid >> 5;   // ty 0..3
        #pragma unroll
        for (int r = 0; r < 8; r++) {
            int i = i0 + ty + r * 4, j = j0 + tx;
            tile[ty + r * 4][tx] = (i < DD && j < DD) ? bw[(k * DD + i) * DD + j] : 0.0f;
        }
        __syncthreads();
        #pragma unroll
        for (int r = 0; r < 8; r++) {
            int j = j0 + ty + r * 4, i = i0 + tx;
            if (j < DP && i < DP)
                g_bwTh[(k * DP + j) * DP + i] = __float2half_rn(tile[tx][ty + r * 4]);
        }
        return;
    }

    if (bi < F1_PROJ + F1_TR + F1_PAD) {
        int bm = (bi - F1_PROJ - F1_TR) * 128 + tid;
        if (bm < BB * NN) {
            g_h1h[bm * DP + 256] = __float2half_rn(1.0f);
            g_t1h[bm * DP + 256] = __float2half_rn(1.0f);
            #pragma unroll
            for (int j = 257; j < DP; j++) {
                g_h1h[bm * DP + j] = __float2half_rn(0.0f);
                g_t1h[bm * DP + j] = __float2half_rn(0.0f);
            }
            g_head1[bm * DD + 256] = 1.0f;
            g_tail1[bm * DD + 256] = 1.0f;
        }
        return;
    }

    // sb
    for (int idx = tid; idx < CLSK * NPOS; idx += 128) {
        int k = idx / NPOS, p = idx % NPOS;
        float s = 0.0f;
        #pragma unroll
        for (int d = 0; d < SDIM; d++) s += se[p * SDIM + d] * W[k * HSZ + 2 * DD + d];
        g_sbias[idx] = s;
    }
}

// ============================================================================
// fused2 = u (blocks [0,560)) + hw (blocks [560, 560+512)). 128 threads.
// ============================================================================
#define F2_U 560
#define F2_HW 512
#define F2_BLOCKS (F2_U + F2_HW)

__global__ void __launch_bounds__(128) fused2_kernel(const float* __restrict__ W)
{
    __shared__ unsigned As[3][128][20];
    __shared__ unsigned Bs[3][64][20];

    const int bi = blockIdx.x;
    const int tid = threadIdx.x;

    if (bi >= F2_U) {
        // ---------------- hw: warp per row, 2 passes of 7 classes ----------------
        int warp_id = (bi - F2_U) * 4 + (tid >> 5);
        int lane = tid & 31;
        if (warp_id >= 2 * BB * NN) return;
        int which = (warp_id >= BB * NN) ? 1 : 0;
        int bm = warp_id - which * BB * NN;
        const float* hr = (which ? g_tail1 : g_head1) + bm * DD;

        float h[9];
        #pragma unroll
        for (int s = 0; s < 9; s++) {
            int i = lane + 32 * s;
            h[s] = (i < DD) ? hr[i] : 0.0f;
        }

        const float* Wb = W + which * DD;
        float* dst = which ? g_tailW : g_headW;
        int b = bm / NN, m = bm % NN;

        #pragma unroll
        for (int half = 0; half < 2; half++) {
            float acc[7];
            #pragma unroll
            for (int k = 0; k < 7; k++) acc[k] = 0.0f;
            #pragma unroll
            for (int sg = 0; sg < 9; sg++) {
                int i = lane + 32 * sg;
                if (i < DD) {
                    float hv = h[sg];
                    #pragma unroll
                    for (int k = 0; k < 7; k++)
                        acc[k] += hv * __ldg(&Wb[(half * 7 + k) * HSZ + i]);
                }
            }
            #pragma unroll
            for (int k = 0; k < 7; k++) {
                #pragma unroll
                for (int o = 16; o; o >>= 1) acc[k] += __shfl_xor_sync(0xffffffffu, acc[k], o);
            }
            if (lane == 0) {
                #pragma unroll
                for (int k = 0; k < 7; k++)
                    dst[(b * CLSK + half * 7 + k) * NN + m] = acc[k];
            }
        }
        return;
    }

    // ---------------- u: fp16 ldmatrix mma, block 128x64, 4 warps of 64x32 ----------------
    const int bk = bi / 20;
    const int rem = bi % 20;
    const int b = bk / CLSK, kcls = bk % CLSK;
    const int m0 = (rem & 3) * 128;
    const int n0 = (rem >> 2) * 64;
    const __half* A  = g_h1h + b * NN * DP;
    const __half* Bm = g_bwTh + kcls * DP * DP;
    const int w = tid >> 5, lane = tid & 31, g = lane >> 2, tig = lane & 3;
    const int wm = (w >> 1) * 64, wn = (w & 1) * 32;
    const int lrow = lane & 7, sel = lane >> 3;
    const int aMoff = (sel & 1) * 8, aKw = (sel >> 1) * 4;
    const int bNoff = (sel >> 1) * 8, bKw = (sel & 1) * 4;

    float acc[4][4][4] = {};

    #define U_STAGE(buf, k0)                                                     \
        do { _Pragma("unroll")                                                   \
        for (int h = 0; h < 4; h++) {                                            \
            int f = tid + h * 128;                                               \
            int r = f >> 2, q = f & 3;                                           \
            cp16(&As[buf][r][q * 4], &A[(m0 + r) * DP + (k0) + q * 8]);          \
        } _Pragma("unroll")                                                      \
        for (int h = 0; h < 2; h++) {                                            \
            int f = tid + h * 128;                                               \
            int r = f >> 2, q = f & 3;                                           \
            cp16(&Bs[buf][r][q * 4], &Bm[(n0 + r) * DP + (k0) + q * 8]);         \
        } } while (0)

    U_STAGE(0, 0);  CP_COMMIT();
    U_STAGE(1, 32); CP_COMMIT();

    const int NT = DP / 32;  // 9
    int cur = 0;
    for (int kt = 0; kt < NT; kt++) {
        if (kt + 1 < NT) CP_WAIT(1); else CP_WAIT(0);
        __syncthreads();
        if (kt + 2 < NT) {
            int nxt = cur + 2; if (nxt >= 3) nxt -= 3;
            U_STAGE(nxt, (kt + 2) * 32);
            CP_COMMIT();
        }
        uint32_t aBase = s2u(&As[cur][0][0]);
        uint32_t bBase = s2u(&Bs[cur][0][0]);
        #pragma unroll
        for (int kk = 0; kk < 2; kk++) {
            unsigned a[4][4], b2[4][2];
            #pragma unroll
            for (int i = 0; i < 4; i++)
                ldsm4(a[i][0], a[i][1], a[i][2], a[i][3],
                      aBase + (((wm + i * 16 + aMoff + lrow) * 20) + kk * 8 + aKw) * 4);
            #pragma unroll
            for (int jp = 0; jp < 2; jp++)
                ldsm4(b2[2 * jp][0], b2[2 * jp][1], b2[2 * jp + 1][0], b2[2 * jp + 1][1],
                      bBase + (((wn + jp * 16 + bNoff + lrow) * 20) + kk * 8 + bKw) * 4);
            #pragma unroll
            for (int i = 0; i < 4; i++)
                #pragma unroll
                for (int j = 0; j < 4; j++) mma16(acc[i][j], a[i], b2[j]);
        }
        if (++cur == 3) cur = 0;
    }

    __half* U = g_uh + bk * NN * DP;
    #pragma unroll
    for (int i = 0; i < 4; i++) {
        #pragma unroll
        for (int rh = 0; rh < 2; rh++) {
            int m = m0 + wm + i * 16 + g + rh * 8;
            #pragma unroll
            for (int j = 0; j < 4; j++) {
                int c = n0 + wn + j * 8 + tig * 2;
                if (c < DP) {
                    __half2 hv = __floats2half2_rn(acc[i][j][rh * 2 + 0],
                                                   acc[i][j][rh * 2 + 1]);
                    *(__half2*)&U[m * DP + c] = hv;
                }
            }
        }
    }
}

// ---------------- stage 5: out = u @ t1^T + biases (fp16, ldmatrix). 128x128, 4 warps of 64x64 ----------------
#define O_TILE_U (128 * 20)
__global__ void __launch_bounds__(128) out_kernel(float* __restrict__ out)
{
    extern __shared__ unsigned dyn[];
    unsigned (*As)[128][20] = (unsigned(*)[128][20])dyn;
    unsigned (*Bs)[128][20] = (unsigned(*)[128][20])(dyn + 3 * O_TILE_U);
    __shared__ float sHW[128], sTW[128], sSB[NPOS];

    const int bk = blockIdx.z;
    const int b = bk / CLSK, kcls = bk % CLSK;
    const int m0 = blockIdx.x * 128;
    const int n0 = blockIdx.y * 128;
    const __half* A  = g_uh + bk * NN * DP;
    const __half* Bt = g_t1h + b * NN * DP;
    const int tid = threadIdx.x;
    const int w = tid >> 5, lane = tid & 31, g = lane >> 2, tig = lane & 3;
    const int wm = (w >> 1) * 64, wn = (w & 1) * 64;
    const int lrow = lane & 7, sel = lane >> 3;
    const int aMoff = (sel & 1) * 8, aKw = (sel >> 1) * 4;
    const int bNoff = (sel >> 1) * 8, bKw = (sel & 1) * 4;

    if (tid < 128) {
        sHW[tid] = g_headW[bk * NN + m0 + tid];
        sTW[tid] = g_tailW[bk * NN + n0 + tid];
    }
    if (tid < NPOS) sSB[tid] = g_sbias[kcls * NPOS + tid];

    float acc[4][8][4] = {};

    #define O_STAGE(buf, k0)                                                     \
        do { _Pragma("unroll")                                                   \
        for (int h = 0; h < 4; h++) {                                            \
            int f = tid + h * 128;                                               \
            int r = f >> 2, q = f & 3;                                           \
            cp16(&As[buf][r][q * 4], &A[(m0 + r) * DP + (k0) + q * 8]);          \
            cp16(&Bs[buf][r][q * 4], &Bt[(n0 + r) * DP + (k0) + q * 8]);         \
        } } while (0)

    O_STAGE(0, 0);  CP_COMMIT();
    O_STAGE(1, 32); CP_COMMIT();

    const int NT = DP / 32;  // 9
    int cur = 0;
    for (int kt = 0; kt < NT; kt++) {
        if (kt + 1 < NT) CP_WAIT(1); else CP_WAIT(0);
        __syncthreads();
        if (kt + 2 < NT) {
            int nxt = cur + 2; if (nxt >= 3) nxt -= 3;
            O_STAGE(nxt, (kt + 2) * 32);
            CP_COMMIT();
        }
        uint32_t aBase = s2u(&As[cur][0][0]);
        uint32_t bBase = s2u(&Bs[cur][0][0]);
        #pragma unroll
        for (int kk = 0; kk < 2; kk++) {
            unsigned a[4][4], b2[8][2];
            #pragma unroll
            for (int i = 0; i < 4; i++)
                ldsm4(a[i][0], a[i][1], a[i][2], a[i][3],
                      aBase + (((wm + i * 16 + aMoff + lrow) * 20) + kk * 8 + aKw) * 4);
            #pragma unroll
            for (int jp = 0; jp < 4; jp++)
                ldsm4(b2[2 * jp][0], b2[2 * jp][1], b2[2 * jp + 1][0], b2[2 * jp + 1][1],
                      bBase + (((wn + jp * 16 + bNoff + lrow) * 20) + kk * 8 + bKw) * 4);
            #pragma unroll
            for (int i = 0; i < 4; i++)
                #pragma unroll
                for (int j = 0; j < 8; j++) mma16(acc[i][j], a[i], b2[j]);
        }
        if (++cur == 3) cur = 0;
    }

    #pragma unroll
    for (int i = 0; i < 4; i++) {
        #pragma unroll
        for (int rh = 0; rh < 2; rh++) {
            int ml = wm + i * 16 + g + rh * 8;
            int m = m0 + ml;
            float hv = sHW[ml];
            #pragma unroll
            for (int j = 0; j < 8; j++) {
                int cl = wn + j * 8 + tig * 2;
                int n = n0 + cl;
                int d0 = n - m;     d0 = (d0 < -15) ? -15 : (d0 > 14 ? 14 : d0);
                int d1 = n + 1 - m; d1 = (d1 < -15) ? -15 : (d1 > 14 ? 14 : d1);
                float2 vv;
                vv.x = acc[i][j][rh * 2 + 0] + hv + sTW[cl]     + sSB[d0 + 15];
                vv.y = acc[i][j][rh * 2 + 1] + hv + sTW[cl + 1] + sSB[d1 + 15];
                *(float2*)&out[(bk * NN + m) * NN + n] = vv;
            }
        }
    }
}

// ---------------- launch: 3 kernels, single stream ----------------
extern "C" void kernel_launch(void* const* d_in, const int* in_sizes, int n_in,
                              void* d_out, int out_size)
{
    const float* x   = (const float*)d_in[0];
    const float* y   = (const float*)d_in[1];
    // d_in[2] = z : dead input
    const float* w1  = (const float*)d_in[3];
    const float* b1  = (const float*)d_in[4];
    const float* w2  = (const float*)d_in[5];
    const float* b2  = (const float*)d_in[6];
    const float* hw  = (const float*)d_in[7];
    const float* hb  = (const float*)d_in[8];
    const float* tw  = (const float*)d_in[9];
    const float* tb  = (const float*)d_in[10];
    const float* bw  = (const float*)d_in[11];
    const float* W   = (const float*)d_in[12];
    const float* se  = (const float*)d_in[13];
    float* out = (float*)d_out;

    const int OUT_SMEM = 3 * 2 * O_TILE_U * 4;   // 61440 bytes
    static int attr_done = 0;
    if (!attr_done) {
        cudaFuncSetAttribute(out_kernel, cudaFuncAttributeMaxDynamicSharedMemorySize, OUT_SMEM);
        attr_done = 1;
    }

    fused1_kernel<<<F1_BLOCKS, 128>>>(x, y, w1, b1, w2, b2, hw, hb, tw, tb, bw, W, se);
    fused2_kernel<<<F2_BLOCKS, 128>>>(W);
    out_kernel<<<dim3(4, 4, BB * CLSK), 128, OUT_SMEM>>>(out);
}

// round 14
// speedup vs baseline: 1.8236x; 1.0069x over previous
#include <cuda_runtime.h>
#include <cuda_fp16.h>
#include <math.h>
#include <stdint.h>

// ---------------- problem constants ----------------
#define BB   2
#define NN   512
#define HIDD 768
#define BIAF 256
#define DD   257      // BIAF + 1
#define DP   288      // DD padded to 9*32 (fp16 K-tiles of 32) — zero pad
#define CLSK 14
#define HSZ  539      // 2*(BIAF+1) + 25
#define NPOS 30
#define SDIM 25

// ---------------- device scratch ----------------
__device__ __half g_h1h[BB * NN * DP];                 // fp16 gelu(x@mlp1)+1, zero pad
__device__ __half g_t1h[BB * NN * DP];
__device__ float  g_head1[BB * NN * DD];               // full precision (for bias dots)
__device__ float  g_tail1[BB * NN * DD];
__device__ __half g_uh[BB * CLSK * NN * DP];           // fp16 h1 @ biaf_W[k]
__device__ __half g_bwTh[CLSK * DP * DP + 64 * DP];    // fp16 [k][j][i], zero pad + slack (zero-init)
__device__ float  g_headW[BB * CLSK * NN];
__device__ float  g_tailW[BB * CLSK * NN];
__device__ float  g_sbias[CLSK * NPOS];

// ---------------- helpers ----------------
__device__ __forceinline__ void mma16(float c[4], const unsigned a[4], const unsigned b[2]) {
    asm volatile("mma.sync.aligned.m16n8k16.row.col.f32.f16.f16.f32 "
                 "{%0,%1,%2,%3}, {%4,%5,%6,%7}, {%8,%9}, {%0,%1,%2,%3};"
                 : "+f"(c[0]), "+f"(c[1]), "+f"(c[2]), "+f"(c[3])
                 : "r"(a[0]), "r"(a[1]), "r"(a[2]), "r"(a[3]), "r"(b[0]), "r"(b[1]));
}
__device__ __forceinline__ void ldsm4(unsigned& r0, unsigned& r1, unsigned& r2, unsigned& r3,
                                      uint32_t a) {
    asm volatile("ldmatrix.sync.aligned.m8n8.x4.shared.b16 {%0,%1,%2,%3}, [%4];"
                 : "=r"(r0), "=r"(r1), "=r"(r2), "=r"(r3) : "r"(a));
}
__device__ __forceinline__ void cp16(void* dst, const void* src) {
    unsigned d = (unsigned)__cvta_generic_to_shared(dst);
    asm volatile("cp.async.ca.shared.global [%0], [%1], 16;" :: "r"(d), "l"(src));
}
#define CP_COMMIT() asm volatile("cp.async.commit_group;")
#define CP_WAIT(n)  asm volatile("cp.async.wait_group %0;" :: "n"(n))
__device__ __forceinline__ uint32_t s2u(const void* p) {
    uint32_t a;
    asm("{ .reg .u64 t; cvta.to.shared.u64 t, %1; cvt.u32.u64 %0, t; }" : "=r"(a) : "l"(p));
    return a;
}

// ============================================================================
// fused1 = proj (blocks [0,256)) + tr (256+[0,1134)) + pad (next 8) + sb (last)
// 128 threads everywhere.
// ============================================================================
#define F1_PROJ 256
#define F1_TR   (9 * 9 * CLSK)       // 1134
#define F1_PAD  8
#define F1_BLOCKS (F1_PROJ + F1_TR + F1_PAD + 1)

__global__ void __launch_bounds__(128) fused1_kernel(
    const float* __restrict__ x, const float* __restrict__ y,
    const float* __restrict__ w1, const float* __restrict__ b1,
    const float* __restrict__ w2, const float* __restrict__ b2,
    const float* __restrict__ hw, const float* __restrict__ hb,
    const float* __restrict__ tw, const float* __restrict__ tb,
    const float* __restrict__ bw, const float* __restrict__ W,
    const float* __restrict__ se)
{
    const int bi = blockIdx.x;
    const int tid = threadIdx.x;

    if (bi < F1_PROJ) {
        // ---------------- proj: fp16 mma16 + ldmatrix, 64x64 tiles ----------------
        // register double-buffer: next k-tile's 8 float4 prefetched before compute
        __shared__ unsigned As[64][20];
        __shared__ unsigned Bs[64][20];

        const int v = bi >> 6;
        const int rem = bi & 63;
        const int m0 = (rem >> 2) * 64;
        const int n0 = (rem & 3) * 64;
        const float* X = (v == 1) ? y : x;
        const float* Wm; const float* bias;
        if (v == 0)      { Wm = w1; bias = b1; }
        else if (v == 1) { Wm = w2; bias = b2; }
        else if (v == 2) { Wm = hw; bias = hb; }
        else             { Wm = tw; bias = tb; }

        const int w = tid >> 5, lane = tid & 31, g = lane >> 2, tig = lane & 3;
        const int wm = (w >> 1) * 32, wn = (w & 1) * 32;
        const int lrow = lane & 7, sel = lane >> 3;
        const int aMoff = (sel & 1) * 8, aKw = (sel >> 1) * 4;
        const int bNoff = (sel >> 1) * 8, bKw = (sel & 1) * 4;
        const uint32_t aBase = s2u(&As[0][0]);
        const uint32_t bBase = s2u(&Bs[0][0]);

        const int r = tid >> 1, hs = tid & 1;
        const float* xrow = &X[(m0 + r) * HIDD + hs * 16];
        const float* wrow = &Wm[(n0 + r) * HIDD + hs * 16];

        float acc[2][4][4] = {};
        float4 pa[4], pb[4];
        #pragma unroll
        for (int e = 0; e < 4; e++) {
            pa[e] = *(const float4*)&xrow[e * 4];
            pb[e] = *(const float4*)&wrow[e * 4];
        }

        for (int k0 = 0; k0 < HIDD; k0 += 32) {
            // convert current tile from regs -> fp16 smem
            unsigned* da = &As[r][hs * 8];
            unsigned* db = &Bs[r][hs * 8];
            #pragma unroll
            for (int e = 0; e < 4; e++) {
                __half2 x01 = __floats2half2_rn(pa[e].x, pa[e].y);
                __half2 x23 = __floats2half2_rn(pa[e].z, pa[e].w);
                __half2 w01 = __floats2half2_rn(pb[e].x, pb[e].y);
                __half2 w23 = __floats2half2_rn(pb[e].z, pb[e].w);
                da[e * 2]     = *(unsigned*)&x01;
                da[e * 2 + 1] = *(unsigned*)&x23;
                db[e * 2]     = *(unsigned*)&w01;
                db[e * 2 + 1] = *(unsigned*)&w23;
            }
            __syncthreads();
            // prefetch next tile (latency overlapped with ldsm+mma below)
            if (k0 + 32 < HIDD) {
                #pragma unroll
                for (int e = 0; e < 4; e++) {
                    pa[e] = *(const float4*)&xrow[k0 + 32 + e * 4];
                    pb[e] = *(const float4*)&wrow[k0 + 32 + e * 4];
                }
            }
            #pragma unroll
            for (int kk = 0; kk < 2; kk++) {
                unsigned a[2][4], b[4][2];
                #pragma unroll
                for (int i = 0; i < 2; i++)
                    ldsm4(a[i][0], a[i][1], a[i][2], a[i][3],
                          aBase + (((wm + i * 16 + aMoff + lrow) * 20) + kk * 8 + aKw) * 4);
                #pragma unroll
                for (int jp = 0; jp < 2; jp++)
                    ldsm4(b[2 * jp][0], b[2 * jp][1], b[2 * jp + 1][0], b[2 * jp + 1][1],
                          bBase + (((wn + jp * 16 + bNoff + lrow) * 20) + kk * 8 + bKw) * 4);
                #pragma unroll
                for (int i = 0; i < 2; i++)
                    #pragma unroll
                    for (int j = 0; j < 4; j++) mma16(acc[i][j], a[i], b[j]);
            }
            __syncthreads();
        }

        #pragma unroll
        for (int i = 0; i < 2; i++) {
            #pragma unroll
            for (int rh = 0; rh < 2; rh++) {
                int m = m0 + wm + i * 16 + g + rh * 8;
                #pragma unroll
                for (int j = 0; j < 4; j++) {
                    #pragma unroll
                    for (int cb = 0; cb < 2; cb++) {
                        int c = n0 + wn + j * 8 + tig * 2 + cb;
                        float vv = acc[i][j][rh * 2 + cb] + bias[c];
                        if (v < 2) {
                            vv = 0.5f * vv * (1.0f + erff(vv * 0.70710678118654752f));
                            __half* dst = (v == 0) ? g_h1h : g_t1h;
                            dst[m * DP + c] = __float2half_rn(vv);
                        } else {
                            vv = (vv > 0.0f) ? vv : 0.01f * vv;
                            float* dst = (v == 2) ? g_head1 : g_tail1;
                            dst[m * DD + c] = vv;
                        }
                    }
                }
            }
        }
        return;
    }

    if (bi < F1_PROJ + F1_TR) {
        // ---------------- transpose biaf_W -> g_bwTh ----------------
        __shared__ float tile[32][33];
        int t = bi - F1_PROJ;
        int k = t / 81;
        int rem = t % 81;
        int i0 = (rem / 9) * 32, j0 = (rem % 9) * 32;
        int tx = tid & 31, ty = tid >> 5;   // ty 0..3
        #pragma unroll
        for (int r = 0; r < 8; r++) {
            int i = i0 + ty + r * 4, j = j0 + tx;
            tile[ty + r * 4][tx] = (i < DD && j < DD) ? bw[(k * DD + i) * DD + j] : 0.0f;
        }
        __syncthreads();
        #pragma unroll
        for (int r = 0; r < 8; r++) {
            int j = j0 + ty + r * 4, i = i0 + tx;
            if (j < DP && i < DP)
                g_bwTh[(k * DP + j) * DP + i] = __float2half_rn(tile[tx][ty + r * 4]);
        }
        return;
    }

    if (bi < F1_PROJ + F1_TR + F1_PAD) {
        int bm = (bi - F1_PROJ - F1_TR) * 128 + tid;
        if (bm < BB * NN) {
            g_h1h[bm * DP + 256] = __float2half_rn(1.0f);
            g_t1h[bm * DP + 256] = __float2half_rn(1.0f);
            #pragma unroll
            for (int j = 257; j < DP; j++) {
                g_h1h[bm * DP + j] = __float2half_rn(0.0f);
                g_t1h[bm * DP + j] = __float2half_rn(0.0f);
            }
            g_head1[bm * DD + 256] = 1.0f;
            g_tail1[bm * DD + 256] = 1.0f;
        }
        return;
    }

    // sb
    for (int idx = tid; idx < CLSK * NPOS; idx += 128) {
        int k = idx / NPOS, p = idx % NPOS;
        float s = 0.0f;
        #pragma unroll
        for (int d = 0; d < SDIM; d++) s += se[p * SDIM + d] * W[k * HSZ + 2 * DD + d];
        g_sbias[idx] = s;
    }
}

// ============================================================================
// fused2 = u (blocks [0,560)) + hw (blocks [560, 560+512)). 128 threads.
// ============================================================================
#define F2_U 560
#define F2_HW 512
#define F2_BLOCKS (F2_U + F2_HW)

__global__ void __launch_bounds__(128) fused2_kernel(const float* __restrict__ W)
{
    __shared__ unsigned As[3][128][20];
    __shared__ unsigned Bs[3][64][20];

    const int bi = blockIdx.x;
    const int tid = threadIdx.x;

    if (bi >= F2_U) {
        // ---------------- hw: warp per row, 2 passes of 7 classes ----------------
        int warp_id = (bi - F2_U) * 4 + (tid >> 5);
        int lane = tid & 31;
        if (warp_id >= 2 * BB * NN) return;
        int which = (warp_id >= BB * NN) ? 1 : 0;
        int bm = warp_id - which * BB * NN;
        const float* hr = (which ? g_tail1 : g_head1) + bm * DD;

        float h[9];
        #pragma unroll
        for (int s = 0; s < 9; s++) {
            int i = lane + 32 * s;
            h[s] = (i < DD) ? hr[i] : 0.0f;
        }

        const float* Wb = W + which * DD;
        float* dst = which ? g_tailW : g_headW;
        int b = bm / NN, m = bm % NN;

        #pragma unroll
        for (int half = 0; half < 2; half++) {
            float acc[7];
            #pragma unroll
            for (int k = 0; k < 7; k++) acc[k] = 0.0f;
            #pragma unroll
            for (int sg = 0; sg < 9; sg++) {
                int i = lane + 32 * sg;
                if (i < DD) {
                    float hv = h[sg];
                    #pragma unroll
                    for (int k = 0; k < 7; k++)
                        acc[k] += hv * __ldg(&Wb[(half * 7 + k) * HSZ + i]);
                }
            }
            #pragma unroll
            for (int k = 0; k < 7; k++) {
                #pragma unroll
                for (int o = 16; o; o >>= 1) acc[k] += __shfl_xor_sync(0xffffffffu, acc[k], o);
            }
            if (lane == 0) {
                #pragma unroll
                for (int k = 0; k < 7; k++)
                    dst[(b * CLSK + half * 7 + k) * NN + m] = acc[k];
            }
        }
        return;
    }

    // ---------------- u: fp16 ldmatrix mma, block 128x64, 4 warps of 64x32 ----------------
    const int bk = bi / 20;
    const int rem = bi % 20;
    const int b = bk / CLSK, kcls = bk % CLSK;
    const int m0 = (rem & 3) * 128;
    const int n0 = (rem >> 2) * 64;
    const __half* A  = g_h1h + b * NN * DP;
    const __half* Bm = g_bwTh + kcls * DP * DP;
    const int w = tid >> 5, lane = tid & 31, g = lane >> 2, tig = lane & 3;
    const int wm = (w >> 1) * 64, wn = (w & 1) * 32;
    const int lrow = lane & 7, sel = lane >> 3;
    const int aMoff = (sel & 1) * 8, aKw = (sel >> 1) * 4;
    const int bNoff = (sel >> 1) * 8, bKw = (sel & 1) * 4;

    float acc[4][4][4] = {};

    #define U_STAGE(buf, k0)                                                     \
        do { _Pragma("unroll")                                                   \
        for (int h = 0; h < 4; h++) {                                            \
            int f = tid + h * 128;                                               \
            int r = f >> 2, q = f & 3;                                           \
            cp16(&As[buf][r][q * 4], &A[(m0 + r) * DP + (k0) + q * 8]);          \
        } _Pragma("unroll")                                                      \
        for (int h = 0; h < 2; h++) {                                            \
            int f = tid + h * 128;                                               \
            int r = f >> 2, q = f & 3;                                           \
            cp16(&Bs[buf][r][q * 4], &Bm[(n0 + r) * DP + (k0) + q * 8]);         \
        } } while (0)

    U_STAGE(0, 0);  CP_COMMIT();
    U_STAGE(1, 32); CP_COMMIT();

    const int NT = DP / 32;  // 9
    int cur = 0;
    for (int kt = 0; kt < NT; kt++) {
        if (kt + 1 < NT) CP_WAIT(1); else CP_WAIT(0);
        __syncthreads();
        if (kt + 2 < NT) {
            int nxt = cur + 2; if (nxt >= 3) nxt -= 3;
            U_STAGE(nxt, (kt + 2) * 32);
            CP_COMMIT();
        }
        uint32_t aBase = s2u(&As[cur][0][0]);
        uint32_t bBase = s2u(&Bs[cur][0][0]);
        #pragma unroll
        for (int kk = 0; kk < 2; kk++) {
            unsigned a[4][4], b2[4][2];
            #pragma unroll
            for (int i = 0; i < 4; i++)
                ldsm4(a[i][0], a[i][1], a[i][2], a[i][3],
                      aBase + (((wm + i * 16 + aMoff + lrow) * 20) + kk * 8 + aKw) * 4);
            #pragma unroll
            for (int jp = 0; jp < 2; jp++)
                ldsm4(b2[2 * jp][0], b2[2 * jp][1], b2[2 * jp + 1][0], b2[2 * jp + 1][1],
                      bBase + (((wn + jp * 16 + bNoff + lrow) * 20) + kk * 8 + bKw) * 4);
            #pragma unroll
            for (int i = 0; i < 4; i++)
                #pragma unroll
                for (int j = 0; j < 4; j++) mma16(acc[i][j], a[i], b2[j]);
        }
        if (++cur == 3) cur = 0;
    }

    __half* U = g_uh + bk * NN * DP;
    #pragma unroll
    for (int i = 0; i < 4; i++) {
        #pragma unroll
        for (int rh = 0; rh < 2; rh++) {
            int m = m0 + wm + i * 16 + g + rh * 8;
            #pragma unroll
            for (int j = 0; j < 4; j++) {
                int c = n0 + wn + j * 8 + tig * 2;
                if (c < DP) {
                    __half2 hv = __floats2half2_rn(acc[i][j][rh * 2 + 0],
                                                   acc[i][j][rh * 2 + 1]);
                    *(__half2*)&U[m * DP + c] = hv;
                }
            }
        }
    }
}

// ---------------- stage 5: out = u @ t1^T + biases (fp16, ldmatrix). 128x128, 4 warps of 64x64 ----------------
#define O_TILE_U (128 * 20)
__global__ void __launch_bounds__(128) out_kernel(float* __restrict__ out)
{
    extern __shared__ unsigned dyn[];
    unsigned (*As)[128][20] = (unsigned(*)[128][20])dyn;
    unsigned (*Bs)[128][20] = (unsigned(*)[128][20])(dyn + 3 * O_TILE_U);
    __shared__ float sHW[128], sTW[128], sSB[NPOS];

    const int bk = blockIdx.z;
    const int b = bk / CLSK, kcls = bk % CLSK;
    const int m0 = blockIdx.x * 128;
    const int n0 = blockIdx.y * 128;
    const __half* A  = g_uh + bk * NN * DP;
    const __half* Bt = g_t1h + b * NN * DP;
    const int tid = threadIdx.x;
    const int w = tid >> 5, lane = tid & 31, g = lane >> 2, tig = lane & 3;
    const int wm = (w >> 1) * 64, wn = (w & 1) * 64;
    const int lrow = lane & 7, sel = lane >> 3;
    const int aMoff = (sel & 1) * 8, aKw = (sel >> 1) * 4;
    const int bNoff = (sel >> 1) * 8, bKw = (sel & 1) * 4;

    if (tid < 128) {
        sHW[tid] = g_headW[bk * NN + m0 + tid];
        sTW[tid] = g_tailW[bk * NN + n0 + tid];
    }
    if (tid < NPOS) sSB[tid] = g_sbias[kcls * NPOS + tid];

    float acc[4][8][4] = {};

    #define O_STAGE(buf, k0)                                                     \
        do { _Pragma("unroll")                                                   \
        for (int h = 0; h < 4; h++) {                                            \
            int f = tid + h * 128;                                               \
            int r = f >> 2, q = f & 3;                                           \
            cp16(&As[buf][r][q * 4], &A[(m0 + r) * DP + (k0) + q * 8]);          \
            cp16(&Bs[buf][r][q * 4], &Bt[(n0 + r) * DP + (k0) + q * 8]);         \
        } } while (0)

    O_STAGE(0, 0);  CP_COMMIT();
    O_STAGE(1, 32); CP_COMMIT();

    const int NT = DP / 32;  // 9
    int cur = 0;
    for (int kt = 0; kt < NT; kt++) {
        if (kt + 1 < NT) CP_WAIT(1); else CP_WAIT(0);
        __syncthreads();
        if (kt + 2 < NT) {
            int nxt = cur + 2; if (nxt >= 3) nxt -= 3;
            O_STAGE(nxt, (kt + 2) * 32);
            CP_COMMIT();
        }
        uint32_t aBase = s2u(&As[cur][0][0]);
        uint32_t bBase = s2u(&Bs[cur][0][0]);
        #pragma unroll
        for (int kk = 0; kk < 2; kk++) {
            unsigned a[4][4], b2[8][2];
            #pragma unroll
            for (int i = 0; i < 4; i++)
                ldsm4(a[i][0], a[i][1], a[i][2], a[i][3],
                      aBase + (((wm + i * 16 + aMoff + lrow) * 20) + kk * 8 + aKw) * 4);
            #pragma unroll
            for (int jp = 0; jp < 4; jp++)
                ldsm4(b2[2 * jp][0], b2[2 * jp][1], b2[2 * jp + 1][0], b2[2 * jp + 1][1],
                      bBase + (((wn + jp * 16 + bNoff + lrow) * 20) + kk * 8 + bKw) * 4);
            #pragma unroll
            for (int i = 0; i < 4; i++)
                #pragma unroll
                for (int j = 0; j < 8; j++) mma16(acc[i][j], a[i], b2[j]);
        }
        if (++cur == 3) cur = 0;
    }

    #pragma unroll
    for (int i = 0; i < 4; i++) {
        #pragma unroll
        for (int rh = 0; rh < 2; rh++) {
            int ml = wm + i * 16 + g + rh * 8;
            int m = m0 + ml;
            float hv = sHW[ml];
            #pragma unroll
            for (int j = 0; j < 8; j++) {
                int cl = wn + j * 8 + tig * 2;
                int n = n0 + cl;
                int d0 = n - m;     d0 = (d0 < -15) ? -15 : (d0 > 14 ? 14 : d0);
                int d1 = n + 1 - m; d1 = (d1 < -15) ? -15 : (d1 > 14 ? 14 : d1);
                float2 vv;
                vv.x = acc[i][j][rh * 2 + 0] + hv + sTW[cl]     + sSB[d0 + 15];
                vv.y = acc[i][j][rh * 2 + 1] + hv + sTW[cl + 1] + sSB[d1 + 15];
                *(float2*)&out[(bk * NN + m) * NN + n] = vv;
            }
        }
    }
}

// ---------------- launch: 3 kernels, single stream ----------------
extern "C" void kernel_launch(void* const* d_in, const int* in_sizes, int n_in,
                              void* d_out, int out_size)
{
    const float* x   = (const float*)d_in[0];
    const float* y   = (const float*)d_in[1];
    // d_in[2] = z : dead input
    const float* w1  = (const float*)d_in[3];
    const float* b1  = (const float*)d_in[4];
    const float* w2  = (const float*)d_in[5];
    const float* b2  = (const float*)d_in[6];
    const float* hw  = (const float*)d_in[7];
    const float* hb  = (const float*)d_in[8];
    const float* tw  = (const float*)d_in[9];
    const float* tb  = (const float*)d_in[10];
    const float* bw  = (const float*)d_in[11];
    const float* W   = (const float*)d_in[12];
    const float* se  = (const float*)d_in[13];
    float* out = (float*)d_out;

    const int OUT_SMEM = 3 * 2 * O_TILE_U * 4;   // 61440 bytes
    static int attr_done = 0;
    if (!attr_done) {
        cudaFuncSetAttribute(out_kernel, cudaFuncAttributeMaxDynamicSharedMemorySize, OUT_SMEM);
        attr_done = 1;
    }

    fused1_kernel<<<F1_BLOCKS, 128>>>(x, y, w1, b1, w2, b2, hw, hb, tw, tb, bw, W, se);
    fused2_kernel<<<F2_BLOCKS, 128>>>(W);
    out_kernel<<<dim3(4, 4, BB * CLSK), 128, OUT_SMEM>>>(out);
}

// round 15
// speedup vs baseline: 2.3631x; 1.2958x over previous
#include <cuda_runtime.h>
#include <cuda_fp16.h>
#include <math.h>
#include <stdint.h>

// ---------------- problem constants ----------------
#define BB   2
#define NN   512
#define HIDD 768
#define BIAF 256
#define DD   257      // BIAF + 1
#define HK   256      // folded biaffine K (ones column handled algebraically)
#define CLSK 14
#define HSZ  539      // 2*(BIAF+1) + 25
#define NPOS 30
#define SDIM 25

// ---------------- device scratch ----------------
__device__ __half g_xh[BB * NN * HIDD];                // fp16 copy of x
__device__ __half g_yh[BB * NN * HIDD];                // fp16 copy of y
__device__ __half g_wh[4 * BIAF * HIDD];               // fp16 w1|w2|hw|tw
__device__ __half g_h1h[BB * NN * HK];                 // fp16 gelu(x@mlp1) (no ones col)
__device__ __half g_t1h[BB * NN * HK];
__device__ float  g_head1[BB * NN * HK];               // fp32 lrelu (no ones col)
__device__ float  g_tail1[BB * NN * HK];
__device__ __half g_uh[BB * CLSK * NN * HK];           // fp16 u[:, 0:256]
__device__ __half g_bwTh[CLSK * HK * HK];              // fp16 biaf_W[k][0:256,0:256]^T [j][i]
__device__ float  g_brow[CLSK * HK];                   // biaf_W[k][256][j], j<256
__device__ float  g_bwlast[CLSK * 260];                // biaf_W[k][i][256], i<257 (pad 260)
__device__ float  g_u256[BB * CLSK * NN];              // u[:,256] = h1 . biaf_W[k][:,256]
__device__ float  g_headW[BB * CLSK * NN];
__device__ float  g_tailW[BB * CLSK * NN];
__device__ float  g_sbias[CLSK * NPOS];

// ---------------- helpers ----------------
__device__ __forceinline__ void mma16(float c[4], const unsigned a[4], const unsigned b[2]) {
    asm volatile("mma.sync.aligned.m16n8k16.row.col.f32.f16.f16.f32 "
                 "{%0,%1,%2,%3}, {%4,%5,%6,%7}, {%8,%9}, {%0,%1,%2,%3};"
                 : "+f"(c[0]), "+f"(c[1]), "+f"(c[2]), "+f"(c[3])
                 : "r"(a[0]), "r"(a[1]), "r"(a[2]), "r"(a[3]), "r"(b[0]), "r"(b[1]));
}
__device__ __forceinline__ void ldsm4(unsigned& r0, unsigned& r1, unsigned& r2, unsigned& r3,
                                      uint32_t a) {
    asm volatile("ldmatrix.sync.aligned.m8n8.x4.shared.b16 {%0,%1,%2,%3}, [%4];"
                 : "=r"(r0), "=r"(r1), "=r"(r2), "=r"(r3) : "r"(a));
}
__device__ __forceinline__ void cp16(void* dst, const void* src) {
    unsigned d = (unsigned)__cvta_generic_to_shared(dst);
    asm volatile("cp.async.ca.shared.global [%0], [%1], 16;" :: "r"(d), "l"(src));
}
#define CP_COMMIT() asm volatile("cp.async.commit_group;")
#define CP_WAIT(n)  asm volatile("cp.async.wait_group %0;" :: "n"(n))
__device__ __forceinline__ uint32_t s2u(const void* p) {
    uint32_t a;
    asm("{ .reg .u64 t; cvta.to.shared.u64 t, %1; cvt.u32.u64 %0, t; }" : "=r"(a) : "l"(p));
    return a;
}

// ============================================================================
// prep = conv (x,y,weights -> fp16) + tr (biaf_W transpose/split) + sb
// ============================================================================
#define CV_X 1536
#define CV_Y 1536
#define CV_W 1536
#define PREP_CONV (CV_X + CV_Y + CV_W)     // 4608
#define PREP_TR   (9 * 9 * CLSK)           // 1134
#define PREP_BLOCKS (PREP_CONV + PREP_TR + 1)

__global__ void __launch_bounds__(128) prep_kernel(
    const float* __restrict__ x, const float* __restrict__ y,
    const float* __restrict__ w1, const float* __restrict__ w2,
    const float* __restrict__ hw, const float* __restrict__ tw,
    const float* __restrict__ bw, const float* __restrict__ W,
    const float* __restrict__ se)
{
    const int bi = blockIdx.x;
    const int tid = threadIdx.x;

    if (bi < PREP_CONV) {
        const float4* src;
        __half* dst;
        int fi;
        if (bi < CV_X) {
            fi = bi * 128 + tid;
            src = (const float4*)x; dst = g_xh;
        } else if (bi < CV_X + CV_Y) {
            fi = (bi - CV_X) * 128 + tid;
            src = (const float4*)y; dst = g_yh;
        } else {
            int widx = (bi - CV_X - CV_Y) * 128 + tid;       // 0..196607 (float4 units)
            int wsel = widx / 49152;
            int off  = widx % 49152;
            const float* ws = (wsel == 0) ? w1 : (wsel == 1) ? w2 : (wsel == 2) ? hw : tw;
            float4 v = ((const float4*)ws)[off];
            __half2* d = (__half2*)&g_wh[(size_t)widx * 4];
            d[0] = __floats2half2_rn(v.x, v.y);
            d[1] = __floats2half2_rn(v.z, v.w);
            return;
        }
        float4 v = src[fi];
        __half2* d = (__half2*)&dst[(size_t)fi * 4];
        d[0] = __floats2half2_rn(v.x, v.y);
        d[1] = __floats2half2_rn(v.z, v.w);
        return;
    }

    if (bi < PREP_CONV + PREP_TR) {
        // transpose biaf_W[k] (257x257) -> g_bwTh (256x256 fp16) + g_brow + g_bwlast
        __shared__ float tile[32][33];
        int t = bi - PREP_CONV;
        int k = t / 81;
        int rem = t % 81;
        int i0 = (rem / 9) * 32, j0 = (rem % 9) * 32;
        int tx = tid & 31, ty = tid >> 5;   // ty 0..3
        #pragma unroll
        for (int r = 0; r < 8; r++) {
            int i = i0 + ty + r * 4, j = j0 + tx;
            tile[ty + r * 4][tx] = (i < DD && j < DD) ? bw[(k * DD + i) * DD + j] : 0.0f;
        }
        __syncthreads();
        #pragma unroll
        for (int r = 0; r < 8; r++) {
            int j = j0 + ty + r * 4, i = i0 + tx;
            float val = tile[tx][ty + r * 4];   // = bw[k][i][j]
            if (j < HK && i < HK)
                g_bwTh[(k * HK + j) * HK + i] = __float2half_rn(val);
            if (j == BIAF && i < DD)
                g_bwlast[k * 260 + i] = val;    // biaf_W[k][i][256]
            if (i == BIAF && j < HK)
                g_brow[k * HK + j] = val;       // biaf_W[k][256][j]
        }
        return;
    }

    // sb
    for (int idx = tid; idx < CLSK * NPOS; idx += 128) {
        int k = idx / NPOS, p = idx % NPOS;
        float s = 0.0f;
        #pragma unroll
        for (int d = 0; d < SDIM; d++) s += se[p * SDIM + d] * W[k * HSZ + 2 * DD + d];
        g_sbias[idx] = s;
    }
}

// ============================================================================
// proj: fp16 cp.async-pipelined GEMM (u-clone). 128x64 tiles, K=768 (24 stages).
// v = blockIdx.z: 0 -> gelu->g_h1h, 1 -> gelu->g_t1h, 2 -> lrelu->g_head1, 3 -> lrelu->g_tail1
// ============================================================================
__global__ void __launch_bounds__(128) proj_kernel(
    const float* __restrict__ b1, const float* __restrict__ b2,
    const float* __restrict__ hb, const float* __restrict__ tb)
{
    __shared__ unsigned As[3][128][20];
    __shared__ unsigned Bs[3][64][20];

    const int v = blockIdx.z;
    const int m0 = blockIdx.x * 128;
    const int n0 = blockIdx.y * 64;
    const __half* A = (v == 1) ? g_yh : g_xh;
    const __half* Bm = g_wh + v * (BIAF * HIDD);
    const float* bias = (v == 0) ? b1 : (v == 1) ? b2 : (v == 2) ? hb : tb;

    const int tid = threadIdx.x;
    const int w = tid >> 5, lane = tid & 31, g = lane >> 2, tig = lane & 3;
    const int wm = (w >> 1) * 64, wn = (w & 1) * 32;
    const int lrow = lane & 7, sel = lane >> 3;
    const int aMoff = (sel & 1) * 8, aKw = (sel >> 1) * 4;
    const int bNoff = (sel >> 1) * 8, bKw = (sel & 1) * 4;

    float acc[4][4][4] = {};

    #define P_STAGE(buf, k0)                                                     \
        do { _Pragma("unroll")                                                   \
        for (int h = 0; h < 4; h++) {                                            \
            int f = tid + h * 128;                                               \
            int r = f >> 2, q = f & 3;                                           \
            cp16(&As[buf][r][q * 4], &A[(m0 + r) * HIDD + (k0) + q * 8]);        \
        } _Pragma("unroll")                                                      \
        for (int h = 0; h < 2; h++) {                                            \
            int f = tid + h * 128;                                               \
            int r = f >> 2, q = f & 3;                                           \
            cp16(&Bs[buf][r][q * 4], &Bm[(n0 + r) * HIDD + (k0) + q * 8]);       \
        } } while (0)

    P_STAGE(0, 0);  CP_COMMIT();
    P_STAGE(1, 32); CP_COMMIT();

    const int NT = HIDD / 32;  // 24
    int cur = 0;
    for (int kt = 0; kt < NT; kt++) {
        if (kt + 1 < NT) CP_WAIT(1); else CP_WAIT(0);
        __syncthreads();
        if (kt + 2 < NT) {
            int nxt = cur + 2; if (nxt >= 3) nxt -= 3;
            P_STAGE(nxt, (kt + 2) * 32);
            CP_COMMIT();
        }
        uint32_t aBase = s2u(&As[cur][0][0]);
        uint32_t bBase = s2u(&Bs[cur][0][0]);
        #pragma unroll
        for (int kk = 0; kk < 2; kk++) {
            unsigned a[4][4], b2[4][2];
            #pragma unroll
            for (int i = 0; i < 4; i++)
                ldsm4(a[i][0], a[i][1], a[i][2], a[i][3],
                      aBase + (((wm + i * 16 + aMoff + lrow) * 20) + kk * 8 + aKw) * 4);
            #pragma unroll
            for (int jp = 0; jp < 2; jp++)
                ldsm4(b2[2 * jp][0], b2[2 * jp][1], b2[2 * jp + 1][0], b2[2 * jp + 1][1],
                      bBase + (((wn + jp * 16 + bNoff + lrow) * 20) + kk * 8 + bKw) * 4);
            #pragma unroll
            for (int i = 0; i < 4; i++)
                #pragma unroll
                for (int j = 0; j < 4; j++) mma16(acc[i][j], a[i], b2[j]);
        }
        if (++cur == 3) cur = 0;
    }

    #pragma unroll
    for (int i = 0; i < 4; i++) {
        #pragma unroll
        for (int rh = 0; rh < 2; rh++) {
            int m = m0 + wm + i * 16 + g + rh * 8;
            #pragma unroll
            for (int j = 0; j < 4; j++) {
                int c = n0 + wn + j * 8 + tig * 2;
                float v0 = acc[i][j][rh * 2 + 0] + __ldg(&bias[c]);
                float v1 = acc[i][j][rh * 2 + 1] + __ldg(&bias[c + 1]);
                if (v < 2) {
                    v0 = 0.5f * v0 * (1.0f + erff(v0 * 0.70710678118654752f));
                    v1 = 0.5f * v1 * (1.0f + erff(v1 * 0.70710678118654752f));
                    __half* dst = (v == 0) ? g_h1h : g_t1h;
                    *(__half2*)&dst[m * HK + c] = __floats2half2_rn(v0, v1);
                } else {
                    v0 = (v0 > 0.0f) ? v0 : 0.01f * v0;
                    v1 = (v1 > 0.0f) ? v1 : 0.01f * v1;
                    float* dst = (v == 2) ? g_head1 : g_tail1;
                    *(float2*)&dst[m * HK + c] = make_float2(v0, v1);
                }
            }
        }
    }
}

// ============================================================================
// fused2 = u (blocks [0,448)) + hw/u256 (blocks [448, 448+768)). 128 threads.
// ============================================================================
#define F2_U 448
#define F2_HW 768
#define F2_BLOCKS (F2_U + F2_HW)

__global__ void __launch_bounds__(128) fused2_kernel(const float* __restrict__ W)
{
    __shared__ unsigned As[3][128][20];
    __shared__ unsigned Bs[3][64][20];
    __shared__ float sBrow[64];

    const int bi = blockIdx.x;
    const int tid = threadIdx.x;

    if (bi >= F2_U) {
        // ---------------- hw/u256: warp per row, 3 domains, 2 passes of 7 classes ----------------
        int warp_id = (bi - F2_U) * 4 + (tid >> 5);
        int lane = tid & 31;
        int which = warp_id >> 10;          // 0: head, 1: tail, 2: u256
        int bm = warp_id & 1023;            // b*NN + m
        int b = bm >> 9, m = bm & 511;

        float h[8];
        if (which < 2) {
            const float* hr = (which ? g_tail1 : g_head1) + bm * HK;
            #pragma unroll
            for (int s = 0; s < 8; s++) h[s] = hr[lane + 32 * s];
        } else {
            const __half* hr = g_h1h + bm * HK;
            #pragma unroll
            for (int s = 0; s < 8; s++) h[s] = __half2float(hr[lane + 32 * s]);
        }

        #pragma unroll
        for (int half = 0; half < 2; half++) {
            float acc[7];
            #pragma unroll
            for (int k = 0; k < 7; k++) acc[k] = 0.0f;
            if (which < 2) {
                const float* Wb = W + which * DD;
                #pragma unroll
                for (int sg = 0; sg < 8; sg++) {
                    int i = lane + 32 * sg;
                    float hv = h[sg];
                    #pragma unroll
                    for (int k = 0; k < 7; k++)
                        acc[k] += hv * __ldg(&Wb[(half * 7 + k) * HSZ + i]);
                }
            } else {
                #pragma unroll
                for (int sg = 0; sg < 8; sg++) {
                    int i = lane + 32 * sg;
                    float hv = h[sg];
                    #pragma unroll
                    for (int k = 0; k < 7; k++)
                        acc[k] += hv * __ldg(&g_bwlast[(half * 7 + k) * 260 + i]);
                }
            }
            #pragma unroll
            for (int k = 0; k < 7; k++) {
                #pragma unroll
                for (int o = 16; o; o >>= 1) acc[k] += __shfl_xor_sync(0xffffffffu, acc[k], o);
            }
            if (lane == 0) {
                #pragma unroll
                for (int k = 0; k < 7; k++) {
                    int kc = half * 7 + k;
                    if (which < 2) {
                        // ones term: + W[kc][which*DD + 256]
                        float val = acc[k] + __ldg(&W[kc * HSZ + which * DD + BIAF]);
                        float* dst = which ? g_tailW : g_headW;
                        dst[(b * CLSK + kc) * NN + m] = val;
                    } else {
                        float val = acc[k] + __ldg(&g_bwlast[kc * 260 + BIAF]);
                        g_u256[(b * CLSK + kc) * NN + m] = val;
                    }
                }
            }
        }
        return;
    }

    // ---------------- u: fp16 ldmatrix mma, block 128x64, K=256 (8 stages) ----------------
    const int bk = bi >> 4;
    const int rem = bi & 15;
    const int b = bk / CLSK, kcls = bk % CLSK;
    const int m0 = (rem & 3) * 128;
    const int n0 = (rem >> 2) * 64;
    const __half* A  = g_h1h + b * NN * HK;
    const __half* Bm = g_bwTh + kcls * HK * HK;
    const int w = tid >> 5, lane = tid & 31, g = lane >> 2, tig = lane & 3;
    const int wm = (w >> 1) * 64, wn = (w & 1) * 32;
    const int lrow = lane & 7, sel = lane >> 3;
    const int aMoff = (sel & 1) * 8, aKw = (sel >> 1) * 4;
    const int bNoff = (sel >> 1) * 8, bKw = (sel & 1) * 4;

    if (tid < 64) sBrow[tid] = g_brow[kcls * HK + n0 + tid];

    float acc[4][4][4] = {};

    #define U_STAGE(buf, k0)                                                     \
        do { _Pragma("unroll")                                                   \
        for (int h = 0; h < 4; h++) {                                            \
            int f = tid + h * 128;                                               \
            int r = f >> 2, q = f & 3;                                           \
            cp16(&As[buf][r][q * 4], &A[(m0 + r) * HK + (k0) + q * 8]);          \
        } _Pragma("unroll")                                                      \
        for (int h = 0; h < 2; h++) {                                            \
            int f = tid + h * 128;                                               \
            int r = f >> 2, q = f & 3;                                           \
            cp16(&Bs[buf][r][q * 4], &Bm[(n0 + r) * HK + (k0) + q * 8]);         \
        } } while (0)

    U_STAGE(0, 0);  CP_COMMIT();
    U_STAGE(1, 32); CP_COMMIT();

    const int NT = HK / 32;  // 8
    int cur = 0;
    for (int kt = 0; kt < NT; kt++) {
        if (kt + 1 < NT) CP_WAIT(1); else CP_WAIT(0);
        __syncthreads();
        if (kt + 2 < NT) {
            int nxt = cur + 2; if (nxt >= 3) nxt -= 3;
            U_STAGE(nxt, (kt + 2) * 32);
            CP_COMMIT();
        }
        uint32_t aBase = s2u(&As[cur][0][0]);
        uint32_t bBase = s2u(&Bs[cur][0][0]);
        #pragma unroll
        for (int kk = 0; kk < 2; kk++) {
            unsigned a[4][4], b2[4][2];
            #pragma unroll
            for (int i = 0; i < 4; i++)
                ldsm4(a[i][0], a[i][1], a[i][2], a[i][3],
                      aBase + (((wm + i * 16 + aMoff + lrow) * 20) + kk * 8 + aKw) * 4);
            #pragma unroll
            for (int jp = 0; jp < 2; jp++)
                ldsm4(b2[2 * jp][0], b2[2 * jp][1], b2[2 * jp + 1][0], b2[2 * jp + 1][1],
                      bBase + (((wn + jp * 16 + bNoff + lrow) * 20) + kk * 8 + bKw) * 4);
            #pragma unroll
            for (int i = 0; i < 4; i++)
                #pragma unroll
                for (int j = 0; j < 4; j++) mma16(acc[i][j], a[i], b2[j]);
        }
        if (++cur == 3) cur = 0;
    }

    __half* U = g_uh + bk * NN * HK;
    #pragma unroll
    for (int i = 0; i < 4; i++) {
        #pragma unroll
        for (int rh = 0; rh < 2; rh++) {
            int m = m0 + wm + i * 16 + g + rh * 8;
            #pragma unroll
            for (int j = 0; j < 4; j++) {
                int cl = wn + j * 8 + tig * 2;
                float v0 = acc[i][j][rh * 2 + 0] + sBrow[cl];
                float v1 = acc[i][j][rh * 2 + 1] + sBrow[cl + 1];
                *(__half2*)&U[m * HK + n0 + cl] = __floats2half2_rn(v0, v1);
            }
        }
    }
}

// ---------------- out = u @ t1^T + biases. 128x128, K=256 (8 stages) ----------------
#define O_TILE_U (128 * 20)
__global__ void __launch_bounds__(128) out_kernel(float* __restrict__ out)
{
    extern __shared__ unsigned dyn[];
    unsigned (*As)[128][20] = (unsigned(*)[128][20])dyn;
    unsigned (*Bs)[128][20] = (unsigned(*)[128][20])(dyn + 3 * O_TILE_U);
    __shared__ float sHW[128], sTW[128], sSB[NPOS];

    const int bk = blockIdx.z;
    const int b = bk / CLSK, kcls = bk % CLSK;
    const int m0 = blockIdx.x * 128;
    const int n0 = blockIdx.y * 128;
    const __half* A  = g_uh + bk * NN * HK;
    const __half* Bt = g_t1h + b * NN * HK;
    const int tid = threadIdx.x;
    const int w = tid >> 5, lane = tid & 31, g = lane >> 2, tig = lane & 3;
    const int wm = (w >> 1) * 64, wn = (w & 1) * 64;
    const int lrow = lane & 7, sel = lane >> 3;
    const int aMoff = (sel & 1) * 8, aKw = (sel >> 1) * 4;
    const int bNoff = (sel >> 1) * 8, bKw = (sel & 1) * 4;

    if (tid < 128) {
        sHW[tid] = g_headW[bk * NN + m0 + tid] + g_u256[bk * NN + m0 + tid];
        sTW[tid] = g_tailW[bk * NN + n0 + tid];
    }
    if (tid < NPOS) sSB[tid] = g_sbias[kcls * NPOS + tid];

    float acc[4][8][4] = {};

    #define O_STAGE(buf, k0)                                                     \
        do { _Pragma("unroll")                                                   \
        for (int h = 0; h < 4; h++) {                                            \
            int f = tid + h * 128;                                               \
            int r = f >> 2, q = f & 3;                                           \
            cp16(&As[buf][r][q * 4], &A[(m0 + r) * HK + (k0) + q * 8]);          \
            cp16(&Bs[buf][r][q * 4], &Bt[(n0 + r) * HK + (k0) + q * 8]);         \
        } } while (0)

    O_STAGE(0, 0);  CP_COMMIT();
    O_STAGE(1, 32); CP_COMMIT();

    const int NT = HK / 32;  // 8
    int cur = 0;
    for (int kt = 0; kt < NT; kt++) {
        if (kt + 1 < NT) CP_WAIT(1); else CP_WAIT(0);
        __syncthreads();
        if (kt + 2 < NT) {
            int nxt = cur + 2; if (nxt >= 3) nxt -= 3;
            O_STAGE(nxt, (kt + 2) * 32);
            CP_COMMIT();
        }
        uint32_t aBase = s2u(&As[cur][0][0]);
        uint32_t bBase = s2u(&Bs[cur][0][0]);
        #pragma unroll
        for (int kk = 0; kk < 2; kk++) {
            unsigned a[4][4], b2[8][2];
            #pragma unroll
            for (int i = 0; i < 4; i++)
                ldsm4(a[i][0], a[i][1], a[i][2], a[i][3],
                      aBase + (((wm + i * 16 + aMoff + lrow) * 20) + kk * 8 + aKw) * 4);
            #pragma unroll
            for (int jp = 0; jp < 4; jp++)
                ldsm4(b2[2 * jp][0], b2[2 * jp][1], b2[2 * jp + 1][0], b2[2 * jp + 1][1],
                      bBase + (((wn + jp * 16 + bNoff + lrow) * 20) + kk * 8 + bKw) * 4);
            #pragma unroll
            for (int i = 0; i < 4; i++)
                #pragma unroll
                for (int j = 0; j < 8; j++) mma16(acc[i][j], a[i], b2[j]);
        }
        if (++cur == 3) cur = 0;
    }

    #pragma unroll
    for (int i = 0; i < 4; i++) {
        #pragma unroll
        for (int rh = 0; rh < 2; rh++) {
            int ml = wm + i * 16 + g + rh * 8;
            int m = m0 + ml;
            float hv = sHW[ml];
            #pragma unroll
            for (int j = 0; j < 8; j++) {
                int cl = wn + j * 8 + tig * 2;
                int n = n0 + cl;
                int d0 = n - m;     d0 = (d0 < -15) ? -15 : (d0 > 14 ? 14 : d0);
                int d1 = n + 1 - m; d1 = (d1 < -15) ? -15 : (d1 > 14 ? 14 : d1);
                float2 vv;
                vv.x = acc[i][j][rh * 2 + 0] + hv + sTW[cl]     + sSB[d0 + 15];
                vv.y = acc[i][j][rh * 2 + 1] + hv + sTW[cl + 1] + sSB[d1 + 15];
                *(float2*)&out[(bk * NN + m) * NN + n] = vv;
            }
        }
    }
}

// ---------------- launch: 4 kernels, single stream ----------------
extern "C" void kernel_launch(void* const* d_in, const int* in_sizes, int n_in,
                              void* d_out, int out_size)
{
    const float* x   = (const float*)d_in[0];
    const float* y   = (const float*)d_in[1];
    // d_in[2] = z : dead input
    const float* w1  = (const float*)d_in[3];
    const float* b1  = (const float*)d_in[4];
    const float* w2  = (const float*)d_in[5];
    const float* b2  = (const float*)d_in[6];
    const float* hw  = (const float*)d_in[7];
    const float* hb  = (const float*)d_in[8];
    const float* tw  = (const float*)d_in[9];
    const float* tb  = (const float*)d_in[10];
    const float* bw  = (const float*)d_in[11];
    const float* W   = (const float*)d_in[12];
    const float* se  = (const float*)d_in[13];
    float* out = (float*)d_out;

    const int OUT_SMEM = 3 * 2 * O_TILE_U * 4;   // 61440 bytes
    static int attr_done = 0;
    if (!attr_done) {
        cudaFuncSetAttribute(out_kernel, cudaFuncAttributeMaxDynamicSharedMemorySize, OUT_SMEM);
        attr_done = 1;
    }

    prep_kernel<<<PREP_BLOCKS, 128>>>(x, y, w1, w2, hw, tw, bw, W, se);
    proj_kernel<<<dim3(8, 4, 4), 128>>>(b1, b2, hb, tb);
    fused2_kernel<<<F2_BLOCKS, 128>>>(W);
    out_kernel<<<dim3(4, 4, BB * CLSK), 128, OUT_SMEM>>>(out);
}

// round 16
// speedup vs baseline: 2.4446x; 1.0345x over previous
#include <cuda_runtime.h>
#include <cuda_fp16.h>
#include <math.h>
#include <stdint.h>

// ---------------- problem constants ----------------
#define BB   2
#define NN   512
#define HIDD 768
#define BIAF 256
#define DD   257      // BIAF + 1
#define HK   256      // folded biaffine K (ones column handled algebraically)
#define CLSK 14
#define HSZ  539      // 2*(BIAF+1) + 25
#define NPOS 30
#define SDIM 25

// ---------------- device scratch ----------------
__device__ __half g_xh[BB * NN * HIDD];                // fp16 copy of x
__device__ __half g_yh[BB * NN * HIDD];                // fp16 copy of y
__device__ __half g_wh[4 * BIAF * HIDD];               // fp16 w1|w2|hw|tw
__device__ __half g_h1h[BB * NN * HK];                 // fp16 gelu(x@mlp1) (no ones col)
__device__ __half g_t1h[BB * NN * HK];
__device__ float  g_head1[BB * NN * HK];               // fp32 lrelu (no ones col)
__device__ float  g_tail1[BB * NN * HK];
__device__ __half g_uh[BB * CLSK * NN * HK];           // fp16 u[:, 0:256]
__device__ __half g_bwTh[CLSK * HK * HK];              // fp16 biaf_W[k][0:256,0:256]^T [j][i]
__device__ float  g_brow[CLSK * HK];                   // biaf_W[k][256][j], j<256
__device__ float  g_bwlast[CLSK * 260];                // biaf_W[k][i][256], i<257 (pad 260)
__device__ float  g_u256[BB * CLSK * NN];              // u[:,256] = h1 . biaf_W[k][:,256]
__device__ float  g_headW[BB * CLSK * NN];
__device__ float  g_tailW[BB * CLSK * NN];
__device__ float  g_sbias[CLSK * NPOS];

// ---------------- helpers ----------------
__device__ __forceinline__ void mma16(float c[4], const unsigned a[4], const unsigned b[2]) {
    asm volatile("mma.sync.aligned.m16n8k16.row.col.f32.f16.f16.f32 "
                 "{%0,%1,%2,%3}, {%4,%5,%6,%7}, {%8,%9}, {%0,%1,%2,%3};"
                 : "+f"(c[0]), "+f"(c[1]), "+f"(c[2]), "+f"(c[3])
                 : "r"(a[0]), "r"(a[1]), "r"(a[2]), "r"(a[3]), "r"(b[0]), "r"(b[1]));
}
__device__ __forceinline__ void ldsm4(unsigned& r0, unsigned& r1, unsigned& r2, unsigned& r3,
                                      uint32_t a) {
    asm volatile("ldmatrix.sync.aligned.m8n8.x4.shared.b16 {%0,%1,%2,%3}, [%4];"
                 : "=r"(r0), "=r"(r1), "=r"(r2), "=r"(r3) : "r"(a));
}
__device__ __forceinline__ void cp16(void* dst, const void* src) {
    unsigned d = (unsigned)__cvta_generic_to_shared(dst);
    asm volatile("cp.async.ca.shared.global [%0], [%1], 16;" :: "r"(d), "l"(src));
}
#define CP_COMMIT() asm volatile("cp.async.commit_group;")
#define CP_WAIT(n)  asm volatile("cp.async.wait_group %0;" :: "n"(n))
__device__ __forceinline__ uint32_t s2u(const void* p) {
    uint32_t a;
    asm("{ .reg .u64 t; cvta.to.shared.u64 t, %1; cvt.u32.u64 %0, t; }" : "=r"(a) : "l"(p));
    return a;
}
__device__ __forceinline__ void grid_dep_sync() {
#if __CUDA_ARCH__ >= 900
    cudaGridDependencySynchronize();
#endif
}

// ============================================================================
// prep = conv (x,y,weights -> fp16) + tr (biaf_W transpose/split) + sb
// ============================================================================
#define CV_X 1536
#define CV_Y 1536
#define CV_W 1536
#define PREP_CONV (CV_X + CV_Y + CV_W)     // 4608
#define PREP_TR   (9 * 9 * CLSK)           // 1134
#define PREP_BLOCKS (PREP_CONV + PREP_TR + 1)

__global__ void __launch_bounds__(128) prep_kernel(
    const float* __restrict__ x, const float* __restrict__ y,
    const float* __restrict__ w1, const float* __restrict__ w2,
    const float* __restrict__ hw, const float* __restrict__ tw,
    const float* __restrict__ bw, const float* __restrict__ W,
    const float* __restrict__ se)
{
    const int bi = blockIdx.x;
    const int tid = threadIdx.x;

    if (bi < PREP_CONV) {
        const float4* src;
        __half* dst;
        int fi;
        if (bi < CV_X) {
            fi = bi * 128 + tid;
            src = (const float4*)x; dst = g_xh;
        } else if (bi < CV_X + CV_Y) {
            fi = (bi - CV_X) * 128 + tid;
            src = (const float4*)y; dst = g_yh;
        } else {
            int widx = (bi - CV_X - CV_Y) * 128 + tid;
            int wsel = widx / 49152;
            int off  = widx % 49152;
            const float* ws = (wsel == 0) ? w1 : (wsel == 1) ? w2 : (wsel == 2) ? hw : tw;
            float4 v = ((const float4*)ws)[off];
            __half2* d = (__half2*)&g_wh[(size_t)widx * 4];
            d[0] = __floats2half2_rn(v.x, v.y);
            d[1] = __floats2half2_rn(v.z, v.w);
            return;
        }
        float4 v = src[fi];
        __half2* d = (__half2*)&dst[(size_t)fi * 4];
        d[0] = __floats2half2_rn(v.x, v.y);
        d[1] = __floats2half2_rn(v.z, v.w);
        return;
    }

    if (bi < PREP_CONV + PREP_TR) {
        __shared__ float tile[32][33];
        int t = bi - PREP_CONV;
        int k = t / 81;
        int rem = t % 81;
        int i0 = (rem / 9) * 32, j0 = (rem % 9) * 32;
        int tx = tid & 31, ty = tid >> 5;
        #pragma unroll
        for (int r = 0; r < 8; r++) {
            int i = i0 + ty + r * 4, j = j0 + tx;
            tile[ty + r * 4][tx] = (i < DD && j < DD) ? bw[(k * DD + i) * DD + j] : 0.0f;
        }
        __syncthreads();
        #pragma unroll
        for (int r = 0; r < 8; r++) {
            int j = j0 + ty + r * 4, i = i0 + tx;
            float val = tile[tx][ty + r * 4];
            if (j < HK && i < HK)
                g_bwTh[(k * HK + j) * HK + i] = __float2half_rn(val);
            if (j == BIAF && i < DD)
                g_bwlast[k * 260 + i] = val;
            if (i == BIAF && j < HK)
                g_brow[k * HK + j] = val;
        }
        return;
    }

    for (int idx = tid; idx < CLSK * NPOS; idx += 128) {
        int k = idx / NPOS, p = idx % NPOS;
        float s = 0.0f;
        #pragma unroll
        for (int d = 0; d < SDIM; d++) s += se[p * SDIM + d] * W[k * HSZ + 2 * DD + d];
        g_sbias[idx] = s;
    }
}

// ============================================================================
// proj: fp16 cp.async-pipelined GEMM. 128x64 tiles, K=768 (24 stages).
// ============================================================================
__global__ void __launch_bounds__(128) proj_kernel(
    const float* __restrict__ b1, const float* __restrict__ b2,
    const float* __restrict__ hb, const float* __restrict__ tb)
{
    __shared__ unsigned As[3][128][20];
    __shared__ unsigned Bs[3][64][20];

    grid_dep_sync();   // PDL: wait on prep before reading g_xh/g_yh/g_wh

    const int v = blockIdx.z;
    const int m0 = blockIdx.x * 128;
    const int n0 = blockIdx.y * 64;
    const __half* A = (v == 1) ? g_yh : g_xh;
    const __half* Bm = g_wh + v * (BIAF * HIDD);
    const float* bias = (v == 0) ? b1 : (v == 1) ? b2 : (v == 2) ? hb : tb;

    const int tid = threadIdx.x;
    const int w = tid >> 5, lane = tid & 31, g = lane >> 2, tig = lane & 3;
    const int wm = (w >> 1) * 64, wn = (w & 1) * 32;
    const int lrow = lane & 7, sel = lane >> 3;
    const int aMoff = (sel & 1) * 8, aKw = (sel >> 1) * 4;
    const int bNoff = (sel >> 1) * 8, bKw = (sel & 1) * 4;

    float acc[4][4][4] = {};

    #define P_STAGE(buf, k0)                                                     \
        do { _Pragma("unroll")                                                   \
        for (int h = 0; h < 4; h++) {                                            \
            int f = tid + h * 128;                                               \
            int r = f >> 2, q = f & 3;                                           \
            cp16(&As[buf][r][q * 4], &A[(m0 + r) * HIDD + (k0) + q * 8]);        \
        } _Pragma("unroll")                                                      \
        for (int h = 0; h < 2; h++) {                                            \
            int f = tid + h * 128;                                               \
            int r = f >> 2, q = f & 3;                                           \
            cp16(&Bs[buf][r][q * 4], &Bm[(n0 + r) * HIDD + (k0) + q * 8]);       \
        } } while (0)

    P_STAGE(0, 0);  CP_COMMIT();
    P_STAGE(1, 32); CP_COMMIT();

    const int NT = HIDD / 32;  // 24
    int cur = 0;
    for (int kt = 0; kt < NT; kt++) {
        if (kt + 1 < NT) CP_WAIT(1); else CP_WAIT(0);
        __syncthreads();
        if (kt + 2 < NT) {
            int nxt = cur + 2; if (nxt >= 3) nxt -= 3;
            P_STAGE(nxt, (kt + 2) * 32);
            CP_COMMIT();
        }
        uint32_t aBase = s2u(&As[cur][0][0]);
        uint32_t bBase = s2u(&Bs[cur][0][0]);
        #pragma unroll
        for (int kk = 0; kk < 2; kk++) {
            unsigned a[4][4], b2[4][2];
            #pragma unroll
            for (int i = 0; i < 4; i++)
                ldsm4(a[i][0], a[i][1], a[i][2], a[i][3],
                      aBase + (((wm + i * 16 + aMoff + lrow) * 20) + kk * 8 + aKw) * 4);
            #pragma unroll
            for (int jp = 0; jp < 2; jp++)
                ldsm4(b2[2 * jp][0], b2[2 * jp][1], b2[2 * jp + 1][0], b2[2 * jp + 1][1],
                      bBase + (((wn + jp * 16 + bNoff + lrow) * 20) + kk * 8 + bKw) * 4);
            #pragma unroll
            for (int i = 0; i < 4; i++)
                #pragma unroll
                for (int j = 0; j < 4; j++) mma16(acc[i][j], a[i], b2[j]);
        }
        if (++cur == 3) cur = 0;
    }

    #pragma unroll
    for (int i = 0; i < 4; i++) {
        #pragma unroll
        for (int rh = 0; rh < 2; rh++) {
            int m = m0 + wm + i * 16 + g + rh * 8;
            #pragma unroll
            for (int j = 0; j < 4; j++) {
                int c = n0 + wn + j * 8 + tig * 2;
                float v0 = acc[i][j][rh * 2 + 0] + __ldg(&bias[c]);
                float v1 = acc[i][j][rh * 2 + 1] + __ldg(&bias[c + 1]);
                if (v < 2) {
                    v0 = 0.5f * v0 * (1.0f + erff(v0 * 0.70710678118654752f));
                    v1 = 0.5f * v1 * (1.0f + erff(v1 * 0.70710678118654752f));
                    __half* dst = (v == 0) ? g_h1h : g_t1h;
                    *(__half2*)&dst[m * HK + c] = __floats2half2_rn(v0, v1);
                } else {
                    v0 = (v0 > 0.0f) ? v0 : 0.01f * v0;
                    v1 = (v1 > 0.0f) ? v1 : 0.01f * v1;
                    float* dst = (v == 2) ? g_head1 : g_tail1;
                    *(float2*)&dst[m * HK + c] = make_float2(v0, v1);
                }
            }
        }
    }
}

// ============================================================================
// fused2 = u (blocks [0,448)) + hw/u256 (blocks [448, 448+768)). 128 threads.
// ============================================================================
#define F2_U 448
#define F2_HW 768
#define F2_BLOCKS (F2_U + F2_HW)

__global__ void __launch_bounds__(128) fused2_kernel(const float* __restrict__ W)
{
    __shared__ unsigned As[3][128][20];
    __shared__ unsigned Bs[3][64][20];
    __shared__ float sBrow[64];

    grid_dep_sync();   // PDL: wait on proj before reading h1/t1/head1/tail1

    const int bi = blockIdx.x;
    const int tid = threadIdx.x;

    if (bi >= F2_U) {
        int warp_id = (bi - F2_U) * 4 + (tid >> 5);
        int lane = tid & 31;
        int which = warp_id >> 10;
        int bm = warp_id & 1023;
        int b = bm >> 9, m = bm & 511;

        float h[8];
        if (which < 2) {
            const float* hr = (which ? g_tail1 : g_head1) + bm * HK;
            #pragma unroll
            for (int s = 0; s < 8; s++) h[s] = hr[lane + 32 * s];
        } else {
            const __half* hr = g_h1h + bm * HK;
            #pragma unroll
            for (int s = 0; s < 8; s++) h[s] = __half2float(hr[lane + 32 * s]);
        }

        #pragma unroll
        for (int half = 0; half < 2; half++) {
            float acc[7];
            #pragma unroll
            for (int k = 0; k < 7; k++) acc[k] = 0.0f;
            if (which < 2) {
                const float* Wb = W + which * DD;
                #pragma unroll
                for (int sg = 0; sg < 8; sg++) {
                    int i = lane + 32 * sg;
                    float hv = h[sg];
                    #pragma unroll
                    for (int k = 0; k < 7; k++)
                        acc[k] += hv * __ldg(&Wb[(half * 7 + k) * HSZ + i]);
                }
            } else {
                #pragma unroll
                for (int sg = 0; sg < 8; sg++) {
                    int i = lane + 32 * sg;
                    float hv = h[sg];
                    #pragma unroll
                    for (int k = 0; k < 7; k++)
                        acc[k] += hv * __ldg(&g_bwlast[(half * 7 + k) * 260 + i]);
                }
            }
            #pragma unroll
            for (int k = 0; k < 7; k++) {
                #pragma unroll
                for (int o = 16; o; o >>= 1) acc[k] += __shfl_xor_sync(0xffffffffu, acc[k], o);
            }
            if (lane == 0) {
                #pragma unroll
                for (int k = 0; k < 7; k++) {
                    int kc = half * 7 + k;
                    if (which < 2) {
                        float val = acc[k] + __ldg(&W[kc * HSZ + which * DD + BIAF]);
                        float* dst = which ? g_tailW : g_headW;
                        dst[(b * CLSK + kc) * NN + m] = val;
                    } else {
                        float val = acc[k] + __ldg(&g_bwlast[kc * 260 + BIAF]);
                        g_u256[(b * CLSK + kc) * NN + m] = val;
                    }
                }
            }
        }
        return;
    }

    const int bk = bi >> 4;
    const int rem = bi & 15;
    const int b = bk / CLSK, kcls = bk % CLSK;
    const int m0 = (rem & 3) * 128;
    const int n0 = (rem >> 2) * 64;
    const __half* A  = g_h1h + b * NN * HK;
    const __half* Bm = g_bwTh + kcls * HK * HK;
    const int w = tid >> 5, lane = tid & 31, g = lane >> 2, tig = lane & 3;
    const int wm = (w >> 1) * 64, wn = (w & 1) * 32;
    const int lrow = lane & 7, sel = lane >> 3;
    const int aMoff = (sel & 1) * 8, aKw = (sel >> 1) * 4;
    const int bNoff = (sel >> 1) * 8, bKw = (sel & 1) * 4;

    if (tid < 64) sBrow[tid] = g_brow[kcls * HK + n0 + tid];

    float acc[4][4][4] = {};

    #define U_STAGE(buf, k0)                                                     \
        do { _Pragma("unroll")                                                   \
        for (int h = 0; h < 4; h++) {                                            \
            int f = tid + h * 128;                                               \
            int r = f >> 2, q = f & 3;                                           \
            cp16(&As[buf][r][q * 4], &A[(m0 + r) * HK + (k0) + q * 8]);          \
        } _Pragma("unroll")                                                      \
        for (int h = 0; h < 2; h++) {                                            \
            int f = tid + h * 128;                                               \
            int r = f >> 2, q = f & 3;                                           \
            cp16(&Bs[buf][r][q * 4], &Bm[(n0 + r) * HK + (k0) + q * 8]);         \
        } } while (0)

    U_STAGE(0, 0);  CP_COMMIT();
    U_STAGE(1, 32); CP_COMMIT();

    const int NT = HK / 32;  // 8
    int cur = 0;
    for (int kt = 0; kt < NT; kt++) {
        if (kt + 1 < NT) CP_WAIT(1); else CP_WAIT(0);
        __syncthreads();
        if (kt + 2 < NT) {
            int nxt = cur + 2; if (nxt >= 3) nxt -= 3;
            U_STAGE(nxt, (kt + 2) * 32);
            CP_COMMIT();
        }
        uint32_t aBase = s2u(&As[cur][0][0]);
        uint32_t bBase = s2u(&Bs[cur][0][0]);
        #pragma unroll
        for (int kk = 0; kk < 2; kk++) {
            unsigned a[4][4], b2[4][2];
            #pragma unroll
            for (int i = 0; i < 4; i++)
                ldsm4(a[i][0], a[i][1], a[i][2], a[i][3],
                      aBase + (((wm + i * 16 + aMoff + lrow) * 20) + kk * 8 + aKw) * 4);
            #pragma unroll
            for (int jp = 0; jp < 2; jp++)
                ldsm4(b2[2 * jp][0], b2[2 * jp][1], b2[2 * jp + 1][0], b2[2 * jp + 1][1],
                      bBase + (((wn + jp * 16 + bNoff + lrow) * 20) + kk * 8 + bKw) * 4);
            #pragma unroll
            for (int i = 0; i < 4; i++)
                #pragma unroll
                for (int j = 0; j < 4; j++) mma16(acc[i][j], a[i], b2[j]);
        }
        if (++cur == 3) cur = 0;
    }

    __half* U = g_uh + bk * NN * HK;
    #pragma unroll
    for (int i = 0; i < 4; i++) {
        #pragma unroll
        for (int rh = 0; rh < 2; rh++) {
            int m = m0 + wm + i * 16 + g + rh * 8;
            #pragma unroll
            for (int j = 0; j < 4; j++) {
                int cl = wn + j * 8 + tig * 2;
                float v0 = acc[i][j][rh * 2 + 0] + sBrow[cl];
                float v1 = acc[i][j][rh * 2 + 1] + sBrow[cl + 1];
                *(__half2*)&U[m * HK + n0 + cl] = __floats2half2_rn(v0, v1);
            }
        }
    }
}

// ---------------- out = u @ t1^T + biases. 128x128, K=256 (8 stages) ----------------
#define O_TILE_U (128 * 20)
__global__ void __launch_bounds__(128) out_kernel(float* __restrict__ out)
{
    extern __shared__ unsigned dyn[];
    unsigned (*As)[128][20] = (unsigned(*)[128][20])dyn;
    unsigned (*Bs)[128][20] = (unsigned(*)[128][20])(dyn + 3 * O_TILE_U);
    __shared__ float sHW[128], sTW[128], sSB[NPOS];

    grid_dep_sync();   // PDL: wait on fused2 before reading g_uh/g_headW/g_u256

    const int bk = blockIdx.z;
    const int b = bk / CLSK, kcls = bk % CLSK;
    const int m0 = blockIdx.x * 128;
    const int n0 = blockIdx.y * 128;
    const __half* A  = g_uh + bk * NN * HK;
    const __half* Bt = g_t1h + b * NN * HK;
    const int tid = threadIdx.x;
    const int w = tid >> 5, lane = tid & 31, g = lane >> 2, tig = lane & 3;
    const int wm = (w >> 1) * 64, wn = (w & 1) * 64;
    const int lrow = lane & 7, sel = lane >> 3;
    const int aMoff = (sel & 1) * 8, aKw = (sel >> 1) * 4;
    const int bNoff = (sel >> 1) * 8, bKw = (sel & 1) * 4;

    if (tid < 128) {
        sHW[tid] = g_headW[bk * NN + m0 + tid] + g_u256[bk * NN + m0 + tid];
        sTW[tid] = g_tailW[bk * NN + n0 + tid];
    }
    if (tid < NPOS) sSB[tid] = g_sbias[kcls * NPOS + tid];

    float acc[4][8][4] = {};

    #define O_STAGE(buf, k0)                                                     \
        do { _Pragma("unroll")                                                   \
        for (int h = 0; h < 4; h++) {                                            \
            int f = tid + h * 128;                                               \
            int r = f >> 2, q = f & 3;                                           \
            cp16(&As[buf][r][q * 4], &A[(m0 + r) * HK + (k0) + q * 8]);          \
            cp16(&Bs[buf][r][q * 4], &Bt[(n0 + r) * HK + (k0) + q * 8]);         \
        } } while (0)

    O_STAGE(0, 0);  CP_COMMIT();
    O_STAGE(1, 32); CP_COMMIT();

    const int NT = HK / 32;  // 8
    int cur = 0;
    for (int kt = 0; kt < NT; kt++) {
        if (kt + 1 < NT) CP_WAIT(1); else CP_WAIT(0);
        __syncthreads();
        if (kt + 2 < NT) {
            int nxt = cur + 2; if (nxt >= 3) nxt -= 3;
            O_STAGE(nxt, (kt + 2) * 32);
            CP_COMMIT();
        }
        uint32_t aBase = s2u(&As[cur][0][0]);
        uint32_t bBase = s2u(&Bs[cur][0][0]);
        #pragma unroll
        for (int kk = 0; kk < 2; kk++) {
            unsigned a[4][4], b2[8][2];
            #pragma unroll
            for (int i = 0; i < 4; i++)
                ldsm4(a[i][0], a[i][1], a[i][2], a[i][3],
                      aBase + (((wm + i * 16 + aMoff + lrow) * 20) + kk * 8 + aKw) * 4);
            #pragma unroll
            for (int jp = 0; jp < 4; jp++)
                ldsm4(b2[2 * jp][0], b2[2 * jp][1], b2[2 * jp + 1][0], b2[2 * jp + 1][1],
                      bBase + (((wn + jp * 16 + bNoff + lrow) * 20) + kk * 8 + bKw) * 4);
            #pragma unroll
            for (int i = 0; i < 4; i++)
                #pragma unroll
                for (int j = 0; j < 8; j++) mma16(acc[i][j], a[i], b2[j]);
        }
        if (++cur == 3) cur = 0;
    }

    #pragma unroll
    for (int i = 0; i < 4; i++) {
        #pragma unroll
        for (int rh = 0; rh < 2; rh++) {
            int ml = wm + i * 16 + g + rh * 8;
            int m = m0 + ml;
            float hv = sHW[ml];
            #pragma unroll
            for (int j = 0; j < 8; j++) {
                int cl = wn + j * 8 + tig * 2;
                int n = n0 + cl;
                int d0 = n - m;     d0 = (d0 < -15) ? -15 : (d0 > 14 ? 14 : d0);
                int d1 = n + 1 - m; d1 = (d1 < -15) ? -15 : (d1 > 14 ? 14 : d1);
                float2 vv;
                vv.x = acc[i][j][rh * 2 + 0] + hv + sTW[cl]     + sSB[d0 + 15];
                vv.y = acc[i][j][rh * 2 + 1] + hv + sTW[cl + 1] + sSB[d1 + 15];
                *(float2*)&out[(bk * NN + m) * NN + n] = vv;
            }
        }
    }
}

// ---------------- launch: 4 kernels with PDL chaining ----------------
extern "C" void kernel_launch(void* const* d_in, const int* in_sizes, int n_in,
                              void* d_out, int out_size)
{
    const float* x   = (const float*)d_in[0];
    const float* y   = (const float*)d_in[1];
    // d_in[2] = z : dead input
    const float* w1  = (const float*)d_in[3];
    const float* b1  = (const float*)d_in[4];
    const float* w2  = (const float*)d_in[5];
    const float* b2  = (const float*)d_in[6];
    const float* hw  = (const float*)d_in[7];
    const float* hb  = (const float*)d_in[8];
    const float* tw  = (const float*)d_in[9];
    const float* tb  = (const float*)d_in[10];
    const float* bw  = (const float*)d_in[11];
    const float* W   = (const float*)d_in[12];
    const float* se  = (const float*)d_in[13];
    float* out = (float*)d_out;

    const int OUT_SMEM = 3 * 2 * O_TILE_U * 4;   // 61440 bytes
    static int attr_done = 0;
    if (!attr_done) {
        cudaFuncSetAttribute(out_kernel, cudaFuncAttributeMaxDynamicSharedMemorySize, OUT_SMEM);
        attr_done = 1;
    }

    prep_kernel<<<PREP_BLOCKS, 128>>>(x, y, w1, w2, hw, tw, bw, W, se);

    cudaLaunchAttribute at[1];
    at[0].id = cudaLaunchAttributeProgrammaticStreamSerialization;
    at[0].val.programmaticStreamSerializationAllowed = 1;

    {
        cudaLaunchConfig_t cfg = {};
        cfg.gridDim = dim3(8, 4, 4);
        cfg.blockDim = dim3(128, 1, 1);
        cfg.attrs = at; cfg.numAttrs = 1;
        cudaLaunchKernelEx(&cfg, proj_kernel, b1, b2, hb, tb);
    }
    {
        cudaLaunchConfig_t cfg = {};
        cfg.gridDim = dim3(F2_BLOCKS, 1, 1);
        cfg.blockDim = dim3(128, 1, 1);
        cfg.attrs = at; cfg.numAttrs = 1;
        cudaLaunchKernelEx(&cfg, fused2_kernel, W);
    }
    {
        cudaLaunchConfig_t cfg = {};
        cfg.gridDim = dim3(4, 4, BB * CLSK);
        cfg.blockDim = dim3(128, 1, 1);
        cfg.dynamicSmemBytes = OUT_SMEM;
        cfg.attrs = at; cfg.numAttrs = 1;
        cudaLaunchKernelEx(&cfg, out_kernel, out);
    }
}

// round 17
// speedup vs baseline: 2.4461x; 1.0006x over previous
#include <cuda_runtime.h>
#include <cuda_fp16.h>
#include <math.h>
#include <stdint.h>

// ---------------- problem constants ----------------
#define BB   2
#define NN   512
#define HIDD 768
#define BIAF 256
#define DD   257      // BIAF + 1
#define HK   256      // folded biaffine K
#define CLSK 14
#define HSZ  539
#define NPOS 30
#define SDIM 25

// ---------------- device scratch ----------------
__device__ __half g_xh[BB * NN * HIDD];
__device__ __half g_yh[BB * NN * HIDD];
__device__ __half g_wh[4 * BIAF * HIDD];
__device__ __half g_h1h[BB * NN * HK];
__device__ __half g_t1h[BB * NN * HK];
__device__ float  g_head1[BB * NN * HK];
__device__ float  g_tail1[BB * NN * HK];
__device__ __half g_uh[BB * CLSK * NN * HK];
__device__ __half g_bwTh[CLSK * HK * HK];
__device__ float  g_brow[CLSK * HK];
__device__ float  g_bwlast[CLSK * 260];
__device__ float  g_u256[BB * CLSK * NN];
__device__ float  g_headW[BB * CLSK * NN];
__device__ float  g_tailW[BB * CLSK * NN];
__device__ float  g_sbias[CLSK * NPOS];

// ---------------- helpers ----------------
__device__ __forceinline__ void mma16(float c[4], const unsigned a[4], const unsigned b[2]) {
    asm volatile("mma.sync.aligned.m16n8k16.row.col.f32.f16.f16.f32 "
                 "{%0,%1,%2,%3}, {%4,%5,%6,%7}, {%8,%9}, {%0,%1,%2,%3};"
                 : "+f"(c[0]), "+f"(c[1]), "+f"(c[2]), "+f"(c[3])
                 : "r"(a[0]), "r"(a[1]), "r"(a[2]), "r"(a[3]), "r"(b[0]), "r"(b[1]));
}
__device__ __forceinline__ void ldsm4(unsigned& r0, unsigned& r1, unsigned& r2, unsigned& r3,
                                      uint32_t a) {
    asm volatile("ldmatrix.sync.aligned.m8n8.x4.shared.b16 {%0,%1,%2,%3}, [%4];"
                 : "=r"(r0), "=r"(r1), "=r"(r2), "=r"(r3) : "r"(a));
}
__device__ __forceinline__ void cp16(void* dst, const void* src) {
    unsigned d = (unsigned)__cvta_generic_to_shared(dst);
    asm volatile("cp.async.ca.shared.global [%0], [%1], 16;" :: "r"(d), "l"(src));
}
#define CP_COMMIT() asm volatile("cp.async.commit_group;")
#define CP_WAIT(n)  asm volatile("cp.async.wait_group %0;" :: "n"(n))
__device__ __forceinline__ uint32_t s2u(const void* p) {
    uint32_t a;
    asm("{ .reg .u64 t; cvta.to.shared.u64 t, %1; cvt.u32.u64 %0, t; }" : "=r"(a) : "l"(p));
    return a;
}
__device__ __forceinline__ void grid_dep_sync() {
#if __CUDA_ARCH__ >= 900
    cudaGridDependencySynchronize();
#endif
}

// ============================================================================
// prep = conv (x,y,weights -> fp16) + tr (biaf_W transpose/split) + sb
// ============================================================================
#define CV_X 1536
#define CV_Y 1536
#define CV_W 1536
#define PREP_CONV (CV_X + CV_Y + CV_W)
#define PREP_TR   (9 * 9 * CLSK)
#define PREP_BLOCKS (PREP_CONV + PREP_TR + 1)

__global__ void __launch_bounds__(128) prep_kernel(
    const float* __restrict__ x, const float* __restrict__ y,
    const float* __restrict__ w1, const float* __restrict__ w2,
    const float* __restrict__ hw, const float* __restrict__ tw,
    const float* __restrict__ bw, const float* __restrict__ W,
    const float* __restrict__ se)
{
    const int bi = blockIdx.x;
    const int tid = threadIdx.x;

    if (bi < PREP_CONV) {
        const float4* src;
        __half* dst;
        int fi;
        if (bi < CV_X) {
            fi = bi * 128 + tid;
            src = (const float4*)x; dst = g_xh;
        } else if (bi < CV_X + CV_Y) {
            fi = (bi - CV_X) * 128 + tid;
            src = (const float4*)y; dst = g_yh;
        } else {
            int widx = (bi - CV_X - CV_Y) * 128 + tid;
            int wsel = widx / 49152;
            int off  = widx % 49152;
            const float* ws = (wsel == 0) ? w1 : (wsel == 1) ? w2 : (wsel == 2) ? hw : tw;
            float4 v = ((const float4*)ws)[off];
            __half2* d = (__half2*)&g_wh[(size_t)widx * 4];
            d[0] = __floats2half2_rn(v.x, v.y);
            d[1] = __floats2half2_rn(v.z, v.w);
            return;
        }
        float4 v = src[fi];
        __half2* d = (__half2*)&dst[(size_t)fi * 4];
        d[0] = __floats2half2_rn(v.x, v.y);
        d[1] = __floats2half2_rn(v.z, v.w);
        return;
    }

    if (bi < PREP_CONV + PREP_TR) {
        __shared__ float tile[32][33];
        int t = bi - PREP_CONV;
        int k = t / 81;
        int rem = t % 81;
        int i0 = (rem / 9) * 32, j0 = (rem % 9) * 32;
        int tx = tid & 31, ty = tid >> 5;
        #pragma unroll
        for (int r = 0; r < 8; r++) {
            int i = i0 + ty + r * 4, j = j0 + tx;
            tile[ty + r * 4][tx] = (i < DD && j < DD) ? bw[(k * DD + i) * DD + j] : 0.0f;
        }
        __syncthreads();
        #pragma unroll
        for (int r = 0; r < 8; r++) {
            int j = j0 + ty + r * 4, i = i0 + tx;
            float val = tile[tx][ty + r * 4];
            if (j < HK && i < HK)
                g_bwTh[(k * HK + j) * HK + i] = __float2half_rn(val);
            if (j == BIAF && i < DD)
                g_bwlast[k * 260 + i] = val;
            if (i == BIAF && j < HK)
                g_brow[k * HK + j] = val;
        }
        return;
    }

    for (int idx = tid; idx < CLSK * NPOS; idx += 128) {
        int k = idx / NPOS, p = idx % NPOS;
        float s = 0.0f;
        #pragma unroll
        for (int d = 0; d < SDIM; d++) s += se[p * SDIM + d] * W[k * HSZ + 2 * DD + d];
        g_sbias[idx] = s;
    }
}

// ============================================================================
// proj: fp16 cp.async GEMM. 64x64 tiles (256 blocks), warp tile 32x32, K=768.
// ============================================================================
__global__ void __launch_bounds__(128) proj_kernel(
    const float* __restrict__ b1, const float* __restrict__ b2,
    const float* __restrict__ hb, const float* __restrict__ tb)
{
    __shared__ unsigned As[3][64][20];
    __shared__ unsigned Bs[3][64][20];

    grid_dep_sync();

    const int v = blockIdx.z;
    const int m0 = blockIdx.x * 64;
    const int n0 = blockIdx.y * 64;
    const __half* A = (v == 1) ? g_yh : g_xh;
    const __half* Bm = g_wh + v * (BIAF * HIDD);
    const float* bias = (v == 0) ? b1 : (v == 1) ? b2 : (v == 2) ? hb : tb;

    const int tid = threadIdx.x;
    const int w = tid >> 5, lane = tid & 31, g = lane >> 2, tig = lane & 3;
    const int wm = (w >> 1) * 32, wn = (w & 1) * 32;
    const int lrow = lane & 7, sel = lane >> 3;
    const int aMoff = (sel & 1) * 8, aKw = (sel >> 1) * 4;
    const int bNoff = (sel >> 1) * 8, bKw = (sel & 1) * 4;

    float acc[2][4][4] = {};

    #define P_STAGE(buf, k0)                                                     \
        do { _Pragma("unroll")                                                   \
        for (int h = 0; h < 2; h++) {                                            \
            int f = tid + h * 128;                                               \
            int r = f >> 2, q = f & 3;                                           \
            cp16(&As[buf][r][q * 4], &A[(m0 + r) * HIDD + (k0) + q * 8]);        \
            cp16(&Bs[buf][r][q * 4], &Bm[(n0 + r) * HIDD + (k0) + q * 8]);       \
        } } while (0)

    P_STAGE(0, 0);  CP_COMMIT();
    P_STAGE(1, 32); CP_COMMIT();

    const int NT = HIDD / 32;  // 24
    int cur = 0;
    for (int kt = 0; kt < NT; kt++) {
        if (kt + 1 < NT) CP_WAIT(1); else CP_WAIT(0);
        __syncthreads();
        if (kt + 2 < NT) {
            int nxt = cur + 2; if (nxt >= 3) nxt -= 3;
            P_STAGE(nxt, (kt + 2) * 32);
            CP_COMMIT();
        }
        uint32_t aBase = s2u(&As[cur][0][0]);
        uint32_t bBase = s2u(&Bs[cur][0][0]);
        #pragma unroll
        for (int kk = 0; kk < 2; kk++) {
            unsigned a[2][4], b2v[4][2];
            #pragma unroll
            for (int i = 0; i < 2; i++)
                ldsm4(a[i][0], a[i][1], a[i][2], a[i][3],
                      aBase + (((wm + i * 16 + aMoff + lrow) * 20) + kk * 8 + aKw) * 4);
            #pragma unroll
            for (int jp = 0; jp < 2; jp++)
                ldsm4(b2v[2 * jp][0], b2v[2 * jp][1], b2v[2 * jp + 1][0], b2v[2 * jp + 1][1],
                      bBase + (((wn + jp * 16 + bNoff + lrow) * 20) + kk * 8 + bKw) * 4);
            #pragma unroll
            for (int i = 0; i < 2; i++)
                #pragma unroll
                for (int j = 0; j < 4; j++) mma16(acc[i][j], a[i], b2v[j]);
        }
        if (++cur == 3) cur = 0;
    }

    #pragma unroll
    for (int i = 0; i < 2; i++) {
        #pragma unroll
        for (int rh = 0; rh < 2; rh++) {
            int m = m0 + wm + i * 16 + g + rh * 8;
            #pragma unroll
            for (int j = 0; j < 4; j++) {
                int c = n0 + wn + j * 8 + tig * 2;
                float v0 = acc[i][j][rh * 2 + 0] + __ldg(&bias[c]);
                float v1 = acc[i][j][rh * 2 + 1] + __ldg(&bias[c + 1]);
                if (v < 2) {
                    v0 = 0.5f * v0 * (1.0f + erff(v0 * 0.70710678118654752f));
                    v1 = 0.5f * v1 * (1.0f + erff(v1 * 0.70710678118654752f));
                    __half* dst = (v == 0) ? g_h1h : g_t1h;
                    *(__half2*)&dst[m * HK + c] = __floats2half2_rn(v0, v1);
                } else {
                    v0 = (v0 > 0.0f) ? v0 : 0.01f * v0;
                    v1 = (v1 > 0.0f) ? v1 : 0.01f * v1;
                    float* dst = (v == 2) ? g_head1 : g_tail1;
                    *(float2*)&dst[m * HK + c] = make_float2(v0, v1);
                }
            }
        }
    }
}

// ============================================================================
// fused2 = u (blocks [0,224), 128x128 tiles) + hw/u256 (blocks [224, 224+768)).
// dynamic smem: 3*(128+128)*20*4 = 61440 (+pad).
// ============================================================================
#define F2_U 224
#define F2_HW 768
#define F2_BLOCKS (F2_U + F2_HW)
#define F2_TILE_U (128 * 20)
#define F2_SMEM (3 * 2 * F2_TILE_U * 4 + 512)

__global__ void __launch_bounds__(128) fused2_kernel(const float* __restrict__ W)
{
    extern __shared__ unsigned f2dyn[];
    unsigned (*As)[128][20] = (unsigned(*)[128][20])f2dyn;
    unsigned (*Bs)[128][20] = (unsigned(*)[128][20])(f2dyn + 3 * F2_TILE_U);
    float* sBrow = (float*)(f2dyn + 6 * F2_TILE_U);

    grid_dep_sync();

    const int bi = blockIdx.x;
    const int tid = threadIdx.x;

    if (bi >= F2_U) {
        int warp_id = (bi - F2_U) * 4 + (tid >> 5);
        int lane = tid & 31;
        int which = warp_id >> 10;
        int bm = warp_id & 1023;
        int b = bm >> 9, m = bm & 511;

        float h[8];
        if (which < 2) {
            const float* hr = (which ? g_tail1 : g_head1) + bm * HK;
            #pragma unroll
            for (int s = 0; s < 8; s++) h[s] = hr[lane + 32 * s];
        } else {
            const __half* hr = g_h1h + bm * HK;
            #pragma unroll
            for (int s = 0; s < 8; s++) h[s] = __half2float(hr[lane + 32 * s]);
        }

        #pragma unroll
        for (int half = 0; half < 2; half++) {
            float acc[7];
            #pragma unroll
            for (int k = 0; k < 7; k++) acc[k] = 0.0f;
            if (which < 2) {
                const float* Wb = W + which * DD;
                #pragma unroll
                for (int sg = 0; sg < 8; sg++) {
                    int i = lane + 32 * sg;
                    float hv = h[sg];
                    #pragma unroll
                    for (int k = 0; k < 7; k++)
                        acc[k] += hv * __ldg(&Wb[(half * 7 + k) * HSZ + i]);
                }
            } else {
                #pragma unroll
                for (int sg = 0; sg < 8; sg++) {
                    int i = lane + 32 * sg;
                    float hv = h[sg];
                    #pragma unroll
                    for (int k = 0; k < 7; k++)
                        acc[k] += hv * __ldg(&g_bwlast[(half * 7 + k) * 260 + i]);
                }
            }
            #pragma unroll
            for (int k = 0; k < 7; k++) {
                #pragma unroll
                for (int o = 16; o; o >>= 1) acc[k] += __shfl_xor_sync(0xffffffffu, acc[k], o);
            }
            if (lane == 0) {
                #pragma unroll
                for (int k = 0; k < 7; k++) {
                    int kc = half * 7 + k;
                    if (which < 2) {
                        float val = acc[k] + __ldg(&W[kc * HSZ + which * DD + BIAF]);
                        float* dst = which ? g_tailW : g_headW;
                        dst[(b * CLSK + kc) * NN + m] = val;
                    } else {
                        float val = acc[k] + __ldg(&g_bwlast[kc * 260 + BIAF]);
                        g_u256[(b * CLSK + kc) * NN + m] = val;
                    }
                }
            }
        }
        return;
    }

    // ---------------- u: 128x128 tiles, 4 warps of 64x64 ----------------
    const int bk = bi >> 3;
    const int rem = bi & 7;
    const int b = bk / CLSK, kcls = bk % CLSK;
    const int m0 = (rem & 3) * 128;
    const int n0 = (rem >> 2) * 128;
    const __half* A  = g_h1h + b * NN * HK;
    const __half* Bm = g_bwTh + kcls * HK * HK;
    const int w = tid >> 5, lane = tid & 31, g = lane >> 2, tig = lane & 3;
    const int wm = (w >> 1) * 64, wn = (w & 1) * 64;
    const int lrow = lane & 7, sel = lane >> 3;
    const int aMoff = (sel & 1) * 8, aKw = (sel >> 1) * 4;
    const int bNoff = (sel >> 1) * 8, bKw = (sel & 1) * 4;

    if (tid < 128) sBrow[tid] = g_brow[kcls * HK + n0 + tid];

    float acc[4][8][4] = {};

    #define U_STAGE(buf, k0)                                                     \
        do { _Pragma("unroll")                                                   \
        for (int h = 0; h < 4; h++) {                                            \
            int f = tid + h * 128;                                               \
            int r = f >> 2, q = f & 3;                                           \
            cp16(&As[buf][r][q * 4], &A[(m0 + r) * HK + (k0) + q * 8]);          \
            cp16(&Bs[buf][r][q * 4], &Bm[(n0 + r) * HK + (k0) + q * 8]);         \
        } } while (0)

    U_STAGE(0, 0);  CP_COMMIT();
    U_STAGE(1, 32); CP_COMMIT();

    const int NT = HK / 32;  // 8
    int cur = 0;
    for (int kt = 0; kt < NT; kt++) {
        if (kt + 1 < NT) CP_WAIT(1); else CP_WAIT(0);
        __syncthreads();
        if (kt + 2 < NT) {
            int nxt = cur + 2; if (nxt >= 3) nxt -= 3;
            U_STAGE(nxt, (kt + 2) * 32);
            CP_COMMIT();
        }
        uint32_t aBase = s2u(&As[cur][0][0]);
        uint32_t bBase = s2u(&Bs[cur][0][0]);
        #pragma unroll
        for (int kk = 0; kk < 2; kk++) {
            unsigned a[4][4], b2[8][2];
            #pragma unroll
            for (int i = 0; i < 4; i++)
                ldsm4(a[i][0], a[i][1], a[i][2], a[i][3],
                      aBase + (((wm + i * 16 + aMoff + lrow) * 20) + kk * 8 + aKw) * 4);
            #pragma unroll
            for (int jp = 0; jp < 4; jp++)
                ldsm4(b2[2 * jp][0], b2[2 * jp][1], b2[2 * jp + 1][0], b2[2 * jp + 1][1],
                      bBase + (((wn + jp * 16 + bNoff + lrow) * 20) + kk * 8 + bKw) * 4);
            #pragma unroll
            for (int i = 0; i < 4; i++)
                #pragma unroll
                for (int j = 0; j < 8; j++) mma16(acc[i][j], a[i], b2[j]);
        }
        if (++cur == 3) cur = 0;
    }

    __half* U = g_uh + bk * NN * HK;
    #pragma unroll
    for (int i = 0; i < 4; i++) {
        #pragma unroll
        for (int rh = 0; rh < 2; rh++) {
            int m = m0 + wm + i * 16 + g + rh * 8;
            #pragma unroll
            for (int j = 0; j < 8; j++) {
                int cl = wn + j * 8 + tig * 2;
                float v0 = acc[i][j][rh * 2 + 0] + sBrow[cl];
                float v1 = acc[i][j][rh * 2 + 1] + sBrow[cl + 1];
                *(__half2*)&U[m * HK + n0 + cl] = __floats2half2_rn(v0, v1);
            }
        }
    }
}

// ---------------- out = u @ t1^T + biases. 128x128, K=256 (8 stages) ----------------
#define O_TILE_U (128 * 20)
__global__ void __launch_bounds__(128) out_kernel(float* __restrict__ out)
{
    extern __shared__ unsigned dyn[];
    unsigned (*As)[128][20] = (unsigned(*)[128][20])dyn;
    unsigned (*Bs)[128][20] = (unsigned(*)[128][20])(dyn + 3 * O_TILE_U);
    __shared__ float sHW[128], sTW[128], sSB[NPOS];

    grid_dep_sync();

    const int bk = blockIdx.z;
    const int b = bk / CLSK, kcls = bk % CLSK;
    const int m0 = blockIdx.x * 128;
    const int n0 = blockIdx.y * 128;
    const __half* A  = g_uh + bk * NN * HK;
    const __half* Bt = g_t1h + b * NN * HK;
    const int tid = threadIdx.x;
    const int w = tid >> 5, lane = tid & 31, g = lane >> 2, tig = lane & 3;
    const int wm = (w >> 1) * 64, wn = (w & 1) * 64;
    const int lrow = lane & 7, sel = lane >> 3;
    const int aMoff = (sel & 1) * 8, aKw = (sel >> 1) * 4;
    const int bNoff = (sel >> 1) * 8, bKw = (sel & 1) * 4;

    if (tid < 128) {
        sHW[tid] = g_headW[bk * NN + m0 + tid] + g_u256[bk * NN + m0 + tid];
        sTW[tid] = g_tailW[bk * NN + n0 + tid];
    }
    if (tid < NPOS) sSB[tid] = g_sbias[kcls * NPOS + tid];

    float acc[4][8][4] = {};

    #define O_STAGE(buf, k0)                                                     \
        do { _Pragma("unroll")                                                   \
        for (int h = 0; h < 4; h++) {                                            \
            int f = tid + h * 128;                                               \
            int r = f >> 2, q = f & 3;                                           \
            cp16(&As[buf][r][q * 4], &A[(m0 + r) * HK + (k0) + q * 8]);          \
            cp16(&Bs[buf][r][q * 4], &Bt[(n0 + r) * HK + (k0) + q * 8]);         \
        } } while (0)

    O_STAGE(0, 0);  CP_COMMIT();
    O_STAGE(1, 32); CP_COMMIT();

    const int NT = HK / 32;  // 8
    int cur = 0;
    for (int kt = 0; kt < NT; kt++) {
        if (kt + 1 < NT) CP_WAIT(1); else CP_WAIT(0);
        __syncthreads();
        if (kt + 2 < NT) {
            int nxt = cur + 2; if (nxt >= 3) nxt -= 3;
            O_STAGE(nxt, (kt + 2) * 32);
            CP_COMMIT();
        }
        uint32_t aBase = s2u(&As[cur][0][0]);
        uint32_t bBase = s2u(&Bs[cur][0][0]);
        #pragma unroll
        for (int kk = 0; kk < 2; kk++) {
            unsigned a[4][4], b2[8][2];
            #pragma unroll
            for (int i = 0; i < 4; i++)
                ldsm4(a[i][0], a[i][1], a[i][2], a[i][3],
                      aBase + (((wm + i * 16 + aMoff + lrow) * 20) + kk * 8 + aKw) * 4);
            #pragma unroll
            for (int jp = 0; jp < 4; jp++)
                ldsm4(b2[2 * jp][0], b2[2 * jp][1], b2[2 * jp + 1][0], b2[2 * jp + 1][1],
                      bBase + (((wn + jp * 16 + bNoff + lrow) * 20) + kk * 8 + bKw) * 4);
            #pragma unroll
            for (int i = 0; i < 4; i++)
                #pragma unroll
                for (int j = 0; j < 8; j++) mma16(acc[i][j], a[i], b2[j]);
        }
        if (++cur == 3) cur = 0;
    }

    #pragma unroll
    for (int i = 0; i < 4; i++) {
        #pragma unroll
        for (int rh = 0; rh < 2; rh++) {
            int ml = wm + i * 16 + g + rh * 8;
            int m = m0 + ml;
            float hv = sHW[ml];
            #pragma unroll
            for (int j = 0; j < 8; j++) {
                int cl = wn + j * 8 + tig * 2;
                int n = n0 + cl;
                int d0 = n - m;     d0 = (d0 < -15) ? -15 : (d0 > 14 ? 14 : d0);
                int d1 = n + 1 - m; d1 = (d1 < -15) ? -15 : (d1 > 14 ? 14 : d1);
                float2 vv;
                vv.x = acc[i][j][rh * 2 + 0] + hv + sTW[cl]     + sSB[d0 + 15];
                vv.y = acc[i][j][rh * 2 + 1] + hv + sTW[cl + 1] + sSB[d1 + 15];
                *(float2*)&out[(bk * NN + m) * NN + n] = vv;
            }
        }
    }
}

// ---------------- launch: 4 kernels with PDL chaining ----------------
extern "C" void kernel_launch(void* const* d_in, const int* in_sizes, int n_in,
                              void* d_out, int out_size)
{
    const float* x   = (const float*)d_in[0];
    const float* y   = (const float*)d_in[1];
    // d_in[2] = z : dead input
    const float* w1  = (const float*)d_in[3];
    const float* b1  = (const float*)d_in[4];
    const float* w2  = (const float*)d_in[5];
    const float* b2  = (const float*)d_in[6];
    const float* hw  = (const float*)d_in[7];
    const float* hb  = (const float*)d_in[8];
    const float* tw  = (const float*)d_in[9];
    const float* tb  = (const float*)d_in[10];
    const float* bw  = (const float*)d_in[11];
    const float* W   = (const float*)d_in[12];
    const float* se  = (const float*)d_in[13];
    float* out = (float*)d_out;

    const int OUT_SMEM = 3 * 2 * O_TILE_U * 4;   // 61440
    static int attr_done = 0;
    if (!attr_done) {
        cudaFuncSetAttribute(out_kernel, cudaFuncAttributeMaxDynamicSharedMemorySize, OUT_SMEM);
        cudaFuncSetAttribute(fused2_kernel, cudaFuncAttributeMaxDynamicSharedMemorySize, F2_SMEM);
        attr_done = 1;
    }

    prep_kernel<<<PREP_BLOCKS, 128>>>(x, y, w1, w2, hw, tw, bw, W, se);

    cudaLaunchAttribute at[1];
    at[0].id = cudaLaunchAttributeProgrammaticStreamSerialization;
    at[0].val.programmaticStreamSerializationAllowed = 1;

    {
        cudaLaunchConfig_t cfg = {};
        cfg.gridDim = dim3(16, 4, 4);
        cfg.blockDim = dim3(128, 1, 1);
        cfg.attrs = at; cfg.numAttrs = 1;
        cudaLaunchKernelEx(&cfg, proj_kernel, b1, b2, hb, tb);
    }
    {
        cudaLaunchConfig_t cfg = {};
        cfg.gridDim = dim3(F2_BLOCKS, 1, 1);
        cfg.blockDim = dim3(128, 1, 1);
        cfg.dynamicSmemBytes = F2_SMEM;
        cfg.attrs = at; cfg.numAttrs = 1;
        cudaLaunchKernelEx(&cfg, fused2_kernel, W);
    }
    {
        cudaLaunchConfig_t cfg = {};
        cfg.gridDim = dim3(4, 4, BB * CLSK);
        cfg.blockDim = dim3(128, 1, 1);
        cfg.dynamicSmemBytes = OUT_SMEM;
        cfg.attrs = at; cfg.numAttrs = 1;
        cudaLaunchKernelEx(&cfg, out_kernel, out);
    }
}